// round 7
// baseline (speedup 1.0000x reference)
#include <cuda_runtime.h>
#include <cuda_bf16.h>
#include <cstdint>
#include <math.h>

#define Bn 16
#define Sn 768
#define Hn 768
#define Tn 128
#define NQn 640
#define DHn 64
#define NHn 12
#define CHn 10
#define Mn (Bn * Sn)   // 12288

// ---------------- device scratch (no cudaMalloc allowed) -------------------
__device__ float g_Q[(size_t)Mn * Hn];
__device__ float g_K[(size_t)Mn * Hn];
__device__ float g_V[(size_t)Mn * Hn];
__device__ float g_Vsum[Bn * Hn];
__device__ __nv_bfloat16 g_hs_hi[(size_t)Mn * Hn];
__device__ __nv_bfloat16 g_hs_lo[(size_t)Mn * Hn];
__device__ __nv_bfloat16 g_W_hi[3 * Hn * Hn];
__device__ __nv_bfloat16 g_W_lo[3 * Hn * Hn];

// ---------------------------------------------------------------------------
// fp32 -> (bf16 hi, bf16 lo) split conversions (vectorized)
// ---------------------------------------------------------------------------
__global__ void cvt_hs(const float* __restrict__ hs)
{
    const int n4 = (Mn * Hn) / 4;
    __nv_bfloat162* hi2 = (__nv_bfloat162*)g_hs_hi;
    __nv_bfloat162* lo2 = (__nv_bfloat162*)g_hs_lo;
    for (int i = blockIdx.x * blockDim.x + threadIdx.x; i < n4;
         i += gridDim.x * blockDim.x) {
        float4 x = ((const float4*)hs)[i];
        __nv_bfloat16 h0 = __float2bfloat16(x.x), h1 = __float2bfloat16(x.y);
        __nv_bfloat16 h2 = __float2bfloat16(x.z), h3 = __float2bfloat16(x.w);
        hi2[2 * i + 0] = __nv_bfloat162(h0, h1);
        hi2[2 * i + 1] = __nv_bfloat162(h2, h3);
        lo2[2 * i + 0] = __nv_bfloat162(
            __float2bfloat16(x.x - __bfloat162float(h0)),
            __float2bfloat16(x.y - __bfloat162float(h1)));
        lo2[2 * i + 1] = __nv_bfloat162(
            __float2bfloat16(x.z - __bfloat162float(h2)),
            __float2bfloat16(x.w - __bfloat162float(h3)));
    }
}

__global__ void cvt_w(const float* __restrict__ Wq, const float* __restrict__ Wk,
                      const float* __restrict__ Wv)
{
    const int n = Hn * Hn;
    for (int i = blockIdx.x * blockDim.x + threadIdx.x; i < 3 * n;
         i += gridDim.x * blockDim.x) {
        int z = i / n, j = i - z * n;
        const float* W = (z == 0) ? Wq : (z == 1) ? Wk : Wv;
        float x = W[j];
        __nv_bfloat16 hi = __float2bfloat16(x);
        g_W_hi[i] = hi;
        g_W_lo[i] = __float2bfloat16(x - __bfloat162float(hi));
    }
}

// ---------------------------------------------------------------------------
// mma helpers
// ---------------------------------------------------------------------------
__device__ __forceinline__ void mma_bf16(float c[4], uint32_t a0, uint32_t a1,
                                         uint32_t a2, uint32_t a3,
                                         uint32_t b0, uint32_t b1)
{
    asm volatile(
        "mma.sync.aligned.m16n8k16.row.col.f32.bf16.bf16.f32 "
        "{%0,%1,%2,%3}, {%4,%5,%6,%7}, {%8,%9}, {%0,%1,%2,%3};\n"
        : "+f"(c[0]), "+f"(c[1]), "+f"(c[2]), "+f"(c[3])
        : "r"(a0), "r"(a1), "r"(a2), "r"(a3), "r"(b0), "r"(b1));
}

__device__ __forceinline__ void mma_tf32(float c[4], uint32_t a0, uint32_t a1,
                                         uint32_t a2, uint32_t a3,
                                         uint32_t b0, uint32_t b1)
{
    asm volatile(
        "mma.sync.aligned.m16n8k8.row.col.f32.tf32.tf32.f32 "
        "{%0,%1,%2,%3}, {%4,%5,%6,%7}, {%8,%9}, {%0,%1,%2,%3};\n"
        : "+f"(c[0]), "+f"(c[1]), "+f"(c[2]), "+f"(c[3])
        : "r"(a0), "r"(a1), "r"(a2), "r"(a3), "r"(b0), "r"(b1));
}

__device__ __forceinline__ float tf32r(float x)
{
    float r;
    asm("cvt.rna.tf32.f32 %0, %1;" : "=f"(r) : "f"(x));
    return r;
}

__device__ __forceinline__ void ldsm_x4(uint32_t& r0, uint32_t& r1, uint32_t& r2,
                                        uint32_t& r3, uint32_t saddr)
{
    asm volatile("ldmatrix.sync.aligned.m8n8.x4.shared.b16 {%0,%1,%2,%3}, [%4];\n"
                 : "=r"(r0), "=r"(r1), "=r"(r2), "=r"(r3) : "r"(saddr));
}

#define CPASYNC16(saddr, gptr) \
    asm volatile("cp.async.cg.shared.global [%0], [%1], 16;\n" :: "r"(saddr), "l"(gptr))
#define CP_COMMIT() asm volatile("cp.async.commit_group;\n")
#define CP_WAIT(N)  asm volatile("cp.async.wait_group %0;\n" :: "n"(N))

// ---------------------------------------------------------------------------
// Compensated bf16 tensor-core GEMM (unchanged from R5 passing version)
// ---------------------------------------------------------------------------
#define TILE_ELEMS (128 * 40)
#define STAGE_BYTES (4 * TILE_ELEMS * 2)  // 40960
#define NSTAGE 2

__global__ __launch_bounds__(256, 2) void gemm_qkv(
    const float* __restrict__ bq, const float* __restrict__ bk,
    const float* __restrict__ bv)
{
    extern __shared__ __nv_bfloat16 smem[];

    const int tid = threadIdx.x;
    const int rowBase = blockIdx.y * 128;
    const int colBase = blockIdx.x * 128;
    const int z = blockIdx.z;

    const __nv_bfloat16* Ahi = g_hs_hi + (size_t)rowBase * Hn;
    const __nv_bfloat16* Alo = g_hs_lo + (size_t)rowBase * Hn;
    const __nv_bfloat16* Whi = g_W_hi + (size_t)z * Hn * Hn + (size_t)colBase * Hn;
    const __nv_bfloat16* Wlo = g_W_lo + (size_t)z * Hn * Hn + (size_t)colBase * Hn;
    float* C = (z == 0) ? g_Q : (z == 1) ? g_K : g_V;
    const float* bias = (z == 0) ? bq : (z == 1) ? bk : bv;

    const uint32_t sbase = (uint32_t)__cvta_generic_to_shared(smem);

    const int lrow = tid >> 2;
    const int lkc  = (tid & 3) * 8;

    const int warp  = tid >> 5;
    const int lane  = tid & 31;
    const int warpM = warp >> 2;
    const int warpN = warp & 3;
    const int g  = lane >> 2;
    const int tq = lane & 3;
    const int mrow = warpM * 64;
    const int nrow = warpN * 32;
    const int rsel = lane & 15;
    const int ksel = lane >> 4;
    const uint32_t laneoff = (uint32_t)(rsel * 80 + ksel * 16);

    float acc[4][4][4];
#pragma unroll
    for (int mi = 0; mi < 4; mi++)
#pragma unroll
        for (int ni = 0; ni < 4; ni++)
#pragma unroll
            for (int r = 0; r < 4; r++) acc[mi][ni][r] = 0.f;

    auto load_tiles = [&](int stage, int k0) {
        uint32_t s0 = sbase + stage * STAGE_BYTES;
#pragma unroll
        for (int r2 = 0; r2 < 2; r2++) {
            int r = lrow + r2 * 64;
            uint32_t so = (uint32_t)(r * 80 + lkc * 2);
            size_t go = (size_t)r * Hn + k0 + lkc;
            CPASYNC16(s0 + 0 * (TILE_ELEMS * 2) + so, Ahi + go);
            CPASYNC16(s0 + 1 * (TILE_ELEMS * 2) + so, Alo + go);
            CPASYNC16(s0 + 2 * (TILE_ELEMS * 2) + so, Whi + go);
            CPASYNC16(s0 + 3 * (TILE_ELEMS * 2) + so, Wlo + go);
        }
    };

    auto compute = [&](int stage) {
        uint32_t s0 = sbase + stage * STAGE_BYTES;
        const uint32_t sAhi = s0 + 0 * (TILE_ELEMS * 2) + laneoff;
        const uint32_t sAlo = s0 + 1 * (TILE_ELEMS * 2) + laneoff;
        const uint32_t sWhi = s0 + 2 * (TILE_ELEMS * 2) + laneoff;
        const uint32_t sWlo = s0 + 3 * (TILE_ELEMS * 2) + laneoff;
#pragma unroll
        for (int ks = 0; ks < 2; ks++) {
            const uint32_t ko = (uint32_t)(ks * 32);
            uint32_t ahi[4][4], bhi[4][2];
#pragma unroll
            for (int nj = 0; nj < 2; nj++) {
                uint32_t r0, r1, r2, r3;
                ldsm_x4(r0, r1, r2, r3, sWhi + (uint32_t)((nrow + nj * 16) * 80) + ko);
                bhi[nj * 2 + 0][0] = r0; bhi[nj * 2 + 1][0] = r1;
                bhi[nj * 2 + 0][1] = r2; bhi[nj * 2 + 1][1] = r3;
            }
#pragma unroll
            for (int mi = 0; mi < 4; mi++)
                ldsm_x4(ahi[mi][0], ahi[mi][1], ahi[mi][2], ahi[mi][3],
                        sAhi + (uint32_t)((mrow + mi * 16) * 80) + ko);
#pragma unroll
            for (int mi = 0; mi < 4; mi++)
#pragma unroll
                for (int ni = 0; ni < 4; ni++)
                    mma_bf16(acc[mi][ni], ahi[mi][0], ahi[mi][1], ahi[mi][2],
                             ahi[mi][3], bhi[ni][0], bhi[ni][1]);
            {
                uint32_t blo[4][2];
#pragma unroll
                for (int nj = 0; nj < 2; nj++) {
                    uint32_t r0, r1, r2, r3;
                    ldsm_x4(r0, r1, r2, r3, sWlo + (uint32_t)((nrow + nj * 16) * 80) + ko);
                    blo[nj * 2 + 0][0] = r0; blo[nj * 2 + 1][0] = r1;
                    blo[nj * 2 + 0][1] = r2; blo[nj * 2 + 1][1] = r3;
                }
#pragma unroll
                for (int mi = 0; mi < 4; mi++)
#pragma unroll
                    for (int ni = 0; ni < 4; ni++)
                        mma_bf16(acc[mi][ni], ahi[mi][0], ahi[mi][1], ahi[mi][2],
                                 ahi[mi][3], blo[ni][0], blo[ni][1]);
            }
            {
                uint32_t alo[4][4];
#pragma unroll
                for (int mi = 0; mi < 4; mi++)
                    ldsm_x4(alo[mi][0], alo[mi][1], alo[mi][2], alo[mi][3],
                            sAlo + (uint32_t)((mrow + mi * 16) * 80) + ko);
#pragma unroll
                for (int mi = 0; mi < 4; mi++)
#pragma unroll
                    for (int ni = 0; ni < 4; ni++)
                        mma_bf16(acc[mi][ni], alo[mi][0], alo[mi][1], alo[mi][2],
                                 alo[mi][3], bhi[ni][0], bhi[ni][1]);
            }
        }
    };

    const int NKT = Hn / 32;
    load_tiles(0, 0);
    CP_COMMIT();

    for (int kt = 0; kt < NKT; kt++) {
        CP_WAIT(0);
        __syncthreads();
        if (kt + 1 < NKT) {
            load_tiles((kt + 1) & 1, (kt + 1) * 32);
            CP_COMMIT();
        }
        compute(kt & 1);
    }

#pragma unroll
    for (int mi = 0; mi < 4; mi++) {
#pragma unroll
        for (int ni = 0; ni < 4; ni++) {
            int row0 = rowBase + mrow + mi * 16 + g;
            int col0 = colBase + nrow + ni * 8 + 2 * tq;
            float b0 = bias[col0], b1 = bias[col0 + 1];
            float2 v0 = make_float2(acc[mi][ni][0] + b0, acc[mi][ni][1] + b1);
            float2 v1 = make_float2(acc[mi][ni][2] + b0, acc[mi][ni][3] + b1);
            *(float2*)(C + (size_t)row0 * Hn + col0) = v0;
            *(float2*)(C + (size_t)(row0 + 8) * Hn + col0) = v1;
        }
    }
}

// ---------------------------------------------------------------------------
__global__ void vsum_zero()
{
    g_Vsum[blockIdx.x * Hn + threadIdx.x] = 0.f;
}

__global__ void vsum_part()
{
    int b = blockIdx.x, c = blockIdx.y;
    int col = threadIdx.x;
    const float* base = g_V + ((size_t)b * Sn + c * 64) * Hn + col;
    float acc = 0.f;
#pragma unroll 8
    for (int s = 0; s < 64; s++) acc += base[(size_t)s * Hn];
    atomicAdd(&g_Vsum[b * Hn + col], acc);
}

__global__ void tail_copy(float* __restrict__ out)
{
    int b = blockIdx.x / Tn;
    int t = blockIdx.x % Tn;
    size_t r = (size_t)b * Sn + NQn + t;
    out[r * Hn + threadIdx.x] = g_V[r * Hn + threadIdx.x];
}

// ---------------------------------------------------------------------------
// Tensor-core attention (512 threads, 1 CTA/SM).
// scores: tf32 mma m16n8k8 (single pass; error ~1e-4 absolute on s/8)
// PV: compensated bf16 mma m16n8k16 (P hi/lo x V hi/lo, 3 products)
// ---------------------------------------------------------------------------
#define AQS 65     // sQ/sK fp32 stride
#define ASS 193    // sS fp32 stride
#define APS 194    // P / Vt bf16 stride (97 words)

#define OFF_Q 0
#define OFF_K (64 * AQS)                         // 4160
#define OFF_S (OFF_K + 192 * AQS)                // 16640
#define OFF_VHI (OFF_S + 64 * ASS)               // 28992
#define OFF_VLO (OFF_VHI + (64 * APS) / 2)       // 35200
#define OFF_PHI (OFF_VLO + (64 * APS) / 2)       // 41408
#define OFF_PLO (OFF_PHI + (64 * APS) / 2)       // 47616
#define OFF_SMALL (OFF_PLO + (64 * APS) / 2)     // 53824
#define ATTN_FLOATS (OFF_SMALL + 192)            // 54016 -> 216064 B

__global__ __launch_bounds__(512, 1) void attn_kernel(float* __restrict__ out)
{
    extern __shared__ float sm[];
    float* sQ = sm + OFF_Q;
    float* sK = sm + OFF_K;
    float* sS = sm + OFF_S;
    uint32_t* wVhi = (uint32_t*)(sm + OFF_VHI);   // word stride 97
    uint32_t* wVlo = (uint32_t*)(sm + OFF_VLO);
    __nv_bfloat16* sPhi = (__nv_bfloat16*)(sm + OFF_PHI);
    __nv_bfloat16* sPlo = (__nv_bfloat16*)(sm + OFF_PLO);
    uint32_t* wPhi = (uint32_t*)(sm + OFF_PHI);
    uint32_t* wPlo = (uint32_t*)(sm + OFF_PLO);
    float* sem = sm + OFF_SMALL;
    float* sz  = sem + 64;
    float* sms = sz + 64;

    const int tid = threadIdx.x;
    const int chunk = blockIdx.x;
    const int h = blockIdx.y;
    const int b = blockIdx.z;

    const size_t rowC = (size_t)b * Sn + chunk * 64;
    const float* qp = g_Q + rowC * Hn + h * DHn;
    const float* kc = g_K + rowC * Hn + h * DHn;
    const float* kt = g_K + ((size_t)b * Sn + 576) * Hn + h * DHn;  // use j>=64
    const float* vc = g_V + rowC * Hn + h * DHn;
    const float* vt = g_V + ((size_t)b * Sn + NQn) * Hn + h * DHn;  // j-64 in 0..127

    // ---- load Q, K (tf32-rounded), V (transposed bf16 hi/lo) ----
    for (int idx = tid; idx < 64 * 64; idx += 512) {
        int i = idx >> 6, d = idx & 63;
        sQ[i * AQS + d] = tf32r(qp[(size_t)i * Hn + d]);
    }
    for (int idx = tid; idx < 192 * 64; idx += 512) {
        int j = idx >> 6, d = idx & 63;
        float v = (j < 64) ? kc[(size_t)j * Hn + d] : kt[(size_t)j * Hn + d];
        sK[j * AQS + d] = tf32r(v);
    }
    __nv_bfloat16* sVhi = (__nv_bfloat16*)wVhi;
    __nv_bfloat16* sVlo = (__nv_bfloat16*)wVlo;
    for (int idx = tid; idx < 192 * 16; idx += 512) {
        int j = idx >> 4, d4 = idx & 15;
        const float* vp = (j < 64) ? (vc + (size_t)j * Hn) : (vt + (size_t)(j - 64) * Hn);
        float4 f = *(const float4*)(vp + 4 * d4);
#pragma unroll
        for (int c = 0; c < 4; c++) {
            float x = (&f.x)[c];
            __nv_bfloat16 hi = __float2bfloat16(x);
            sVhi[(4 * d4 + c) * APS + j] = hi;
            sVlo[(4 * d4 + c) * APS + j] = __float2bfloat16(x - __bfloat162float(hi));
        }
    }
    __syncthreads();

    const int lane = tid & 31;
    const int wid = tid >> 5;
    const int g = lane >> 2;
    const int t = lane & 3;
    const int warpM = wid >> 2;     // 0..3 -> 16 rows
    const int warpN = wid & 3;      // 0..3
    const int mbase = warpM * 16;

    // ---- scores: tf32 mma, warp covers 16 rows x 48 cols ----
    {
        const int nbase = warpN * 48;
        float acc[6][4];
#pragma unroll
        for (int nt = 0; nt < 6; nt++)
#pragma unroll
            for (int r = 0; r < 4; r++) acc[nt][r] = 0.f;

#pragma unroll
        for (int ks = 0; ks < 8; ks++) {
            int k0 = ks * 8;
            uint32_t a0 = __float_as_uint(sQ[(mbase + g) * AQS + k0 + t]);
            uint32_t a1 = __float_as_uint(sQ[(mbase + g + 8) * AQS + k0 + t]);
            uint32_t a2 = __float_as_uint(sQ[(mbase + g) * AQS + k0 + t + 4]);
            uint32_t a3 = __float_as_uint(sQ[(mbase + g + 8) * AQS + k0 + t + 4]);
#pragma unroll
            for (int nt = 0; nt < 6; nt++) {
                int n = nbase + nt * 8 + g;
                uint32_t b0 = __float_as_uint(sK[n * AQS + k0 + t]);
                uint32_t b1 = __float_as_uint(sK[n * AQS + k0 + t + 4]);
                mma_tf32(acc[nt], a0, a1, a2, a3, b0, b1);
            }
        }
#pragma unroll
        for (int nt = 0; nt < 6; nt++) {
            int c0 = nbase + nt * 8 + 2 * t;
            sS[(mbase + g) * ASS + c0]     = acc[nt][0] * 0.125f;
            sS[(mbase + g) * ASS + c0 + 1] = acc[nt][1] * 0.125f;
            sS[(mbase + g + 8) * ASS + c0]     = acc[nt][2] * 0.125f;
            sS[(mbase + g + 8) * ASS + c0 + 1] = acc[nt][3] * 0.125f;
        }
    }

    // ---- masked-v sum (global fp32 reads; independent of score phase) ----
    {
        const int d = tid >> 3, part = tid & 7;
        float s = 0.f;
#pragma unroll
        for (int j = part * 8; j < part * 8 + 8; j++)
            s += __ldg(vc + (size_t)j * Hn + d);
        s += __shfl_xor_sync(0xFFFFFFFFu, s, 1);
        s += __shfl_xor_sync(0xFFFFFFFFu, s, 2);
        s += __shfl_xor_sync(0xFFFFFFFFu, s, 4);
        if (part == 0) sms[d] = __ldg(&g_Vsum[b * Hn + h * DHn + d]) - s;
    }
    __syncthreads();

    // ---- softmax (masked cols contribute 576*exp(-m)) ----
    {
        const int i = tid >> 3, part = tid & 7;
        const int j0 = part * 24;
        float m = 0.f;
#pragma unroll
        for (int j = j0; j < j0 + 24; j++) m = fmaxf(m, sS[i * ASS + j]);
        m = fmaxf(m, __shfl_xor_sync(0xFFFFFFFFu, m, 1));
        m = fmaxf(m, __shfl_xor_sync(0xFFFFFFFFu, m, 2));
        m = fmaxf(m, __shfl_xor_sync(0xFFFFFFFFu, m, 4));
        float Z = 0.f;
#pragma unroll
        for (int j = j0; j < j0 + 24; j++) {
            float e = __expf(sS[i * ASS + j] - m);
            sS[i * ASS + j] = e;
            Z += e;
        }
        Z += __shfl_xor_sync(0xFFFFFFFFu, Z, 1);
        Z += __shfl_xor_sync(0xFFFFFFFFu, Z, 2);
        Z += __shfl_xor_sync(0xFFFFFFFFu, Z, 4);
        if (part == 0) {
            float em = __expf(-m);
            sem[i] = em;
            sz[i] = 1.f / (Z + 576.f * em);
        }
    }
    __syncthreads();

    // ---- convert P (e-values) to bf16 hi/lo ----
    for (int idx = tid; idx < 64 * 192; idx += 512) {
        int i = idx / 192, j = idx - i * 192;
        float e = sS[i * ASS + j];
        __nv_bfloat16 hi = __float2bfloat16(e);
        sPhi[i * APS + j] = hi;
        sPlo[i * APS + j] = __float2bfloat16(e - __bfloat162float(hi));
    }
    __syncthreads();

    // ---- PV: compensated bf16 mma; warp covers 16 rows x 16 d-cols ----
    {
        const int dbase = warpN * 16;
        float pv[2][4];
#pragma unroll
        for (int nt = 0; nt < 2; nt++)
#pragma unroll
            for (int r = 0; r < 4; r++) pv[nt][r] = 0.f;

#pragma unroll
        for (int ks = 0; ks < 12; ks++) {
            int kw = ks * 8;   // word offset (16 bf16)
            uint32_t ph0 = wPhi[(mbase + g) * 97 + kw + t];
            uint32_t ph1 = wPhi[(mbase + g + 8) * 97 + kw + t];
            uint32_t ph2 = wPhi[(mbase + g) * 97 + kw + t + 4];
            uint32_t ph3 = wPhi[(mbase + g + 8) * 97 + kw + t + 4];
            uint32_t pl0 = wPlo[(mbase + g) * 97 + kw + t];
            uint32_t pl1 = wPlo[(mbase + g + 8) * 97 + kw + t];
            uint32_t pl2 = wPlo[(mbase + g) * 97 + kw + t + 4];
            uint32_t pl3 = wPlo[(mbase + g + 8) * 97 + kw + t + 4];
#pragma unroll
            for (int nt = 0; nt < 2; nt++) {
                int n = dbase + nt * 8 + g;
                uint32_t bh0 = wVhi[n * 97 + kw + t];
                uint32_t bh1 = wVhi[n * 97 + kw + t + 4];
                uint32_t bl0 = wVlo[n * 97 + kw + t];
                uint32_t bl1 = wVlo[n * 97 + kw + t + 4];
                mma_bf16(pv[nt], ph0, ph1, ph2, ph3, bh0, bh1);
                mma_bf16(pv[nt], ph0, ph1, ph2, ph3, bl0, bl1);
                mma_bf16(pv[nt], pl0, pl1, pl2, pl3, bh0, bh1);
            }
        }

        // epilogue
#pragma unroll
        for (int nt = 0; nt < 2; nt++) {
            int d0 = dbase + nt * 8 + 2 * t;
            int r0 = mbase + g;
            int r1 = r0 + 8;
            float inv0 = sz[r0], em0 = sem[r0];
            float inv1 = sz[r1], em1 = sem[r1];
            float* o0 = out + (rowC + r0) * Hn + h * DHn + d0;
            float* o1 = out + (rowC + r1) * Hn + h * DHn + d0;
            o0[0] = (pv[nt][0] + em0 * sms[d0])     * inv0;
            o0[1] = (pv[nt][1] + em0 * sms[d0 + 1]) * inv0;
            o1[0] = (pv[nt][2] + em1 * sms[d0])     * inv1;
            o1[1] = (pv[nt][3] + em1 * sms[d0 + 1]) * inv1;
        }
    }
}

// ---------------------------------------------------------------------------
extern "C" void kernel_launch(void* const* d_in, const int* in_sizes, int n_in,
                              void* d_out, int out_size)
{
    const float* hs = (const float*)d_in[0];
    const float* Wq = (const float*)d_in[1];
    const float* bq = (const float*)d_in[2];
    const float* Wk = (const float*)d_in[3];
    const float* bk = (const float*)d_in[4];
    const float* Wv = (const float*)d_in[5];
    const float* bv = (const float*)d_in[6];
    float* out = (float*)d_out;

    cvt_hs<<<2048, 256>>>(hs);
    cvt_w<<<2048, 256>>>(Wq, Wk, Wv);
    vsum_zero<<<Bn, Hn>>>();

    const int gemm_smem = NSTAGE * STAGE_BYTES;   // 81920
    cudaFuncSetAttribute(gemm_qkv, cudaFuncAttributeMaxDynamicSharedMemorySize, gemm_smem);
    gemm_qkv<<<dim3(Hn / 128, Mn / 128, 3), 256, gemm_smem>>>(bq, bk, bv);  // idx 3 (ncu)

    vsum_part<<<dim3(Bn, CHn), Hn>>>();
    tail_copy<<<Bn * Tn, Hn>>>(out);

    const int attn_smem = ATTN_FLOATS * 4;   // 216064 B
    cudaFuncSetAttribute(attn_kernel, cudaFuncAttributeMaxDynamicSharedMemorySize, attn_smem);
    attn_kernel<<<dim3(CHn, NHn, Bn), 512, attn_smem>>>(out);
}

// round 8
// speedup vs baseline: 1.2915x; 1.2915x over previous
#include <cuda_runtime.h>
#include <cuda_bf16.h>
#include <cstdint>
#include <math.h>

#define Bn 16
#define Sn 768
#define Hn 768
#define Tn 128
#define NQn 640
#define DHn 64
#define NHn 12
#define CHn 10
#define Mn (Bn * Sn)   // 12288

// ---------------- device scratch (no cudaMalloc allowed) -------------------
__device__ float g_Q[(size_t)Mn * Hn];
__device__ float g_K[(size_t)Mn * Hn];
__device__ float g_V[(size_t)Mn * Hn];
__device__ float g_Vsum[Bn * Hn];
__device__ float g_Wt[3 * Hn * Hn];     // tf32-rounded Wq|Wk|Wv

// ---------------------------------------------------------------------------
__device__ __forceinline__ float tf32r(float x)
{
    float r;
    asm("cvt.rna.tf32.f32 %0, %1;" : "=f"(r) : "f"(x));
    return r;
}

__device__ __forceinline__ void mma_tf32(float c[4], uint32_t a0, uint32_t a1,
                                         uint32_t a2, uint32_t a3,
                                         uint32_t b0, uint32_t b1)
{
    asm volatile(
        "mma.sync.aligned.m16n8k8.row.col.f32.tf32.tf32.f32 "
        "{%0,%1,%2,%3}, {%4,%5,%6,%7}, {%8,%9}, {%0,%1,%2,%3};\n"
        : "+f"(c[0]), "+f"(c[1]), "+f"(c[2]), "+f"(c[3])
        : "r"(a0), "r"(a1), "r"(a2), "r"(a3), "r"(b0), "r"(b1));
}

#define CPASYNC16(saddr, gptr) \
    asm volatile("cp.async.cg.shared.global [%0], [%1], 16;\n" :: "r"(saddr), "l"(gptr))
#define CP_COMMIT() asm volatile("cp.async.commit_group;\n")
#define CP_WAIT(N)  asm volatile("cp.async.wait_group %0;\n" :: "n"(N))

// ---------------------------------------------------------------------------
// Weight pre-round to tf32 (RN, removes truncation bias)
// ---------------------------------------------------------------------------
__global__ void cvt_wall(const float* __restrict__ Wq, const float* __restrict__ Wk,
                         const float* __restrict__ Wv)
{
    const int n = Hn * Hn;
    for (int i = blockIdx.x * blockDim.x + threadIdx.x; i < 3 * n;
         i += gridDim.x * blockDim.x) {
        int z = i / n, j = i - z * n;
        const float* W = (z == 0) ? Wq : (z == 1) ? Wk : Wv;
        g_Wt[i] = tf32r(W[j]);
    }
}

__global__ void vsum_zero(int base)
{
    g_Vsum[(base + blockIdx.x) * Hn + threadIdx.x] = 0.f;
}

// ---------------------------------------------------------------------------
// tf32 tensor-core GEMM:  C_z = hs @ W_z^T + bias_z
// 128x128 tile, BK=32, 256 threads (8 warps 2x4), 3-stage cp.async, 2 CTAs/SM.
// A rounded to tf32 in-register; W pre-rounded.
// ---------------------------------------------------------------------------
#define TILE_F 4608                  // 128 rows * 36 floats
#define TILE_BYTES (TILE_F * 4)      // 18432
#define STAGE_F (2 * TILE_F)
#define STAGE_BYTES (2 * TILE_BYTES) // 36864
#define GSTAGES 3
#define GEMM_SMEM (GSTAGES * STAGE_BYTES)  // 110592

__global__ __launch_bounds__(256, 2) void gemm_qkv(
    const float* __restrict__ hs,
    const float* __restrict__ bq, const float* __restrict__ bk,
    const float* __restrict__ bv)
{
    extern __shared__ float smem[];
    const uint32_t sbase = (uint32_t)__cvta_generic_to_shared(smem);

    const int tid = threadIdx.x;
    const int rowBase = blockIdx.y * 128;
    const int colBase = blockIdx.x * 128;
    const int z = blockIdx.z;

    const float* Ag = hs + (size_t)rowBase * Hn;
    const float* Wt = g_Wt + (size_t)z * Hn * Hn + (size_t)colBase * Hn;
    float* C = (z == 0) ? g_Q : (z == 1) ? g_K : g_V;
    const float* bias = (z == 0) ? bq : (z == 1) ? bk : bv;

    const int warp  = tid >> 5;
    const int lane  = tid & 31;
    const int warpM = warp >> 2;
    const int warpN = warp & 3;
    const int g  = lane >> 2;
    const int t  = lane & 3;
    const int mrow = warpM * 64;
    const int nrow = warpN * 32;

    float acc[4][4][4];
#pragma unroll
    for (int mi = 0; mi < 4; mi++)
#pragma unroll
        for (int ni = 0; ni < 4; ni++)
#pragma unroll
            for (int r = 0; r < 4; r++) acc[mi][ni][r] = 0.f;

    auto load_stage = [&](int stage, int ktile) {
        uint32_t s0 = sbase + stage * STAGE_BYTES;
        int kb = ktile * 32;
#pragma unroll
        for (int i = 0; i < 8; i++) {
            int idx = i * 256 + tid;
            int arr = idx >> 10;
            int r = (idx >> 3) & 127;
            int c = idx & 7;
            const float* src = arr ? (Wt + (size_t)r * Hn + kb + c * 4)
                                   : (Ag + (size_t)r * Hn + kb + c * 4);
            CPASYNC16(s0 + arr * TILE_BYTES + (uint32_t)(r * 144 + c * 16), src);
        }
    };

    auto compute = [&](int stage) {
        const float* sA = smem + stage * STAGE_F;
        const float* sW = sA + TILE_F;
        const float* aB = sA + (mrow + g) * 36 + t;
        const float* bB = sW + (nrow + g) * 36 + t;
#pragma unroll
        for (int ks = 0; ks < 4; ks++) {
            const int kf = ks * 8;
            uint32_t a[4][4];
#pragma unroll
            for (int mi = 0; mi < 4; mi++) {
                a[mi][0] = __float_as_uint(tf32r(aB[mi * 576 + kf]));
                a[mi][1] = __float_as_uint(tf32r(aB[mi * 576 + 288 + kf]));
                a[mi][2] = __float_as_uint(tf32r(aB[mi * 576 + kf + 4]));
                a[mi][3] = __float_as_uint(tf32r(aB[mi * 576 + 288 + kf + 4]));
            }
            uint32_t b[4][2];
#pragma unroll
            for (int ni = 0; ni < 4; ni++) {
                b[ni][0] = __float_as_uint(bB[ni * 288 + kf]);
                b[ni][1] = __float_as_uint(bB[ni * 288 + kf + 4]);
            }
#pragma unroll
            for (int mi = 0; mi < 4; mi++)
#pragma unroll
                for (int ni = 0; ni < 4; ni++)
                    mma_tf32(acc[mi][ni], a[mi][0], a[mi][1], a[mi][2], a[mi][3],
                             b[ni][0], b[ni][1]);
        }
    };

    const int NKT = Hn / 32;   // 24
    load_stage(0, 0); CP_COMMIT();
    load_stage(1, 1); CP_COMMIT();

    for (int kt = 0; kt < NKT; kt++) {
        if (kt < NKT - 2) { CP_WAIT(1); } else { CP_WAIT(0); }
        __syncthreads();
        if (kt + 2 < NKT) {
            load_stage((kt + 2) % GSTAGES, kt + 2);
            CP_COMMIT();
        }
        compute(kt % GSTAGES);
    }

    // epilogue: add bias, store fp32
#pragma unroll
    for (int mi = 0; mi < 4; mi++) {
#pragma unroll
        for (int ni = 0; ni < 4; ni++) {
            int row0 = rowBase + mrow + mi * 16 + g;
            int col0 = colBase + nrow + ni * 8 + 2 * t;
            float b0 = bias[col0], b1 = bias[col0 + 1];
            float2 v0 = make_float2(acc[mi][ni][0] + b0, acc[mi][ni][1] + b1);
            float2 v1 = make_float2(acc[mi][ni][2] + b0, acc[mi][ni][3] + b1);
            *(float2*)(C + (size_t)row0 * Hn + col0) = v0;
            *(float2*)(C + (size_t)(row0 + 8) * Hn + col0) = v1;
        }
    }
}

// ---------------------------------------------------------------------------
__global__ void vsum_part()
{
    int b = blockIdx.x, c = blockIdx.y;
    int col = threadIdx.x;
    const float* base = g_V + ((size_t)b * Sn + c * 64) * Hn + col;
    float acc = 0.f;
#pragma unroll 8
    for (int s = 0; s < 64; s++) acc += base[(size_t)s * Hn];
    atomicAdd(&g_Vsum[b * Hn + col], acc);
}

__global__ void tail_copy(float* __restrict__ out)
{
    int b = blockIdx.x / Tn;
    int t = blockIdx.x % Tn;
    size_t r = (size_t)b * Sn + NQn + t;
    out[r * Hn + threadIdx.x] = g_V[r * Hn + threadIdx.x];
}

// ---------------------------------------------------------------------------
// Fused attention (512 threads, 2 CTAs/SM): one CTA per (chunk, head, batch).
// smem: sq(64x68) + sk(192x68); sp(64x193) overlays sq/sk after score phase.
// V is read straight from L1/L2 via __ldg float4 (no smem tile).
// ---------------------------------------------------------------------------
#define SQS 68
#define SPS 193
#define SMALL_OFF (64 * SQS + 192 * SQS)   // 17408 floats

__global__ __launch_bounds__(512, 2) void attn_kernel(float* __restrict__ out)
{
    extern __shared__ float sm[];
    float* sq  = sm;                    // 64 * 68
    float* sk  = sm + 64 * SQS;         // 192 * 68
    float* sp  = sm;                    // overlay (64*193 <= 17408)
    float* sem = sm + SMALL_OFF;        // 64
    float* sz  = sem + 64;              // 64
    float* sms = sz + 64;               // 64

    const int tid = threadIdx.x;
    const int chunk = blockIdx.x;
    const int h = blockIdx.y;
    const int b = blockIdx.z;

    const size_t baseC = ((size_t)b * Sn + chunk * 64) * Hn + h * DHn;
    const size_t baseT = ((size_t)b * Sn + 576) * Hn + h * DHn;   // rows 576+j, j>=64
    const float* vc = g_V + baseC;
    const float* vt = g_V + ((size_t)b * Sn + NQn) * Hn + h * DHn;

    for (int idx = tid; idx < 64 * 64; idx += 512) {
        int i = idx >> 6, d = idx & 63;
        sq[i * SQS + d] = g_Q[baseC + (size_t)i * Hn + d];
    }
    for (int idx = tid; idx < 192 * 64; idx += 512) {
        int j = idx >> 6, d = idx & 63;
        size_t off = (j < 64) ? (baseC + (size_t)j * Hn + d)
                              : (baseT + (size_t)j * Hn + d);
        sk[j * SQS + d] = g_K[off];
    }
    __syncthreads();

    const int tx = tid & 15;
    const int ty = tid >> 4;      // 0..31
    const int i0 = ty * 2;

    // scores in registers: 2 rows x 12 interleaved cols (j = tx + 16*jj)
    float acc[2][12];
#pragma unroll
    for (int ii = 0; ii < 2; ii++)
#pragma unroll
        for (int jj = 0; jj < 12; jj++) acc[ii][jj] = 0.f;

    for (int d4 = 0; d4 < 16; d4++) {
        float4 a0 = *(const float4*)&sq[i0 * SQS + d4 * 4];
        float4 a1 = *(const float4*)&sq[(i0 + 1) * SQS + d4 * 4];
#pragma unroll
        for (int grp = 0; grp < 3; grp++) {
            float4 kb[4];
#pragma unroll
            for (int u = 0; u < 4; u++)
                kb[u] = *(const float4*)&sk[(tx + 16 * (grp * 4 + u)) * SQS + d4 * 4];
#pragma unroll
            for (int u = 0; u < 4; u++) {
                int jj = grp * 4 + u;
                acc[0][jj] = fmaf(a0.x, kb[u].x, acc[0][jj]);
                acc[0][jj] = fmaf(a0.y, kb[u].y, acc[0][jj]);
                acc[0][jj] = fmaf(a0.z, kb[u].z, acc[0][jj]);
                acc[0][jj] = fmaf(a0.w, kb[u].w, acc[0][jj]);
                acc[1][jj] = fmaf(a1.x, kb[u].x, acc[1][jj]);
                acc[1][jj] = fmaf(a1.y, kb[u].y, acc[1][jj]);
                acc[1][jj] = fmaf(a1.z, kb[u].z, acc[1][jj]);
                acc[1][jj] = fmaf(a1.w, kb[u].w, acc[1][jj]);
            }
        }
    }
    __syncthreads();   // all sq/sk reads done -> safe to overlay sp

#pragma unroll
    for (int ii = 0; ii < 2; ii++)
#pragma unroll
        for (int jj = 0; jj < 12; jj++)
            sp[(i0 + ii) * SPS + tx + 16 * jj] = acc[ii][jj] * 0.125f;

    // masked-v sum: d = tid/8, 8 threads sum 8 chunk-rows each (global reads)
    {
        const int d = tid >> 3, part = tid & 7;
        float s = 0.f;
#pragma unroll
        for (int j = part * 8; j < part * 8 + 8; j++)
            s += __ldg(vc + (size_t)j * Hn + d);
        s += __shfl_xor_sync(0xFFFFFFFFu, s, 1);
        s += __shfl_xor_sync(0xFFFFFFFFu, s, 2);
        s += __shfl_xor_sync(0xFFFFFFFFu, s, 4);
        if (part == 0) sms[d] = __ldg(&g_Vsum[b * Hn + h * DHn + d]) - s;
    }
    __syncthreads();

    // softmax: row = tid/8, 8 threads x 24 cols; masked cols add 576*exp(-m)
    {
        const int i = tid >> 3, part = tid & 7;
        const int j0 = part * 24;
        float m = 0.f;   // masked scores are exactly 0
#pragma unroll
        for (int j = j0; j < j0 + 24; j++) m = fmaxf(m, sp[i * SPS + j]);
        m = fmaxf(m, __shfl_xor_sync(0xFFFFFFFFu, m, 1));
        m = fmaxf(m, __shfl_xor_sync(0xFFFFFFFFu, m, 2));
        m = fmaxf(m, __shfl_xor_sync(0xFFFFFFFFu, m, 4));
        float Z = 0.f;
#pragma unroll
        for (int j = j0; j < j0 + 24; j++) {
            float e = __expf(sp[i * SPS + j] - m);
            sp[i * SPS + j] = e;
            Z += e;
        }
        Z += __shfl_xor_sync(0xFFFFFFFFu, Z, 1);
        Z += __shfl_xor_sync(0xFFFFFFFFu, Z, 2);
        Z += __shfl_xor_sync(0xFFFFFFFFu, Z, 4);
        if (part == 0) {
            float em = __expf(-m);
            sem[i] = em;
            sz[i] = 1.f / (Z + 576.f * em);
        }
    }
    __syncthreads();

    // ctx: 2 rows x 4 cols per thread; V via __ldg (L1/L2 resident)
    {
        float o[2][4];
#pragma unroll
        for (int ii = 0; ii < 2; ii++)
#pragma unroll
            for (int dd = 0; dd < 4; dd++) o[ii][dd] = 0.f;
        const int d0 = tx * 4;
        for (int j = 0; j < 64; j++) {
            float p0 = sp[i0 * SPS + j];
            float p1 = sp[(i0 + 1) * SPS + j];
            float4 vj = __ldg((const float4*)(vc + (size_t)j * Hn + d0));
            o[0][0] = fmaf(p0, vj.x, o[0][0]);
            o[0][1] = fmaf(p0, vj.y, o[0][1]);
            o[0][2] = fmaf(p0, vj.z, o[0][2]);
            o[0][3] = fmaf(p0, vj.w, o[0][3]);
            o[1][0] = fmaf(p1, vj.x, o[1][0]);
            o[1][1] = fmaf(p1, vj.y, o[1][1]);
            o[1][2] = fmaf(p1, vj.z, o[1][2]);
            o[1][3] = fmaf(p1, vj.w, o[1][3]);
        }
        for (int j = 0; j < 128; j++) {
            float p0 = sp[i0 * SPS + 64 + j];
            float p1 = sp[(i0 + 1) * SPS + 64 + j];
            float4 vj = __ldg((const float4*)(vt + (size_t)j * Hn + d0));
            o[0][0] = fmaf(p0, vj.x, o[0][0]);
            o[0][1] = fmaf(p0, vj.y, o[0][1]);
            o[0][2] = fmaf(p0, vj.z, o[0][2]);
            o[0][3] = fmaf(p0, vj.w, o[0][3]);
            o[1][0] = fmaf(p1, vj.x, o[1][0]);
            o[1][1] = fmaf(p1, vj.y, o[1][1]);
            o[1][2] = fmaf(p1, vj.z, o[1][2]);
            o[1][3] = fmaf(p1, vj.w, o[1][3]);
        }
#pragma unroll
        for (int ii = 0; ii < 2; ii++) {
            float inv = sz[i0 + ii];
            float em  = sem[i0 + ii];
            float4 ov;
            ov.x = (o[ii][0] + em * sms[d0 + 0]) * inv;
            ov.y = (o[ii][1] + em * sms[d0 + 1]) * inv;
            ov.z = (o[ii][2] + em * sms[d0 + 2]) * inv;
            ov.w = (o[ii][3] + em * sms[d0 + 3]) * inv;
            *(float4*)(out + ((size_t)b * Sn + chunk * 64 + i0 + ii) * Hn + h * DHn + d0) = ov;
        }
    }
}

// ---------------------------------------------------------------------------
extern "C" void kernel_launch(void* const* d_in, const int* in_sizes, int n_in,
                              void* d_out, int out_size)
{
    const float* hs = (const float*)d_in[0];
    const float* Wq = (const float*)d_in[1];
    const float* bq = (const float*)d_in[2];
    const float* Wk = (const float*)d_in[3];
    const float* bk = (const float*)d_in[4];
    const float* Wv = (const float*)d_in[5];
    const float* bv = (const float*)d_in[6];
    float* out = (float*)d_out;

    cvt_wall<<<1024, 256>>>(Wq, Wk, Wv);     // idx 0
    vsum_zero<<<8, Hn>>>(0);                 // idx 1
    vsum_zero<<<8, Hn>>>(8);                 // idx 2

    cudaFuncSetAttribute(gemm_qkv, cudaFuncAttributeMaxDynamicSharedMemorySize,
                         GEMM_SMEM);
    gemm_qkv<<<dim3(Hn / 128, Mn / 128, 3), 256, GEMM_SMEM>>>(hs, bq, bk, bv); // idx 3 (ncu)

    vsum_part<<<dim3(Bn, CHn), Hn>>>();
    tail_copy<<<Bn * Tn, Hn>>>(out);

    const size_t attn_smem = (size_t)(SMALL_OFF + 3 * 64) * sizeof(float);  // 70400 B
    cudaFuncSetAttribute(attn_kernel, cudaFuncAttributeMaxDynamicSharedMemorySize,
                         (int)attn_smem);
    attn_kernel<<<dim3(CHn, NHn, Bn), 512, attn_smem>>>(out);
}

// round 9
// speedup vs baseline: 1.4345x; 1.1107x over previous
#include <cuda_runtime.h>
#include <cuda_bf16.h>
#include <cstdint>
#include <math.h>

#define Bn 16
#define Sn 768
#define Hn 768
#define Tn 128
#define NQn 640
#define DHn 64
#define NHn 12
#define CHn 10
#define Mn (Bn * Sn)   // 12288

// ---------------- device scratch (no cudaMalloc allowed) -------------------
__device__ float g_Q[(size_t)Mn * Hn];
__device__ float g_K[(size_t)Mn * Hn];
__device__ float g_V[(size_t)Mn * Hn];
__device__ float g_Vsum[Bn * Hn];
__device__ float g_Wt[3 * Hn * Hn];     // tf32-rounded Wq|Wk|Wv
__device__ float g_At[(size_t)Mn * Hn]; // tf32-rounded hs

// ---------------------------------------------------------------------------
__device__ __forceinline__ float tf32r(float x)
{
    float r;
    asm("cvt.rna.tf32.f32 %0, %1;" : "=f"(r) : "f"(x));
    return r;
}

__device__ __forceinline__ void mma_tf32(float c[4], uint32_t a0, uint32_t a1,
                                         uint32_t a2, uint32_t a3,
                                         uint32_t b0, uint32_t b1)
{
    asm volatile(
        "mma.sync.aligned.m16n8k8.row.col.f32.tf32.tf32.f32 "
        "{%0,%1,%2,%3}, {%4,%5,%6,%7}, {%8,%9}, {%0,%1,%2,%3};\n"
        : "+f"(c[0]), "+f"(c[1]), "+f"(c[2]), "+f"(c[3])
        : "r"(a0), "r"(a1), "r"(a2), "r"(a3), "r"(b0), "r"(b1));
}

#define CPASYNC16(saddr, gptr) \
    asm volatile("cp.async.cg.shared.global [%0], [%1], 16;\n" :: "r"(saddr), "l"(gptr))
#define CP_COMMIT() asm volatile("cp.async.commit_group;\n")
#define CP_WAIT(N)  asm volatile("cp.async.wait_group %0;\n" :: "n"(N))

// ---------------------------------------------------------------------------
// Pre-rounding passes
// ---------------------------------------------------------------------------
__global__ void cvt_wall(const float* __restrict__ Wq, const float* __restrict__ Wk,
                         const float* __restrict__ Wv)
{
    const int n = Hn * Hn;
    for (int i = blockIdx.x * blockDim.x + threadIdx.x; i < 3 * n;
         i += gridDim.x * blockDim.x) {
        int z = i / n, j = i - z * n;
        const float* W = (z == 0) ? Wq : (z == 1) ? Wk : Wv;
        g_Wt[i] = tf32r(W[j]);
    }
}

__global__ void cvt_a(const float* __restrict__ hs)
{
    const int n4 = (Mn * Hn) / 4;
    float4* dst = (float4*)g_At;
    for (int i = blockIdx.x * blockDim.x + threadIdx.x; i < n4;
         i += gridDim.x * blockDim.x) {
        float4 x = ((const float4*)hs)[i];
        x.x = tf32r(x.x); x.y = tf32r(x.y);
        x.z = tf32r(x.z); x.w = tf32r(x.w);
        dst[i] = x;
    }
}

__global__ void vsum_zero()
{
    g_Vsum[blockIdx.x * Hn + threadIdx.x] = 0.f;
}

// ---------------------------------------------------------------------------
// tf32 tensor-core GEMM:  C_z = At @ Wt_z^T + bias_z   (both pre-rounded)
// 128x128 tile, BK=32, 256 threads (8 warps 2x4), 3-stage cp.async, 2 CTAs/SM.
// ---------------------------------------------------------------------------
#define TILE_F 4608                  // 128 rows * 36 floats
#define TILE_BYTES (TILE_F * 4)      // 18432
#define STAGE_F (2 * TILE_F)
#define STAGE_BYTES (2 * TILE_BYTES) // 36864
#define GSTAGES 3
#define GEMM_SMEM (GSTAGES * STAGE_BYTES)  // 110592

__global__ __launch_bounds__(256, 2) void gemm_qkv(
    const float* __restrict__ bq, const float* __restrict__ bk,
    const float* __restrict__ bv)
{
    extern __shared__ float smem[];
    const uint32_t sbase = (uint32_t)__cvta_generic_to_shared(smem);

    const int tid = threadIdx.x;
    const int rowBase = blockIdx.y * 128;
    const int colBase = blockIdx.x * 128;
    const int z = blockIdx.z;

    const float* Ag = g_At + (size_t)rowBase * Hn;
    const float* Wt = g_Wt + (size_t)z * Hn * Hn + (size_t)colBase * Hn;
    float* C = (z == 0) ? g_Q : (z == 1) ? g_K : g_V;
    const float* bias = (z == 0) ? bq : (z == 1) ? bk : bv;

    const int warp  = tid >> 5;
    const int lane  = tid & 31;
    const int warpM = warp >> 2;
    const int warpN = warp & 3;
    const int g  = lane >> 2;
    const int t  = lane & 3;
    const int mrow = warpM * 64;
    const int nrow = warpN * 32;

    float acc[4][4][4];
#pragma unroll
    for (int mi = 0; mi < 4; mi++)
#pragma unroll
        for (int ni = 0; ni < 4; ni++)
#pragma unroll
            for (int r = 0; r < 4; r++) acc[mi][ni][r] = 0.f;

    auto load_stage = [&](int stage, int ktile) {
        uint32_t s0 = sbase + stage * STAGE_BYTES;
        int kb = ktile * 32;
#pragma unroll
        for (int i = 0; i < 8; i++) {
            int idx = i * 256 + tid;
            int arr = idx >> 10;
            int r = (idx >> 3) & 127;
            int c = idx & 7;
            const float* src = arr ? (Wt + (size_t)r * Hn + kb + c * 4)
                                   : (Ag + (size_t)r * Hn + kb + c * 4);
            CPASYNC16(s0 + arr * TILE_BYTES + (uint32_t)(r * 144 + c * 16), src);
        }
    };

    auto compute = [&](int stage) {
        const float* sA = smem + stage * STAGE_F;
        const float* sW = sA + TILE_F;
        const float* aB = sA + (mrow + g) * 36 + t;
        const float* bB = sW + (nrow + g) * 36 + t;
#pragma unroll
        for (int ks = 0; ks < 4; ks++) {
            const int kf = ks * 8;
            uint32_t a[4][4];
#pragma unroll
            for (int mi = 0; mi < 4; mi++) {
                a[mi][0] = __float_as_uint(aB[mi * 576 + kf]);
                a[mi][1] = __float_as_uint(aB[mi * 576 + 288 + kf]);
                a[mi][2] = __float_as_uint(aB[mi * 576 + kf + 4]);
                a[mi][3] = __float_as_uint(aB[mi * 576 + 288 + kf + 4]);
            }
            uint32_t b[4][2];
#pragma unroll
            for (int ni = 0; ni < 4; ni++) {
                b[ni][0] = __float_as_uint(bB[ni * 288 + kf]);
                b[ni][1] = __float_as_uint(bB[ni * 288 + kf + 4]);
            }
#pragma unroll
            for (int mi = 0; mi < 4; mi++)
#pragma unroll
                for (int ni = 0; ni < 4; ni++)
                    mma_tf32(acc[mi][ni], a[mi][0], a[mi][1], a[mi][2], a[mi][3],
                             b[ni][0], b[ni][1]);
        }
    };

    const int NKT = Hn / 32;   // 24
    load_stage(0, 0); CP_COMMIT();
    load_stage(1, 1); CP_COMMIT();

    for (int kt = 0; kt < NKT; kt++) {
        if (kt < NKT - 2) { CP_WAIT(1); } else { CP_WAIT(0); }
        __syncthreads();
        if (kt + 2 < NKT) {
            load_stage((kt + 2) % GSTAGES, kt + 2);
            CP_COMMIT();
        }
        compute(kt % GSTAGES);
    }

    // epilogue: add bias, store fp32
#pragma unroll
    for (int mi = 0; mi < 4; mi++) {
#pragma unroll
        for (int ni = 0; ni < 4; ni++) {
            int row0 = rowBase + mrow + mi * 16 + g;
            int col0 = colBase + nrow + ni * 8 + 2 * t;
            float b0 = bias[col0], b1 = bias[col0 + 1];
            float2 v0 = make_float2(acc[mi][ni][0] + b0, acc[mi][ni][1] + b1);
            float2 v1 = make_float2(acc[mi][ni][2] + b0, acc[mi][ni][3] + b1);
            *(float2*)(C + (size_t)row0 * Hn + col0) = v0;
            *(float2*)(C + (size_t)(row0 + 8) * Hn + col0) = v1;
        }
    }
}

// ---------------------------------------------------------------------------
__global__ void vsum_part()
{
    int b = blockIdx.x, c = blockIdx.y;
    int col = threadIdx.x;
    const float* base = g_V + ((size_t)b * Sn + c * 64) * Hn + col;
    float acc = 0.f;
#pragma unroll 8
    for (int s = 0; s < 64; s++) acc += base[(size_t)s * Hn];
    atomicAdd(&g_Vsum[b * Hn + col], acc);
}

__global__ void tail_copy(float* __restrict__ out)
{
    int b = blockIdx.x / Tn;
    int t = blockIdx.x % Tn;
    size_t r = (size_t)b * Sn + NQn + t;
    out[r * Hn + threadIdx.x] = g_V[r * Hn + threadIdx.x];
}

// ---------------------------------------------------------------------------
// Fused attention (512 threads, 2 CTAs/SM): one CTA per (chunk, head, batch).
// Scores via tf32 mma (Q/K tf32-rounded in-register); softmax + PV SIMT.
// smem: sq(64x68) + sk(192x68); sp(64x193) overlays sq/sk after score phase.
// ---------------------------------------------------------------------------
#define SQS 68
#define SPS 193
#define SMALL_OFF (64 * SQS + 192 * SQS)   // 17408 floats

__global__ __launch_bounds__(512, 2) void attn_kernel(float* __restrict__ out)
{
    extern __shared__ float sm[];
    float* sq  = sm;                    // 64 * 68
    float* sk  = sm + 64 * SQS;         // 192 * 68
    float* sp  = sm;                    // overlay (64*193 <= 17408)
    float* sem = sm + SMALL_OFF;        // 64
    float* sz  = sem + 64;              // 64
    float* sms = sz + 64;               // 64

    const int tid = threadIdx.x;
    const int chunk = blockIdx.x;
    const int h = blockIdx.y;
    const int b = blockIdx.z;

    const size_t baseC = ((size_t)b * Sn + chunk * 64) * Hn + h * DHn;
    const size_t baseT = ((size_t)b * Sn + 576) * Hn + h * DHn;   // rows 576+j, j>=64
    const float* vc = g_V + baseC;
    const float* vt = g_V + ((size_t)b * Sn + NQn) * Hn + h * DHn;

    for (int idx = tid; idx < 64 * 64; idx += 512) {
        int i = idx >> 6, d = idx & 63;
        sq[i * SQS + d] = g_Q[baseC + (size_t)i * Hn + d];
    }
    for (int idx = tid; idx < 192 * 64; idx += 512) {
        int j = idx >> 6, d = idx & 63;
        size_t off = (j < 64) ? (baseC + (size_t)j * Hn + d)
                              : (baseT + (size_t)j * Hn + d);
        sk[j * SQS + d] = g_K[off];
    }
    __syncthreads();

    const int lane = tid & 31;
    const int wid = tid >> 5;
    const int g = lane >> 2;
    const int t = lane & 3;
    const int mbase = (wid & 3) * 16;    // 4 row-groups of 16
    const int nbase = (wid >> 2) * 48;   // 4 col-groups of 48

    // ---- scores: tf32 mma, each warp 16 rows x 48 cols over k=64 ----
    float acc[6][4];
#pragma unroll
    for (int nt = 0; nt < 6; nt++)
#pragma unroll
        for (int r = 0; r < 4; r++) acc[nt][r] = 0.f;

#pragma unroll
    for (int ks = 0; ks < 8; ks++) {
        const int k0 = ks * 8;
        uint32_t a0 = __float_as_uint(tf32r(sq[(mbase + g) * SQS + k0 + t]));
        uint32_t a1 = __float_as_uint(tf32r(sq[(mbase + g + 8) * SQS + k0 + t]));
        uint32_t a2 = __float_as_uint(tf32r(sq[(mbase + g) * SQS + k0 + t + 4]));
        uint32_t a3 = __float_as_uint(tf32r(sq[(mbase + g + 8) * SQS + k0 + t + 4]));
#pragma unroll
        for (int nt = 0; nt < 6; nt++) {
            const int n = nbase + nt * 8 + g;
            uint32_t b0 = __float_as_uint(tf32r(sk[n * SQS + k0 + t]));
            uint32_t b1 = __float_as_uint(tf32r(sk[n * SQS + k0 + t + 4]));
            mma_tf32(acc[nt], a0, a1, a2, a3, b0, b1);
        }
    }
    __syncthreads();   // all sq/sk reads done -> safe to overlay sp

#pragma unroll
    for (int nt = 0; nt < 6; nt++) {
        const int c0 = nbase + nt * 8 + 2 * t;
        sp[(mbase + g) * SPS + c0]     = acc[nt][0] * 0.125f;
        sp[(mbase + g) * SPS + c0 + 1] = acc[nt][1] * 0.125f;
        sp[(mbase + g + 8) * SPS + c0]     = acc[nt][2] * 0.125f;
        sp[(mbase + g + 8) * SPS + c0 + 1] = acc[nt][3] * 0.125f;
    }

    // masked-v sum: d = tid/8, 8 threads sum 8 chunk-rows each (global reads)
    {
        const int d = tid >> 3, part = tid & 7;
        float s = 0.f;
#pragma unroll
        for (int j = part * 8; j < part * 8 + 8; j++)
            s += __ldg(vc + (size_t)j * Hn + d);
        s += __shfl_xor_sync(0xFFFFFFFFu, s, 1);
        s += __shfl_xor_sync(0xFFFFFFFFu, s, 2);
        s += __shfl_xor_sync(0xFFFFFFFFu, s, 4);
        if (part == 0) sms[d] = __ldg(&g_Vsum[b * Hn + h * DHn + d]) - s;
    }
    __syncthreads();

    // softmax: row = tid/8, 8 threads x 24 cols; masked cols add 576*exp(-m)
    {
        const int i = tid >> 3, part = tid & 7;
        const int j0 = part * 24;
        float m = 0.f;   // masked scores are exactly 0
#pragma unroll
        for (int j = j0; j < j0 + 24; j++) m = fmaxf(m, sp[i * SPS + j]);
        m = fmaxf(m, __shfl_xor_sync(0xFFFFFFFFu, m, 1));
        m = fmaxf(m, __shfl_xor_sync(0xFFFFFFFFu, m, 2));
        m = fmaxf(m, __shfl_xor_sync(0xFFFFFFFFu, m, 4));
        float Z = 0.f;
#pragma unroll
        for (int j = j0; j < j0 + 24; j++) {
            float e = __expf(sp[i * SPS + j] - m);
            sp[i * SPS + j] = e;
            Z += e;
        }
        Z += __shfl_xor_sync(0xFFFFFFFFu, Z, 1);
        Z += __shfl_xor_sync(0xFFFFFFFFu, Z, 2);
        Z += __shfl_xor_sync(0xFFFFFFFFu, Z, 4);
        if (part == 0) {
            float em = __expf(-m);
            sem[i] = em;
            sz[i] = 1.f / (Z + 576.f * em);
        }
    }
    __syncthreads();

    // ctx: 2 rows x 4 cols per thread; V via __ldg (L1/L2 resident)
    {
        const int tx = tid & 15;
        const int i0 = (tid >> 4) * 2;
        float o[2][4];
#pragma unroll
        for (int ii = 0; ii < 2; ii++)
#pragma unroll
            for (int dd = 0; dd < 4; dd++) o[ii][dd] = 0.f;
        const int d0 = tx * 4;
        for (int j = 0; j < 64; j++) {
            float p0 = sp[i0 * SPS + j];
            float p1 = sp[(i0 + 1) * SPS + j];
            float4 vj = __ldg((const float4*)(vc + (size_t)j * Hn + d0));
            o[0][0] = fmaf(p0, vj.x, o[0][0]);
            o[0][1] = fmaf(p0, vj.y, o[0][1]);
            o[0][2] = fmaf(p0, vj.z, o[0][2]);
            o[0][3] = fmaf(p0, vj.w, o[0][3]);
            o[1][0] = fmaf(p1, vj.x, o[1][0]);
            o[1][1] = fmaf(p1, vj.y, o[1][1]);
            o[1][2] = fmaf(p1, vj.z, o[1][2]);
            o[1][3] = fmaf(p1, vj.w, o[1][3]);
        }
        for (int j = 0; j < 128; j++) {
            float p0 = sp[i0 * SPS + 64 + j];
            float p1 = sp[(i0 + 1) * SPS + 64 + j];
            float4 vj = __ldg((const float4*)(vt + (size_t)j * Hn + d0));
            o[0][0] = fmaf(p0, vj.x, o[0][0]);
            o[0][1] = fmaf(p0, vj.y, o[0][1]);
            o[0][2] = fmaf(p0, vj.z, o[0][2]);
            o[0][3] = fmaf(p0, vj.w, o[0][3]);
            o[1][0] = fmaf(p1, vj.x, o[1][0]);
            o[1][1] = fmaf(p1, vj.y, o[1][1]);
            o[1][2] = fmaf(p1, vj.z, o[1][2]);
            o[1][3] = fmaf(p1, vj.w, o[1][3]);
        }
#pragma unroll
        for (int ii = 0; ii < 2; ii++) {
            float inv = sz[i0 + ii];
            float em  = sem[i0 + ii];
            float4 ov;
            ov.x = (o[ii][0] + em * sms[d0 + 0]) * inv;
            ov.y = (o[ii][1] + em * sms[d0 + 1]) * inv;
            ov.z = (o[ii][2] + em * sms[d0 + 2]) * inv;
            ov.w = (o[ii][3] + em * sms[d0 + 3]) * inv;
            *(float4*)(out + ((size_t)b * Sn + chunk * 64 + i0 + ii) * Hn + h * DHn + d0) = ov;
        }
    }
}

// ---------------------------------------------------------------------------
extern "C" void kernel_launch(void* const* d_in, const int* in_sizes, int n_in,
                              void* d_out, int out_size)
{
    const float* hs = (const float*)d_in[0];
    const float* Wq = (const float*)d_in[1];
    const float* bq = (const float*)d_in[2];
    const float* Wk = (const float*)d_in[3];
    const float* bk = (const float*)d_in[4];
    const float* Wv = (const float*)d_in[5];
    const float* bv = (const float*)d_in[6];
    float* out = (float*)d_out;

    cvt_wall<<<1024, 256>>>(Wq, Wk, Wv);     // idx 0
    cvt_a<<<2048, 256>>>(hs);                // idx 1
    vsum_zero<<<Bn, Hn>>>();                 // idx 2

    cudaFuncSetAttribute(gemm_qkv, cudaFuncAttributeMaxDynamicSharedMemorySize,
                         GEMM_SMEM);
    gemm_qkv<<<dim3(Hn / 128, Mn / 128, 3), 256, GEMM_SMEM>>>(bq, bk, bv); // idx 3 (ncu)

    vsum_part<<<dim3(Bn, CHn), Hn>>>();
    tail_copy<<<Bn * Tn, Hn>>>(out);

    const size_t attn_smem = (size_t)(SMALL_OFF + 3 * 64) * sizeof(float);  // 70400 B
    cudaFuncSetAttribute(attn_kernel, cudaFuncAttributeMaxDynamicSharedMemorySize,
                         (int)attn_smem);
    attn_kernel<<<dim3(CHn, NHn, Bn), 512, attn_smem>>>(out);
}

// round 10
// speedup vs baseline: 1.5059x; 1.0498x over previous
#include <cuda_runtime.h>
#include <cuda_bf16.h>
#include <cstdint>
#include <math.h>

#define Bn 16
#define Sn 768
#define Hn 768
#define Tn 128
#define NQn 640
#define DHn 64
#define NHn 12
#define CHn 10
#define Mn (Bn * Sn)   // 12288

// ---------------- device scratch (no cudaMalloc allowed) -------------------
__device__ float g_Q[(size_t)Mn * Hn];
__device__ float g_K[(size_t)Mn * Hn];
__device__ float g_V[(size_t)Mn * Hn];
__device__ float g_Vsum[Bn * Hn];
__device__ float g_Wt[3 * Hn * Hn];     // tf32-rounded Wq|Wk|Wv
__device__ float g_At[(size_t)Mn * Hn]; // tf32-rounded hs

// ---------------------------------------------------------------------------
__device__ __forceinline__ float tf32r(float x)
{
    float r;
    asm("cvt.rna.tf32.f32 %0, %1;" : "=f"(r) : "f"(x));
    return r;
}

__device__ __forceinline__ void mma_tf32(float c[4], uint32_t a0, uint32_t a1,
                                         uint32_t a2, uint32_t a3,
                                         uint32_t b0, uint32_t b1)
{
    asm volatile(
        "mma.sync.aligned.m16n8k8.row.col.f32.tf32.tf32.f32 "
        "{%0,%1,%2,%3}, {%4,%5,%6,%7}, {%8,%9}, {%0,%1,%2,%3};\n"
        : "+f"(c[0]), "+f"(c[1]), "+f"(c[2]), "+f"(c[3])
        : "r"(a0), "r"(a1), "r"(a2), "r"(a3), "r"(b0), "r"(b1));
}

__device__ __forceinline__ void ldsm_x4(uint32_t& r0, uint32_t& r1, uint32_t& r2,
                                        uint32_t& r3, uint32_t saddr)
{
    asm volatile("ldmatrix.sync.aligned.m8n8.x4.shared.b16 {%0,%1,%2,%3}, [%4];\n"
                 : "=r"(r0), "=r"(r1), "=r"(r2), "=r"(r3) : "r"(saddr));
}

#define CPASYNC16(saddr, gptr) \
    asm volatile("cp.async.cg.shared.global [%0], [%1], 16;\n" :: "r"(saddr), "l"(gptr))
#define CP_COMMIT() asm volatile("cp.async.commit_group;\n")
#define CP_WAIT(N)  asm volatile("cp.async.wait_group %0;\n" :: "n"(N))

// ---------------------------------------------------------------------------
// Pre-rounding passes
// ---------------------------------------------------------------------------
__global__ void cvt_wall(const float* __restrict__ Wq, const float* __restrict__ Wk,
                         const float* __restrict__ Wv)
{
    const int n = Hn * Hn;
    for (int i = blockIdx.x * blockDim.x + threadIdx.x; i < 3 * n;
         i += gridDim.x * blockDim.x) {
        int z = i / n, j = i - z * n;
        const float* W = (z == 0) ? Wq : (z == 1) ? Wk : Wv;
        g_Wt[i] = tf32r(W[j]);
    }
}

__global__ void cvt_a(const float* __restrict__ hs)
{
    const int n4 = (Mn * Hn) / 4;
    float4* dst = (float4*)g_At;
    for (int i = blockIdx.x * blockDim.x + threadIdx.x; i < n4;
         i += gridDim.x * blockDim.x) {
        float4 x = ((const float4*)hs)[i];
        x.x = tf32r(x.x); x.y = tf32r(x.y);
        x.z = tf32r(x.z); x.w = tf32r(x.w);
        dst[i] = x;
    }
}

__global__ void vsum_zero()
{
    g_Vsum[blockIdx.x * Hn + threadIdx.x] = 0.f;
}

// ---------------------------------------------------------------------------
// tf32 tensor-core GEMM with ldmatrix fragment loads.
// 128x128 tile, BK=32, 256 threads (8 warps 2x4), 3-stage cp.async, 2 CTAs/SM.
// smem row stride 36 floats (144 B) -> ldmatrix phase-conflict-free.
// ---------------------------------------------------------------------------
#define TILE_F 4608                  // 128 rows * 36 floats
#define TILE_BYTES (TILE_F * 4)      // 18432
#define STAGE_F (2 * TILE_F)
#define STAGE_BYTES (2 * TILE_BYTES) // 36864
#define GSTAGES 3
#define GEMM_SMEM (GSTAGES * STAGE_BYTES)  // 110592

__global__ __launch_bounds__(256, 2) void gemm_qkv(
    const float* __restrict__ bq, const float* __restrict__ bk,
    const float* __restrict__ bv)
{
    extern __shared__ float smem[];
    const uint32_t sbase = (uint32_t)__cvta_generic_to_shared(smem);

    const int tid = threadIdx.x;
    const int rowBase = blockIdx.y * 128;
    const int colBase = blockIdx.x * 128;
    const int z = blockIdx.z;

    const float* Ag = g_At + (size_t)rowBase * Hn;
    const float* Wt = g_Wt + (size_t)z * Hn * Hn + (size_t)colBase * Hn;
    float* C = (z == 0) ? g_Q : (z == 1) ? g_K : g_V;
    const float* bias = (z == 0) ? bq : (z == 1) ? bk : bv;

    const int warp  = tid >> 5;
    const int lane  = tid & 31;
    const int warpM = warp >> 2;
    const int warpN = warp & 3;
    const int g  = lane >> 2;
    const int t  = lane & 3;
    const int mrow = warpM * 64;
    const int nrow = warpN * 32;
    // ldmatrix lane offset: rows 0-15 (lane&15), k-half 16B (lane>>4)
    const uint32_t laneoff = (uint32_t)((lane & 15) * 144 + (lane >> 4) * 16);

    float acc[4][4][4];
#pragma unroll
    for (int mi = 0; mi < 4; mi++)
#pragma unroll
        for (int ni = 0; ni < 4; ni++)
#pragma unroll
            for (int r = 0; r < 4; r++) acc[mi][ni][r] = 0.f;

    auto load_stage = [&](int stage, int ktile) {
        uint32_t s0 = sbase + stage * STAGE_BYTES;
        int kb = ktile * 32;
#pragma unroll
        for (int i = 0; i < 8; i++) {
            int idx = i * 256 + tid;
            int arr = idx >> 10;
            int r = (idx >> 3) & 127;
            int c = idx & 7;
            const float* src = arr ? (Wt + (size_t)r * Hn + kb + c * 4)
                                   : (Ag + (size_t)r * Hn + kb + c * 4);
            CPASYNC16(s0 + arr * TILE_BYTES + (uint32_t)(r * 144 + c * 16), src);
        }
    };

    auto compute = [&](int stage) {
        const uint32_t s0 = sbase + stage * STAGE_BYTES;
        const uint32_t aB = s0 + (uint32_t)(mrow * 144) + laneoff;
        const uint32_t bB = s0 + TILE_BYTES + (uint32_t)(nrow * 144) + laneoff;
#pragma unroll
        for (int ks = 0; ks < 4; ks++) {
            const uint32_t ko = (uint32_t)(ks * 32);
            uint32_t a[4][4], b[4][2];
            {
                uint32_t r0, r1, r2, r3;
                ldsm_x4(r0, r1, r2, r3, bB + ko);
                b[0][0] = r0; b[1][0] = r1; b[0][1] = r2; b[1][1] = r3;
                ldsm_x4(r0, r1, r2, r3, bB + 16 * 144 + ko);
                b[2][0] = r0; b[3][0] = r1; b[2][1] = r2; b[3][1] = r3;
            }
#pragma unroll
            for (int mi = 0; mi < 4; mi++)
                ldsm_x4(a[mi][0], a[mi][1], a[mi][2], a[mi][3],
                        aB + (uint32_t)(mi * 16 * 144) + ko);
#pragma unroll
            for (int mi = 0; mi < 4; mi++)
#pragma unroll
                for (int ni = 0; ni < 4; ni++)
                    mma_tf32(acc[mi][ni], a[mi][0], a[mi][1], a[mi][2], a[mi][3],
                             b[ni][0], b[ni][1]);
        }
    };

    const int NKT = Hn / 32;   // 24
    load_stage(0, 0); CP_COMMIT();
    load_stage(1, 1); CP_COMMIT();

    for (int kt = 0; kt < NKT; kt++) {
        if (kt < NKT - 2) { CP_WAIT(1); } else { CP_WAIT(0); }
        __syncthreads();
        if (kt + 2 < NKT) {
            load_stage((kt + 2) % GSTAGES, kt + 2);
            CP_COMMIT();
        }
        compute(kt % GSTAGES);
    }

    // epilogue: add bias, store fp32
#pragma unroll
    for (int mi = 0; mi < 4; mi++) {
#pragma unroll
        for (int ni = 0; ni < 4; ni++) {
            int row0 = rowBase + mrow + mi * 16 + g;
            int col0 = colBase + nrow + ni * 8 + 2 * t;
            float b0 = bias[col0], b1 = bias[col0 + 1];
            float2 v0 = make_float2(acc[mi][ni][0] + b0, acc[mi][ni][1] + b1);
            float2 v1 = make_float2(acc[mi][ni][2] + b0, acc[mi][ni][3] + b1);
            *(float2*)(C + (size_t)row0 * Hn + col0) = v0;
            *(float2*)(C + (size_t)(row0 + 8) * Hn + col0) = v1;
        }
    }
}

// ---------------------------------------------------------------------------
__global__ void vsum_part()
{
    int b = blockIdx.x, c = blockIdx.y;
    int col = threadIdx.x;
    const float* base = g_V + ((size_t)b * Sn + c * 64) * Hn + col;
    float acc = 0.f;
#pragma unroll 8
    for (int s = 0; s < 64; s++) acc += base[(size_t)s * Hn];
    atomicAdd(&g_Vsum[b * Hn + col], acc);
}

__global__ void tail_copy(float* __restrict__ out)
{
    int b = blockIdx.x / Tn;
    int t = blockIdx.x % Tn;
    size_t r = (size_t)b * Sn + NQn + t;
    out[r * Hn + threadIdx.x] = g_V[r * Hn + threadIdx.x];
}

// ---------------------------------------------------------------------------
// Fused attention (512 threads, 2 CTAs/SM): one CTA per (chunk, head, batch).
// Scores via tf32 mma; softmax + PV SIMT (float2 score loads).
// smem: sq(64x68) + sk(192x68); sp(64x194) overlays sq/sk after score phase.
// ---------------------------------------------------------------------------
#define SQS 68
#define SPS 194
#define SMALL_OFF (64 * SQS + 192 * SQS)   // 17408 floats (sp 64*194=12416 fits)

__global__ __launch_bounds__(512, 2) void attn_kernel(float* __restrict__ out)
{
    extern __shared__ float sm[];
    float* sq  = sm;                    // 64 * 68
    float* sk  = sm + 64 * SQS;         // 192 * 68
    float* sp  = sm;                    // overlay
    float* sem = sm + SMALL_OFF;        // 64
    float* sz  = sem + 64;              // 64
    float* sms = sz + 64;               // 64

    const int tid = threadIdx.x;
    const int chunk = blockIdx.x;
    const int h = blockIdx.y;
    const int b = blockIdx.z;

    const size_t baseC = ((size_t)b * Sn + chunk * 64) * Hn + h * DHn;
    const size_t baseT = ((size_t)b * Sn + 576) * Hn + h * DHn;   // rows 576+j, j>=64
    const float* vc = g_V + baseC;
    const float* vt = g_V + ((size_t)b * Sn + NQn) * Hn + h * DHn;

    for (int idx = tid; idx < 64 * 64; idx += 512) {
        int i = idx >> 6, d = idx & 63;
        sq[i * SQS + d] = g_Q[baseC + (size_t)i * Hn + d];
    }
    for (int idx = tid; idx < 192 * 64; idx += 512) {
        int j = idx >> 6, d = idx & 63;
        size_t off = (j < 64) ? (baseC + (size_t)j * Hn + d)
                              : (baseT + (size_t)j * Hn + d);
        sk[j * SQS + d] = g_K[off];
    }
    __syncthreads();

    const int lane = tid & 31;
    const int wid = tid >> 5;
    const int g = lane >> 2;
    const int t = lane & 3;
    const int mbase = (wid & 3) * 16;    // 4 row-groups of 16
    const int nbase = (wid >> 2) * 48;   // 4 col-groups of 48

    // ---- scores: tf32 mma, each warp 16 rows x 48 cols over k=64 ----
    float acc[6][4];
#pragma unroll
    for (int nt = 0; nt < 6; nt++)
#pragma unroll
        for (int r = 0; r < 4; r++) acc[nt][r] = 0.f;

#pragma unroll
    for (int ks = 0; ks < 8; ks++) {
        const int k0 = ks * 8;
        uint32_t a0 = __float_as_uint(tf32r(sq[(mbase + g) * SQS + k0 + t]));
        uint32_t a1 = __float_as_uint(tf32r(sq[(mbase + g + 8) * SQS + k0 + t]));
        uint32_t a2 = __float_as_uint(tf32r(sq[(mbase + g) * SQS + k0 + t + 4]));
        uint32_t a3 = __float_as_uint(tf32r(sq[(mbase + g + 8) * SQS + k0 + t + 4]));
#pragma unroll
        for (int nt = 0; nt < 6; nt++) {
            const int n = nbase + nt * 8 + g;
            uint32_t b0 = __float_as_uint(tf32r(sk[n * SQS + k0 + t]));
            uint32_t b1 = __float_as_uint(tf32r(sk[n * SQS + k0 + t + 4]));
            mma_tf32(acc[nt], a0, a1, a2, a3, b0, b1);
        }
    }
    __syncthreads();   // all sq/sk reads done -> safe to overlay sp

#pragma unroll
    for (int nt = 0; nt < 6; nt++) {
        const int c0 = nbase + nt * 8 + 2 * t;
        *(float2*)&sp[(mbase + g) * SPS + c0] =
            make_float2(acc[nt][0] * 0.125f, acc[nt][1] * 0.125f);
        *(float2*)&sp[(mbase + g + 8) * SPS + c0] =
            make_float2(acc[nt][2] * 0.125f, acc[nt][3] * 0.125f);
    }

    // masked-v sum: d = tid/8, 8 threads sum 8 chunk-rows each (global reads)
    {
        const int d = tid >> 3, part = tid & 7;
        float s = 0.f;
#pragma unroll
        for (int j = part * 8; j < part * 8 + 8; j++)
            s += __ldg(vc + (size_t)j * Hn + d);
        s += __shfl_xor_sync(0xFFFFFFFFu, s, 1);
        s += __shfl_xor_sync(0xFFFFFFFFu, s, 2);
        s += __shfl_xor_sync(0xFFFFFFFFu, s, 4);
        if (part == 0) sms[d] = __ldg(&g_Vsum[b * Hn + h * DHn + d]) - s;
    }
    __syncthreads();

    // softmax: row = tid/8, 8 threads x 24 cols; masked cols add 576*exp(-m)
    {
        const int i = tid >> 3, part = tid & 7;
        const int j0 = part * 24;
        float m = 0.f;   // masked scores are exactly 0
#pragma unroll
        for (int j = j0; j < j0 + 24; j++) m = fmaxf(m, sp[i * SPS + j]);
        m = fmaxf(m, __shfl_xor_sync(0xFFFFFFFFu, m, 1));
        m = fmaxf(m, __shfl_xor_sync(0xFFFFFFFFu, m, 2));
        m = fmaxf(m, __shfl_xor_sync(0xFFFFFFFFu, m, 4));
        float Z = 0.f;
#pragma unroll
        for (int j = j0; j < j0 + 24; j++) {
            float e = __expf(sp[i * SPS + j] - m);
            sp[i * SPS + j] = e;
            Z += e;
        }
        Z += __shfl_xor_sync(0xFFFFFFFFu, Z, 1);
        Z += __shfl_xor_sync(0xFFFFFFFFu, Z, 2);
        Z += __shfl_xor_sync(0xFFFFFFFFu, Z, 4);
        if (part == 0) {
            float em = __expf(-m);
            sem[i] = em;
            sz[i] = 1.f / (Z + 576.f * em);
        }
    }
    __syncthreads();

    // ctx: 2 rows x 4 cols per thread; V via __ldg, scores via float2 LDS
    {
        const int tx = tid & 15;
        const int i0 = (tid >> 4) * 2;
        float o[2][4];
#pragma unroll
        for (int ii = 0; ii < 2; ii++)
#pragma unroll
            for (int dd = 0; dd < 4; dd++) o[ii][dd] = 0.f;
        const int d0 = tx * 4;
#pragma unroll 4
        for (int j = 0; j < 64; j += 2) {
            float2 pA = *(const float2*)&sp[i0 * SPS + j];
            float2 pB = *(const float2*)&sp[(i0 + 1) * SPS + j];
            float4 v0 = __ldg((const float4*)(vc + (size_t)j * Hn + d0));
            float4 v1 = __ldg((const float4*)(vc + (size_t)(j + 1) * Hn + d0));
            o[0][0] = fmaf(pA.x, v0.x, fmaf(pA.y, v1.x, o[0][0]));
            o[0][1] = fmaf(pA.x, v0.y, fmaf(pA.y, v1.y, o[0][1]));
            o[0][2] = fmaf(pA.x, v0.z, fmaf(pA.y, v1.z, o[0][2]));
            o[0][3] = fmaf(pA.x, v0.w, fmaf(pA.y, v1.w, o[0][3]));
            o[1][0] = fmaf(pB.x, v0.x, fmaf(pB.y, v1.x, o[1][0]));
            o[1][1] = fmaf(pB.x, v0.y, fmaf(pB.y, v1.y, o[1][1]));
            o[1][2] = fmaf(pB.x, v0.z, fmaf(pB.y, v1.z, o[1][2]));
            o[1][3] = fmaf(pB.x, v0.w, fmaf(pB.y, v1.w, o[1][3]));
        }
#pragma unroll 4
        for (int j = 0; j < 128; j += 2) {
            float2 pA = *(const float2*)&sp[i0 * SPS + 64 + j];
            float2 pB = *(const float2*)&sp[(i0 + 1) * SPS + 64 + j];
            float4 v0 = __ldg((const float4*)(vt + (size_t)j * Hn + d0));
            float4 v1 = __ldg((const float4*)(vt + (size_t)(j + 1) * Hn + d0));
            o[0][0] = fmaf(pA.x, v0.x, fmaf(pA.y, v1.x, o[0][0]));
            o[0][1] = fmaf(pA.x, v0.y, fmaf(pA.y, v1.y, o[0][1]));
            o[0][2] = fmaf(pA.x, v0.z, fmaf(pA.y, v1.z, o[0][2]));
            o[0][3] = fmaf(pA.x, v0.w, fmaf(pA.y, v1.w, o[0][3]));
            o[1][0] = fmaf(pB.x, v0.x, fmaf(pB.y, v1.x, o[1][0]));
            o[1][1] = fmaf(pB.x, v0.y, fmaf(pB.y, v1.y, o[1][1]));
            o[1][2] = fmaf(pB.x, v0.z, fmaf(pB.y, v1.z, o[1][2]));
            o[1][3] = fmaf(pB.x, v0.w, fmaf(pB.y, v1.w, o[1][3]));
        }
#pragma unroll
        for (int ii = 0; ii < 2; ii++) {
            float inv = sz[i0 + ii];
            float em  = sem[i0 + ii];
            float4 ov;
            ov.x = (o[ii][0] + em * sms[d0 + 0]) * inv;
            ov.y = (o[ii][1] + em * sms[d0 + 1]) * inv;
            ov.z = (o[ii][2] + em * sms[d0 + 2]) * inv;
            ov.w = (o[ii][3] + em * sms[d0 + 3]) * inv;
            *(float4*)(out + ((size_t)b * Sn + chunk * 64 + i0 + ii) * Hn + h * DHn + d0) = ov;
        }
    }
}

// ---------------------------------------------------------------------------
extern "C" void kernel_launch(void* const* d_in, const int* in_sizes, int n_in,
                              void* d_out, int out_size)
{
    const float* hs = (const float*)d_in[0];
    const float* Wq = (const float*)d_in[1];
    const float* bq = (const float*)d_in[2];
    const float* Wk = (const float*)d_in[3];
    const float* bk = (const float*)d_in[4];
    const float* Wv = (const float*)d_in[5];
    const float* bv = (const float*)d_in[6];
    float* out = (float*)d_out;

    cvt_wall<<<1024, 256>>>(Wq, Wk, Wv);     // idx 0
    cvt_a<<<2048, 256>>>(hs);                // idx 1
    vsum_zero<<<Bn, Hn>>>();                 // idx 2

    cudaFuncSetAttribute(gemm_qkv, cudaFuncAttributeMaxDynamicSharedMemorySize,
                         GEMM_SMEM);
    gemm_qkv<<<dim3(Hn / 128, Mn / 128, 3), 256, GEMM_SMEM>>>(bq, bk, bv); // idx 3 (ncu)

    vsum_part<<<dim3(Bn, CHn), Hn>>>();
    tail_copy<<<Bn * Tn, Hn>>>(out);

    const size_t attn_smem = (size_t)(SMALL_OFF + 3 * 64) * sizeof(float);  // 70400 B
    cudaFuncSetAttribute(attn_kernel, cudaFuncAttributeMaxDynamicSharedMemorySize,
                         (int)attn_smem);
    attn_kernel<<<dim3(CHn, NHn, Bn), 512, attn_smem>>>(out);
}

// round 11
// speedup vs baseline: 1.5565x; 1.0336x over previous
#include <cuda_runtime.h>
#include <cuda_bf16.h>
#include <cstdint>
#include <math.h>

#define Bn 16
#define Sn 768
#define Hn 768
#define Tn 128
#define NQn 640
#define DHn 64
#define NHn 12
#define CHn 10
#define Mn (Bn * Sn)   // 12288

// ---------------- device scratch (no cudaMalloc allowed) -------------------
__device__ float g_Q[(size_t)Mn * Hn];
__device__ float g_K[(size_t)Mn * Hn];
__device__ float g_V[(size_t)Mn * Hn];
__device__ float g_Vsum[Bn * Hn];
__device__ float g_Wt[3 * Hn * Hn];     // tf32-rounded Wq|Wk|Wv
__device__ float g_At[(size_t)Mn * Hn]; // tf32-rounded hs

// ---------------------------------------------------------------------------
__device__ __forceinline__ float tf32r(float x)
{
    float r;
    asm("cvt.rna.tf32.f32 %0, %1;" : "=f"(r) : "f"(x));
    return r;
}

__device__ __forceinline__ void mma_tf32(float c[4], uint32_t a0, uint32_t a1,
                                         uint32_t a2, uint32_t a3,
                                         uint32_t b0, uint32_t b1)
{
    asm volatile(
        "mma.sync.aligned.m16n8k8.row.col.f32.tf32.tf32.f32 "
        "{%0,%1,%2,%3}, {%4,%5,%6,%7}, {%8,%9}, {%0,%1,%2,%3};\n"
        : "+f"(c[0]), "+f"(c[1]), "+f"(c[2]), "+f"(c[3])
        : "r"(a0), "r"(a1), "r"(a2), "r"(a3), "r"(b0), "r"(b1));
}

#define CPASYNC16(saddr, gptr) \
    asm volatile("cp.async.cg.shared.global [%0], [%1], 16;\n" :: "r"(saddr), "l"(gptr))
#define CP_COMMIT() asm volatile("cp.async.commit_group;\n")
#define CP_WAIT(N)  asm volatile("cp.async.wait_group %0;\n" :: "n"(N))

// ---------------------------------------------------------------------------
// Pre-rounding passes
// ---------------------------------------------------------------------------
__global__ void cvt_wall(const float* __restrict__ Wq, const float* __restrict__ Wk,
                         const float* __restrict__ Wv)
{
    const int n = Hn * Hn;
    for (int i = blockIdx.x * blockDim.x + threadIdx.x; i < 3 * n;
         i += gridDim.x * blockDim.x) {
        int z = i / n, j = i - z * n;
        const float* W = (z == 0) ? Wq : (z == 1) ? Wk : Wv;
        g_Wt[i] = tf32r(W[j]);
    }
}

__global__ void cvt_a(const float* __restrict__ hs)
{
    const int n4 = (Mn * Hn) / 4;
    float4* dst = (float4*)g_At;
    for (int i = blockIdx.x * blockDim.x + threadIdx.x; i < n4;
         i += gridDim.x * blockDim.x) {
        float4 x = ((const float4*)hs)[i];
        x.x = tf32r(x.x); x.y = tf32r(x.y);
        x.z = tf32r(x.z); x.w = tf32r(x.w);
        dst[i] = x;
    }
}

__global__ void vsum_zero()
{
    g_Vsum[blockIdx.x * Hn + threadIdx.x] = 0.f;
}

// ---------------------------------------------------------------------------
// tf32 tensor-core GEMM (R9 configuration: scalar LDS fragment loads).
// 128x128 tile, BK=32, 256 threads (8 warps 2x4), 3-stage cp.async, 2 CTAs/SM.
// ---------------------------------------------------------------------------
#define TILE_F 4608                  // 128 rows * 36 floats
#define TILE_BYTES (TILE_F * 4)      // 18432
#define STAGE_F (2 * TILE_F)
#define STAGE_BYTES (2 * TILE_BYTES) // 36864
#define GSTAGES 3
#define GEMM_SMEM (GSTAGES * STAGE_BYTES)  // 110592

__global__ __launch_bounds__(256, 2) void gemm_qkv(
    const float* __restrict__ bq, const float* __restrict__ bk,
    const float* __restrict__ bv)
{
    extern __shared__ float smem[];
    const uint32_t sbase = (uint32_t)__cvta_generic_to_shared(smem);

    const int tid = threadIdx.x;
    const int rowBase = blockIdx.y * 128;
    const int colBase = blockIdx.x * 128;
    const int z = blockIdx.z;

    const float* Ag = g_At + (size_t)rowBase * Hn;
    const float* Wt = g_Wt + (size_t)z * Hn * Hn + (size_t)colBase * Hn;
    float* C = (z == 0) ? g_Q : (z == 1) ? g_K : g_V;
    const float* bias = (z == 0) ? bq : (z == 1) ? bk : bv;

    const int warp  = tid >> 5;
    const int lane  = tid & 31;
    const int warpM = warp >> 2;
    const int warpN = warp & 3;
    const int g  = lane >> 2;
    const int t  = lane & 3;
    const int mrow = warpM * 64;
    const int nrow = warpN * 32;

    float acc[4][4][4];
#pragma unroll
    for (int mi = 0; mi < 4; mi++)
#pragma unroll
        for (int ni = 0; ni < 4; ni++)
#pragma unroll
            for (int r = 0; r < 4; r++) acc[mi][ni][r] = 0.f;

    auto load_stage = [&](int stage, int ktile) {
        uint32_t s0 = sbase + stage * STAGE_BYTES;
        int kb = ktile * 32;
#pragma unroll
        for (int i = 0; i < 8; i++) {
            int idx = i * 256 + tid;
            int arr = idx >> 10;
            int r = (idx >> 3) & 127;
            int c = idx & 7;
            const float* src = arr ? (Wt + (size_t)r * Hn + kb + c * 4)
                                   : (Ag + (size_t)r * Hn + kb + c * 4);
            CPASYNC16(s0 + arr * TILE_BYTES + (uint32_t)(r * 144 + c * 16), src);
        }
    };

    auto compute = [&](int stage) {
        const float* sA = smem + stage * STAGE_F;
        const float* sW = sA + TILE_F;
        const float* aB = sA + (mrow + g) * 36 + t;
        const float* bB = sW + (nrow + g) * 36 + t;
#pragma unroll
        for (int ks = 0; ks < 4; ks++) {
            const int kf = ks * 8;
            uint32_t a[4][4];
#pragma unroll
            for (int mi = 0; mi < 4; mi++) {
                a[mi][0] = __float_as_uint(aB[mi * 576 + kf]);
                a[mi][1] = __float_as_uint(aB[mi * 576 + 288 + kf]);
                a[mi][2] = __float_as_uint(aB[mi * 576 + kf + 4]);
                a[mi][3] = __float_as_uint(aB[mi * 576 + 288 + kf + 4]);
            }
            uint32_t b[4][2];
#pragma unroll
            for (int ni = 0; ni < 4; ni++) {
                b[ni][0] = __float_as_uint(bB[ni * 288 + kf]);
                b[ni][1] = __float_as_uint(bB[ni * 288 + kf + 4]);
            }
#pragma unroll
            for (int mi = 0; mi < 4; mi++)
#pragma unroll
                for (int ni = 0; ni < 4; ni++)
                    mma_tf32(acc[mi][ni], a[mi][0], a[mi][1], a[mi][2], a[mi][3],
                             b[ni][0], b[ni][1]);
        }
    };

    const int NKT = Hn / 32;   // 24
    load_stage(0, 0); CP_COMMIT();
    load_stage(1, 1); CP_COMMIT();

    for (int kt = 0; kt < NKT; kt++) {
        if (kt < NKT - 2) { CP_WAIT(1); } else { CP_WAIT(0); }
        __syncthreads();
        if (kt + 2 < NKT) {
            load_stage((kt + 2) % GSTAGES, kt + 2);
            CP_COMMIT();
        }
        compute(kt % GSTAGES);
    }

    // epilogue: add bias, store fp32
#pragma unroll
    for (int mi = 0; mi < 4; mi++) {
#pragma unroll
        for (int ni = 0; ni < 4; ni++) {
            int row0 = rowBase + mrow + mi * 16 + g;
            int col0 = colBase + nrow + ni * 8 + 2 * t;
            float b0 = bias[col0], b1 = bias[col0 + 1];
            float2 v0 = make_float2(acc[mi][ni][0] + b0, acc[mi][ni][1] + b1);
            float2 v1 = make_float2(acc[mi][ni][2] + b0, acc[mi][ni][3] + b1);
            *(float2*)(C + (size_t)row0 * Hn + col0) = v0;
            *(float2*)(C + (size_t)(row0 + 8) * Hn + col0) = v1;
        }
    }
}

// ---------------------------------------------------------------------------
__global__ void vsum_part()
{
    int b = blockIdx.x, c = blockIdx.y;
    int col = threadIdx.x;
    const float* base = g_V + ((size_t)b * Sn + c * 64) * Hn + col;
    float acc = 0.f;
#pragma unroll 8
    for (int s = 0; s < 64; s++) acc += base[(size_t)s * Hn];
    atomicAdd(&g_Vsum[b * Hn + col], acc);
}

__global__ void tail_copy(float* __restrict__ out)
{
    int b = blockIdx.x / Tn;
    int t = blockIdx.x % Tn;
    size_t r = (size_t)b * Sn + NQn + t;
    out[r * Hn + threadIdx.x] = g_V[r * Hn + threadIdx.x];
}

// ---------------------------------------------------------------------------
// Fused attention (512 threads, 2 CTAs/SM): one CTA per (chunk, head, batch).
// Scores via tf32 mma; softmax + PV SIMT (float2 score loads).
// smem: sq(64x68) + sk(192x68); sp(64x194) overlays sq/sk after score phase.
// ---------------------------------------------------------------------------
#define SQS 68
#define SPS 194
#define SMALL_OFF (64 * SQS + 192 * SQS)   // 17408 floats (sp 64*194=12416 fits)

__global__ __launch_bounds__(512, 2) void attn_kernel(float* __restrict__ out)
{
    extern __shared__ float sm[];
    float* sq  = sm;                    // 64 * 68
    float* sk  = sm + 64 * SQS;         // 192 * 68
    float* sp  = sm;                    // overlay
    float* sem = sm + SMALL_OFF;        // 64
    float* sz  = sem + 64;              // 64
    float* sms = sz + 64;               // 64

    const int tid = threadIdx.x;
    const int chunk = blockIdx.x;
    const int h = blockIdx.y;
    const int b = blockIdx.z;

    const size_t baseC = ((size_t)b * Sn + chunk * 64) * Hn + h * DHn;
    const size_t baseT = ((size_t)b * Sn + 576) * Hn + h * DHn;   // rows 576+j, j>=64
    const float* vc = g_V + baseC;
    const float* vt = g_V + ((size_t)b * Sn + NQn) * Hn + h * DHn;

    for (int idx = tid; idx < 64 * 64; idx += 512) {
        int i = idx >> 6, d = idx & 63;
        sq[i * SQS + d] = g_Q[baseC + (size_t)i * Hn + d];
    }
    for (int idx = tid; idx < 192 * 64; idx += 512) {
        int j = idx >> 6, d = idx & 63;
        size_t off = (j < 64) ? (baseC + (size_t)j * Hn + d)
                              : (baseT + (size_t)j * Hn + d);
        sk[j * SQS + d] = g_K[off];
    }
    __syncthreads();

    const int lane = tid & 31;
    const int wid = tid >> 5;
    const int g = lane >> 2;
    const int t = lane & 3;
    const int mbase = (wid & 3) * 16;    // 4 row-groups of 16
    const int nbase = (wid >> 2) * 48;   // 4 col-groups of 48

    // ---- scores: tf32 mma, each warp 16 rows x 48 cols over k=64 ----
    float acc[6][4];
#pragma unroll
    for (int nt = 0; nt < 6; nt++)
#pragma unroll
        for (int r = 0; r < 4; r++) acc[nt][r] = 0.f;

#pragma unroll
    for (int ks = 0; ks < 8; ks++) {
        const int k0 = ks * 8;
        uint32_t a0 = __float_as_uint(tf32r(sq[(mbase + g) * SQS + k0 + t]));
        uint32_t a1 = __float_as_uint(tf32r(sq[(mbase + g + 8) * SQS + k0 + t]));
        uint32_t a2 = __float_as_uint(tf32r(sq[(mbase + g) * SQS + k0 + t + 4]));
        uint32_t a3 = __float_as_uint(tf32r(sq[(mbase + g + 8) * SQS + k0 + t + 4]));
#pragma unroll
        for (int nt = 0; nt < 6; nt++) {
            const int n = nbase + nt * 8 + g;
            uint32_t b0 = __float_as_uint(tf32r(sk[n * SQS + k0 + t]));
            uint32_t b1 = __float_as_uint(tf32r(sk[n * SQS + k0 + t + 4]));
            mma_tf32(acc[nt], a0, a1, a2, a3, b0, b1);
        }
    }
    __syncthreads();   // all sq/sk reads done -> safe to overlay sp

#pragma unroll
    for (int nt = 0; nt < 6; nt++) {
        const int c0 = nbase + nt * 8 + 2 * t;
        *(float2*)&sp[(mbase + g) * SPS + c0] =
            make_float2(acc[nt][0] * 0.125f, acc[nt][1] * 0.125f);
        *(float2*)&sp[(mbase + g + 8) * SPS + c0] =
            make_float2(acc[nt][2] * 0.125f, acc[nt][3] * 0.125f);
    }

    // masked-v sum: d = tid/8, 8 threads sum 8 chunk-rows each (global reads)
    {
        const int d = tid >> 3, part = tid & 7;
        float s = 0.f;
#pragma unroll
        for (int j = part * 8; j < part * 8 + 8; j++)
            s += __ldg(vc + (size_t)j * Hn + d);
        s += __shfl_xor_sync(0xFFFFFFFFu, s, 1);
        s += __shfl_xor_sync(0xFFFFFFFFu, s, 2);
        s += __shfl_xor_sync(0xFFFFFFFFu, s, 4);
        if (part == 0) sms[d] = __ldg(&g_Vsum[b * Hn + h * DHn + d]) - s;
    }
    __syncthreads();

    // softmax: row = tid/8, 8 threads x 24 cols; masked cols add 576*exp(-m)
    {
        const int i = tid >> 3, part = tid & 7;
        const int j0 = part * 24;
        float m = 0.f;   // masked scores are exactly 0
#pragma unroll
        for (int j = j0; j < j0 + 24; j++) m = fmaxf(m, sp[i * SPS + j]);
        m = fmaxf(m, __shfl_xor_sync(0xFFFFFFFFu, m, 1));
        m = fmaxf(m, __shfl_xor_sync(0xFFFFFFFFu, m, 2));
        m = fmaxf(m, __shfl_xor_sync(0xFFFFFFFFu, m, 4));
        float Z = 0.f;
#pragma unroll
        for (int j = j0; j < j0 + 24; j++) {
            float e = __expf(sp[i * SPS + j] - m);
            sp[i * SPS + j] = e;
            Z += e;
        }
        Z += __shfl_xor_sync(0xFFFFFFFFu, Z, 1);
        Z += __shfl_xor_sync(0xFFFFFFFFu, Z, 2);
        Z += __shfl_xor_sync(0xFFFFFFFFu, Z, 4);
        if (part == 0) {
            float em = __expf(-m);
            sem[i] = em;
            sz[i] = 1.f / (Z + 576.f * em);
        }
    }
    __syncthreads();

    // ctx: 2 rows x 4 cols per thread; V via __ldg, scores via float2 LDS
    {
        const int tx = tid & 15;
        const int i0 = (tid >> 4) * 2;
        float o[2][4];
#pragma unroll
        for (int ii = 0; ii < 2; ii++)
#pragma unroll
            for (int dd = 0; dd < 4; dd++) o[ii][dd] = 0.f;
        const int d0 = tx * 4;
#pragma unroll 4
        for (int j = 0; j < 64; j += 2) {
            float2 pA = *(const float2*)&sp[i0 * SPS + j];
            float2 pB = *(const float2*)&sp[(i0 + 1) * SPS + j];
            float4 v0 = __ldg((const float4*)(vc + (size_t)j * Hn + d0));
            float4 v1 = __ldg((const float4*)(vc + (size_t)(j + 1) * Hn + d0));
            o[0][0] = fmaf(pA.x, v0.x, fmaf(pA.y, v1.x, o[0][0]));
            o[0][1] = fmaf(pA.x, v0.y, fmaf(pA.y, v1.y, o[0][1]));
            o[0][2] = fmaf(pA.x, v0.z, fmaf(pA.y, v1.z, o[0][2]));
            o[0][3] = fmaf(pA.x, v0.w, fmaf(pA.y, v1.w, o[0][3]));
            o[1][0] = fmaf(pB.x, v0.x, fmaf(pB.y, v1.x, o[1][0]));
            o[1][1] = fmaf(pB.x, v0.y, fmaf(pB.y, v1.y, o[1][1]));
            o[1][2] = fmaf(pB.x, v0.z, fmaf(pB.y, v1.z, o[1][2]));
            o[1][3] = fmaf(pB.x, v0.w, fmaf(pB.y, v1.w, o[1][3]));
        }
#pragma unroll 4
        for (int j = 0; j < 128; j += 2) {
            float2 pA = *(const float2*)&sp[i0 * SPS + 64 + j];
            float2 pB = *(const float2*)&sp[(i0 + 1) * SPS + 64 + j];
            float4 v0 = __ldg((const float4*)(vt + (size_t)j * Hn + d0));
            float4 v1 = __ldg((const float4*)(vt + (size_t)(j + 1) * Hn + d0));
            o[0][0] = fmaf(pA.x, v0.x, fmaf(pA.y, v1.x, o[0][0]));
            o[0][1] = fmaf(pA.x, v0.y, fmaf(pA.y, v1.y, o[0][1]));
            o[0][2] = fmaf(pA.x, v0.z, fmaf(pA.y, v1.z, o[0][2]));
            o[0][3] = fmaf(pA.x, v0.w, fmaf(pA.y, v1.w, o[0][3]));
            o[1][0] = fmaf(pB.x, v0.x, fmaf(pB.y, v1.x, o[1][0]));
            o[1][1] = fmaf(pB.x, v0.y, fmaf(pB.y, v1.y, o[1][1]));
            o[1][2] = fmaf(pB.x, v0.z, fmaf(pB.y, v1.z, o[1][2]));
            o[1][3] = fmaf(pB.x, v0.w, fmaf(pB.y, v1.w, o[1][3]));
        }
#pragma unroll
        for (int ii = 0; ii < 2; ii++) {
            float inv = sz[i0 + ii];
            float em  = sem[i0 + ii];
            float4 ov;
            ov.x = (o[ii][0] + em * sms[d0 + 0]) * inv;
            ov.y = (o[ii][1] + em * sms[d0 + 1]) * inv;
            ov.z = (o[ii][2] + em * sms[d0 + 2]) * inv;
            ov.w = (o[ii][3] + em * sms[d0 + 3]) * inv;
            *(float4*)(out + ((size_t)b * Sn + chunk * 64 + i0 + ii) * Hn + h * DHn + d0) = ov;
        }
    }
}

// ---------------------------------------------------------------------------
extern "C" void kernel_launch(void* const* d_in, const int* in_sizes, int n_in,
                              void* d_out, int out_size)
{
    const float* hs = (const float*)d_in[0];
    const float* Wq = (const float*)d_in[1];
    const float* bq = (const float*)d_in[2];
    const float* Wk = (const float*)d_in[3];
    const float* bk = (const float*)d_in[4];
    const float* Wv = (const float*)d_in[5];
    const float* bv = (const float*)d_in[6];
    float* out = (float*)d_out;

    cvt_wall<<<1024, 256>>>(Wq, Wk, Wv);     // idx 0
    cvt_a<<<2048, 256>>>(hs);                // idx 1
    vsum_zero<<<Bn, Hn>>>();                 // idx 2

    cudaFuncSetAttribute(gemm_qkv, cudaFuncAttributeMaxDynamicSharedMemorySize,
                         GEMM_SMEM);
    gemm_qkv<<<dim3(Hn / 128, Mn / 128, 3), 256, GEMM_SMEM>>>(bq, bk, bv); // idx 3 (ncu)

    vsum_part<<<dim3(Bn, CHn), Hn>>>();
    tail_copy<<<Bn * Tn, Hn>>>(out);

    const size_t attn_smem = (size_t)(SMALL_OFF + 3 * 64) * sizeof(float);  // 70400 B
    cudaFuncSetAttribute(attn_kernel, cudaFuncAttributeMaxDynamicSharedMemorySize,
                         (int)attn_smem);
    attn_kernel<<<dim3(CHn, NHn, Bn), 512, attn_smem>>>(out);
}

// round 12
// speedup vs baseline: 1.8560x; 1.1924x over previous
#include <cuda_runtime.h>
#include <cuda_bf16.h>
#include <cstdint>
#include <math.h>

#define Bn 16
#define Sn 768
#define Hn 768
#define Tn 128
#define NQn 640
#define DHn 64
#define NHn 12
#define CHn 10
#define Mn (Bn * Sn)   // 12288

// ---------------- device scratch (no cudaMalloc allowed) -------------------
__device__ float g_Q[(size_t)Mn * Hn];
__device__ float g_K[(size_t)Mn * Hn];
__device__ float g_V[(size_t)Mn * Hn];
__device__ float g_Vsum[Bn * Hn];
__device__ float g_Wt[3 * Hn * Hn];     // tf32-rounded Wq|Wk|Wv
__device__ float g_At[(size_t)Mn * Hn]; // tf32-rounded hs

// ---------------------------------------------------------------------------
__device__ __forceinline__ float tf32r(float x)
{
    float r;
    asm("cvt.rna.tf32.f32 %0, %1;" : "=f"(r) : "f"(x));
    return r;
}

__device__ __forceinline__ void mma_tf32(float c[4], uint32_t a0, uint32_t a1,
                                         uint32_t a2, uint32_t a3,
                                         uint32_t b0, uint32_t b1)
{
    asm volatile(
        "mma.sync.aligned.m16n8k8.row.col.f32.tf32.tf32.f32 "
        "{%0,%1,%2,%3}, {%4,%5,%6,%7}, {%8,%9}, {%0,%1,%2,%3};\n"
        : "+f"(c[0]), "+f"(c[1]), "+f"(c[2]), "+f"(c[3])
        : "r"(a0), "r"(a1), "r"(a2), "r"(a3), "r"(b0), "r"(b1));
}

#define CPASYNC16(saddr, gptr) \
    asm volatile("cp.async.cg.shared.global [%0], [%1], 16;\n" :: "r"(saddr), "l"(gptr))
#define CP_COMMIT() asm volatile("cp.async.commit_group;\n")
#define CP_WAIT(N)  asm volatile("cp.async.wait_group %0;\n" :: "n"(N))

// ---------------------------------------------------------------------------
// Pre-rounding passes
// ---------------------------------------------------------------------------
__global__ void cvt_wall(const float* __restrict__ Wq, const float* __restrict__ Wk,
                         const float* __restrict__ Wv)
{
    const int n = Hn * Hn;
    for (int i = blockIdx.x * blockDim.x + threadIdx.x; i < 3 * n;
         i += gridDim.x * blockDim.x) {
        int z = i / n, j = i - z * n;
        const float* W = (z == 0) ? Wq : (z == 1) ? Wk : Wv;
        g_Wt[i] = tf32r(W[j]);
    }
}

__global__ void cvt_a(const float* __restrict__ hs)
{
    const int n4 = (Mn * Hn) / 4;
    float4* dst = (float4*)g_At;
    for (int i = blockIdx.x * blockDim.x + threadIdx.x; i < n4;
         i += gridDim.x * blockDim.x) {
        float4 x = ((const float4*)hs)[i];
        x.x = tf32r(x.x); x.y = tf32r(x.y);
        x.z = tf32r(x.z); x.w = tf32r(x.w);
        dst[i] = x;
    }
}

__global__ void vsum_zero()
{
    g_Vsum[blockIdx.x * Hn + threadIdx.x] = 0.f;
}

// ---------------------------------------------------------------------------
// tf32 tensor-core GEMM (scalar LDS fragment loads).
// Outputs tf32-rounded (consumed by tf32-MMA attention).
// Skips unused Q tiles (rows 640-767 of each batch; tile y%6==5, z==0).
// ---------------------------------------------------------------------------
#define TILE_F 4608                  // 128 rows * 36 floats
#define TILE_BYTES (TILE_F * 4)      // 18432
#define STAGE_F (2 * TILE_F)
#define STAGE_BYTES (2 * TILE_BYTES) // 36864
#define GSTAGES 3
#define GEMM_SMEM (GSTAGES * STAGE_BYTES)  // 110592

__global__ __launch_bounds__(256, 2) void gemm_qkv(
    const float* __restrict__ bq, const float* __restrict__ bk,
    const float* __restrict__ bv)
{
    extern __shared__ float smem[];
    const uint32_t sbase = (uint32_t)__cvta_generic_to_shared(smem);

    const int tid = threadIdx.x;
    const int rowBase = blockIdx.y * 128;
    const int colBase = blockIdx.x * 128;
    const int z = blockIdx.z;

    if (z == 0 && (blockIdx.y % 6) == 5) return;   // Q tail rows never read

    const float* Ag = g_At + (size_t)rowBase * Hn;
    const float* Wt = g_Wt + (size_t)z * Hn * Hn + (size_t)colBase * Hn;
    float* C = (z == 0) ? g_Q : (z == 1) ? g_K : g_V;
    const float* bias = (z == 0) ? bq : (z == 1) ? bk : bv;

    const int warp  = tid >> 5;
    const int lane  = tid & 31;
    const int warpM = warp >> 2;
    const int warpN = warp & 3;
    const int g  = lane >> 2;
    const int t  = lane & 3;
    const int mrow = warpM * 64;
    const int nrow = warpN * 32;

    float acc[4][4][4];
#pragma unroll
    for (int mi = 0; mi < 4; mi++)
#pragma unroll
        for (int ni = 0; ni < 4; ni++)
#pragma unroll
            for (int r = 0; r < 4; r++) acc[mi][ni][r] = 0.f;

    auto load_stage = [&](int stage, int ktile) {
        uint32_t s0 = sbase + stage * STAGE_BYTES;
        int kb = ktile * 32;
#pragma unroll
        for (int i = 0; i < 8; i++) {
            int idx = i * 256 + tid;
            int arr = idx >> 10;
            int r = (idx >> 3) & 127;
            int c = idx & 7;
            const float* src = arr ? (Wt + (size_t)r * Hn + kb + c * 4)
                                   : (Ag + (size_t)r * Hn + kb + c * 4);
            CPASYNC16(s0 + arr * TILE_BYTES + (uint32_t)(r * 144 + c * 16), src);
        }
    };

    auto compute = [&](int stage) {
        const float* sA = smem + stage * STAGE_F;
        const float* sW = sA + TILE_F;
        const float* aB = sA + (mrow + g) * 36 + t;
        const float* bB = sW + (nrow + g) * 36 + t;
#pragma unroll
        for (int ks = 0; ks < 4; ks++) {
            const int kf = ks * 8;
            uint32_t a[4][4];
#pragma unroll
            for (int mi = 0; mi < 4; mi++) {
                a[mi][0] = __float_as_uint(aB[mi * 576 + kf]);
                a[mi][1] = __float_as_uint(aB[mi * 576 + 288 + kf]);
                a[mi][2] = __float_as_uint(aB[mi * 576 + kf + 4]);
                a[mi][3] = __float_as_uint(aB[mi * 576 + 288 + kf + 4]);
            }
            uint32_t b[4][2];
#pragma unroll
            for (int ni = 0; ni < 4; ni++) {
                b[ni][0] = __float_as_uint(bB[ni * 288 + kf]);
                b[ni][1] = __float_as_uint(bB[ni * 288 + kf + 4]);
            }
#pragma unroll
            for (int mi = 0; mi < 4; mi++)
#pragma unroll
                for (int ni = 0; ni < 4; ni++)
                    mma_tf32(acc[mi][ni], a[mi][0], a[mi][1], a[mi][2], a[mi][3],
                             b[ni][0], b[ni][1]);
        }
    };

    const int NKT = Hn / 32;   // 24
    load_stage(0, 0); CP_COMMIT();
    load_stage(1, 1); CP_COMMIT();

    for (int kt = 0; kt < NKT; kt++) {
        if (kt < NKT - 2) { CP_WAIT(1); } else { CP_WAIT(0); }
        __syncthreads();
        if (kt + 2 < NKT) {
            load_stage((kt + 2) % GSTAGES, kt + 2);
            CP_COMMIT();
        }
        compute(kt % GSTAGES);
    }

    // epilogue: add bias, round to tf32, store
#pragma unroll
    for (int mi = 0; mi < 4; mi++) {
#pragma unroll
        for (int ni = 0; ni < 4; ni++) {
            int row0 = rowBase + mrow + mi * 16 + g;
            int col0 = colBase + nrow + ni * 8 + 2 * t;
            float b0 = bias[col0], b1 = bias[col0 + 1];
            float2 v0 = make_float2(tf32r(acc[mi][ni][0] + b0), tf32r(acc[mi][ni][1] + b1));
            float2 v1 = make_float2(tf32r(acc[mi][ni][2] + b0), tf32r(acc[mi][ni][3] + b1));
            *(float2*)(C + (size_t)row0 * Hn + col0) = v0;
            *(float2*)(C + (size_t)(row0 + 8) * Hn + col0) = v1;
        }
    }
}

// ---------------------------------------------------------------------------
__global__ void vsum_part()
{
    int b = blockIdx.x, c = blockIdx.y;
    int col = threadIdx.x;
    const float* base = g_V + ((size_t)b * Sn + c * 64) * Hn + col;
    float acc = 0.f;
#pragma unroll 8
    for (int s = 0; s < 64; s++) acc += base[(size_t)s * Hn];
    atomicAdd(&g_Vsum[b * Hn + col], acc);
}

__global__ void tail_copy(float* __restrict__ out)
{
    int b = blockIdx.x / Tn;
    int t = blockIdx.x % Tn;
    size_t r = (size_t)b * Sn + NQn + t;
    out[r * Hn + threadIdx.x] = g_V[r * Hn + threadIdx.x];
}

// ---------------------------------------------------------------------------
// Fused attention (512 threads, 2 CTAs/SM): one CTA per (chunk, head, batch).
// Scores: tf32 mma (Q/K pre-rounded). PV: tf32 mma with V B-fragments loaded
// straight from global (L1/L2-hot), P read from sp (tf32-rounded at softmax).
// smem: sq(64x68) + sk(192x68); sp(64x196) overlays sq/sk after score phase.
// ---------------------------------------------------------------------------
#define SQS 68
#define SPS 196
#define SMALL_OFF (64 * SQS + 192 * SQS)   // 17408 floats (sp 64*196=12544 fits)

__global__ __launch_bounds__(512, 2) void attn_kernel(float* __restrict__ out)
{
    extern __shared__ float sm[];
    float* sq  = sm;                    // 64 * 68
    float* sk  = sm + 64 * SQS;         // 192 * 68
    float* sp  = sm;                    // overlay
    float* sem = sm + SMALL_OFF;        // 64
    float* sz  = sem + 64;              // 64
    float* sms = sz + 64;               // 64

    const int tid = threadIdx.x;
    const int chunk = blockIdx.x;
    const int h = blockIdx.y;
    const int b = blockIdx.z;

    const size_t rowC = (size_t)b * Sn + chunk * 64;
    const size_t baseC = rowC * Hn + h * DHn;
    const size_t baseT = ((size_t)b * Sn + 576) * Hn + h * DHn;   // rows 576+j, j>=64
    const float* vc = g_V + baseC;
    const float* vt = g_V + ((size_t)b * Sn + NQn) * Hn + h * DHn;

    for (int idx = tid; idx < 64 * 64; idx += 512) {
        int i = idx >> 6, d = idx & 63;
        sq[i * SQS + d] = g_Q[baseC + (size_t)i * Hn + d];
    }
    for (int idx = tid; idx < 192 * 64; idx += 512) {
        int j = idx >> 6, d = idx & 63;
        size_t off = (j < 64) ? (baseC + (size_t)j * Hn + d)
                              : (baseT + (size_t)j * Hn + d);
        sk[j * SQS + d] = g_K[off];
    }
    __syncthreads();

    const int lane = tid & 31;
    const int wid = tid >> 5;
    const int g = lane >> 2;
    const int t = lane & 3;
    const int mbase = (wid & 3) * 16;    // 4 row-groups of 16
    const int nbase = (wid >> 2) * 48;   // 4 col-groups of 48 (scores)

    // ---- scores: tf32 mma, each warp 16 rows x 48 cols over k=64 ----
    float acc[6][4];
#pragma unroll
    for (int nt = 0; nt < 6; nt++)
#pragma unroll
        for (int r = 0; r < 4; r++) acc[nt][r] = 0.f;

#pragma unroll
    for (int ks = 0; ks < 8; ks++) {
        const int k0 = ks * 8;
        uint32_t a0 = __float_as_uint(sq[(mbase + g) * SQS + k0 + t]);
        uint32_t a1 = __float_as_uint(sq[(mbase + g + 8) * SQS + k0 + t]);
        uint32_t a2 = __float_as_uint(sq[(mbase + g) * SQS + k0 + t + 4]);
        uint32_t a3 = __float_as_uint(sq[(mbase + g + 8) * SQS + k0 + t + 4]);
#pragma unroll
        for (int nt = 0; nt < 6; nt++) {
            const int n = nbase + nt * 8 + g;
            uint32_t b0 = __float_as_uint(sk[n * SQS + k0 + t]);
            uint32_t b1 = __float_as_uint(sk[n * SQS + k0 + t + 4]);
            mma_tf32(acc[nt], a0, a1, a2, a3, b0, b1);
        }
    }
    __syncthreads();   // all sq/sk reads done -> safe to overlay sp

#pragma unroll
    for (int nt = 0; nt < 6; nt++) {
        const int c0 = nbase + nt * 8 + 2 * t;
        *(float2*)&sp[(mbase + g) * SPS + c0] =
            make_float2(acc[nt][0] * 0.125f, acc[nt][1] * 0.125f);
        *(float2*)&sp[(mbase + g + 8) * SPS + c0] =
            make_float2(acc[nt][2] * 0.125f, acc[nt][3] * 0.125f);
    }

    // masked-v sum: d = tid/8, 8 threads sum 8 chunk-rows each (global reads)
    {
        const int d = tid >> 3, part = tid & 7;
        float s = 0.f;
#pragma unroll
        for (int j = part * 8; j < part * 8 + 8; j++)
            s += __ldg(vc + (size_t)j * Hn + d);
        s += __shfl_xor_sync(0xFFFFFFFFu, s, 1);
        s += __shfl_xor_sync(0xFFFFFFFFu, s, 2);
        s += __shfl_xor_sync(0xFFFFFFFFu, s, 4);
        if (part == 0) sms[d] = __ldg(&g_Vsum[b * Hn + h * DHn + d]) - s;
    }
    __syncthreads();

    // softmax: row = tid/8, 8 threads x 24 cols; probs stored tf32-rounded
    {
        const int i = tid >> 3, part = tid & 7;
        const int j0 = part * 24;
        float m = 0.f;   // masked scores are exactly 0
#pragma unroll
        for (int j = j0; j < j0 + 24; j++) m = fmaxf(m, sp[i * SPS + j]);
        m = fmaxf(m, __shfl_xor_sync(0xFFFFFFFFu, m, 1));
        m = fmaxf(m, __shfl_xor_sync(0xFFFFFFFFu, m, 2));
        m = fmaxf(m, __shfl_xor_sync(0xFFFFFFFFu, m, 4));
        float Z = 0.f;
#pragma unroll
        for (int j = j0; j < j0 + 24; j++) {
            float e = tf32r(__expf(sp[i * SPS + j] - m));
            sp[i * SPS + j] = e;
            Z += e;
        }
        Z += __shfl_xor_sync(0xFFFFFFFFu, Z, 1);
        Z += __shfl_xor_sync(0xFFFFFFFFu, Z, 2);
        Z += __shfl_xor_sync(0xFFFFFFFFu, Z, 4);
        if (part == 0) {
            float em = __expf(-m);
            sem[i] = em;
            sz[i] = 1.f / (Z + 576.f * em);
        }
    }
    __syncthreads();

    // ---- PV: tf32 mma; warp = 16 q-rows x 16 d-cols; V frags from global ----
    {
        const int dbase = (wid >> 2) * 16;
        float c0[4] = {0.f, 0.f, 0.f, 0.f};
        float c1[4] = {0.f, 0.f, 0.f, 0.f};

#pragma unroll
        for (int ks = 0; ks < 24; ks++) {
            const int k0 = ks * 8;
            const float* vb = (ks < 8) ? (vc + (size_t)(k0 + t) * Hn)
                                       : (vt + (size_t)(k0 - 64 + t) * Hn);
            const float* vb2 = vb + 4 * Hn;   // row k0+t+4, same region (8-blocks)
            uint32_t a0 = __float_as_uint(sp[(mbase + g) * SPS + k0 + t]);
            uint32_t a1 = __float_as_uint(sp[(mbase + g + 8) * SPS + k0 + t]);
            uint32_t a2 = __float_as_uint(sp[(mbase + g) * SPS + k0 + t + 4]);
            uint32_t a3 = __float_as_uint(sp[(mbase + g + 8) * SPS + k0 + t + 4]);
            uint32_t b00 = __float_as_uint(__ldg(vb  + dbase + g));
            uint32_t b01 = __float_as_uint(__ldg(vb2 + dbase + g));
            uint32_t b10 = __float_as_uint(__ldg(vb  + dbase + 8 + g));
            uint32_t b11 = __float_as_uint(__ldg(vb2 + dbase + 8 + g));
            mma_tf32(c0, a0, a1, a2, a3, b00, b01);
            mma_tf32(c1, a0, a1, a2, a3, b10, b11);
        }

        const int r0 = mbase + g, r1 = r0 + 8;
        const float inv0 = sz[r0], em0 = sem[r0];
        const float inv1 = sz[r1], em1 = sem[r1];
#pragma unroll
        for (int nt = 0; nt < 2; nt++) {
            const float* cc = nt ? c1 : c0;
            const int col = dbase + nt * 8 + 2 * t;
            const float s0 = sms[col], s1 = sms[col + 1];
            float2 o0 = make_float2((cc[0] + em0 * s0) * inv0,
                                    (cc[1] + em0 * s1) * inv0);
            float2 o1 = make_float2((cc[2] + em1 * s0) * inv1,
                                    (cc[3] + em1 * s1) * inv1);
            *(float2*)(out + (rowC + r0) * Hn + h * DHn + col) = o0;
            *(float2*)(out + (rowC + r1) * Hn + h * DHn + col) = o1;
        }
    }
}

// ---------------------------------------------------------------------------
extern "C" void kernel_launch(void* const* d_in, const int* in_sizes, int n_in,
                              void* d_out, int out_size)
{
    const float* hs = (const float*)d_in[0];
    const float* Wq = (const float*)d_in[1];
    const float* bq = (const float*)d_in[2];
    const float* Wk = (const float*)d_in[3];
    const float* bk = (const float*)d_in[4];
    const float* Wv = (const float*)d_in[5];
    const float* bv = (const float*)d_in[6];
    float* out = (float*)d_out;

    cvt_wall<<<1024, 256>>>(Wq, Wk, Wv);     // idx 0
    cvt_a<<<2048, 256>>>(hs);                // idx 1
    vsum_zero<<<Bn, Hn>>>();                 // idx 2

    cudaFuncSetAttribute(gemm_qkv, cudaFuncAttributeMaxDynamicSharedMemorySize,
                         GEMM_SMEM);
    gemm_qkv<<<dim3(Hn / 128, Mn / 128, 3), 256, GEMM_SMEM>>>(bq, bk, bv); // idx 3 (ncu)

    vsum_part<<<dim3(Bn, CHn), Hn>>>();
    tail_copy<<<Bn * Tn, Hn>>>(out);

    const size_t attn_smem = (size_t)(SMALL_OFF + 3 * 64) * sizeof(float);  // 70400 B
    cudaFuncSetAttribute(attn_kernel, cudaFuncAttributeMaxDynamicSharedMemorySize,
                         (int)attn_smem);
    attn_kernel<<<dim3(CHn, NHn, Bn), 512, attn_smem>>>(out);
}

// round 13
// speedup vs baseline: 1.9069x; 1.0274x over previous
#include <cuda_runtime.h>
#include <cuda_bf16.h>
#include <cstdint>
#include <math.h>

#define Bn 16
#define Sn 768
#define Hn 768
#define Tn 128
#define NQn 640
#define DHn 64
#define NHn 12
#define CHn 10
#define Mn (Bn * Sn)   // 12288

// ---------------- device scratch (no cudaMalloc allowed) -------------------
__device__ float g_Q[(size_t)Mn * Hn];
__device__ float g_K[(size_t)Mn * Hn];
__device__ float g_V[(size_t)Mn * Hn];
__device__ float g_Vsum[Bn * Hn];
__device__ float g_Wt[3 * Hn * Hn];     // tf32-rounded Wq|Wk|Wv
__device__ float g_At[(size_t)Mn * Hn]; // tf32-rounded hs

// ---------------------------------------------------------------------------
__device__ __forceinline__ float tf32r(float x)
{
    float r;
    asm("cvt.rna.tf32.f32 %0, %1;" : "=f"(r) : "f"(x));
    return r;
}

__device__ __forceinline__ void mma_tf32(float c[4], uint32_t a0, uint32_t a1,
                                         uint32_t a2, uint32_t a3,
                                         uint32_t b0, uint32_t b1)
{
    asm volatile(
        "mma.sync.aligned.m16n8k8.row.col.f32.tf32.tf32.f32 "
        "{%0,%1,%2,%3}, {%4,%5,%6,%7}, {%8,%9}, {%0,%1,%2,%3};\n"
        : "+f"(c[0]), "+f"(c[1]), "+f"(c[2]), "+f"(c[3])
        : "r"(a0), "r"(a1), "r"(a2), "r"(a3), "r"(b0), "r"(b1));
}

#define CPASYNC16(saddr, gptr) \
    asm volatile("cp.async.cg.shared.global [%0], [%1], 16;\n" :: "r"(saddr), "l"(gptr))
#define CP_COMMIT() asm volatile("cp.async.commit_group;\n")
#define CP_WAIT(N)  asm volatile("cp.async.wait_group %0;\n" :: "n"(N))

// ---------------------------------------------------------------------------
// prep: fused W-round + A-round + Vsum zero
// ---------------------------------------------------------------------------
__global__ void prep(const float* __restrict__ hs,
                     const float* __restrict__ Wq, const float* __restrict__ Wk,
                     const float* __restrict__ Wv)
{
    const int gs = gridDim.x * blockDim.x;
    const int t0 = blockIdx.x * blockDim.x + threadIdx.x;

    // A: tf32-round hs (float4 granules)
    const int n4 = (Mn * Hn) / 4;
    float4* dst = (float4*)g_At;
    for (int i = t0; i < n4; i += gs) {
        float4 x = ((const float4*)hs)[i];
        x.x = tf32r(x.x); x.y = tf32r(x.y);
        x.z = tf32r(x.z); x.w = tf32r(x.w);
        dst[i] = x;
    }
    // W: tf32-round all three
    const int n = Hn * Hn;
    for (int i = t0; i < 3 * n; i += gs) {
        int z = i / n, j = i - z * n;
        const float* W = (z == 0) ? Wq : (z == 1) ? Wk : Wv;
        g_Wt[i] = tf32r(W[j]);
    }
    // Vsum zero
    for (int i = t0; i < Bn * Hn; i += gs) g_Vsum[i] = 0.f;
}

// ---------------------------------------------------------------------------
// tf32 tensor-core GEMM. Outputs tf32-rounded. Skips unused Q tiles.
// V tiles (z==2, rows<640) also accumulate per-column sums into g_Vsum.
// ---------------------------------------------------------------------------
#define TILE_F 4608                  // 128 rows * 36 floats
#define TILE_BYTES (TILE_F * 4)      // 18432
#define STAGE_F (2 * TILE_F)
#define STAGE_BYTES (2 * TILE_BYTES) // 36864
#define GSTAGES 3
#define GEMM_SMEM (GSTAGES * STAGE_BYTES)  // 110592

__global__ __launch_bounds__(256, 2) void gemm_qkv(
    const float* __restrict__ bq, const float* __restrict__ bk,
    const float* __restrict__ bv)
{
    extern __shared__ float smem[];
    const uint32_t sbase = (uint32_t)__cvta_generic_to_shared(smem);

    const int tid = threadIdx.x;
    const int rowBase = blockIdx.y * 128;
    const int colBase = blockIdx.x * 128;
    const int z = blockIdx.z;

    if (z == 0 && (blockIdx.y % 6) == 5) return;   // Q tail rows never read

    const float* Ag = g_At + (size_t)rowBase * Hn;
    const float* Wt = g_Wt + (size_t)z * Hn * Hn + (size_t)colBase * Hn;
    float* C = (z == 0) ? g_Q : (z == 1) ? g_K : g_V;
    const float* bias = (z == 0) ? bq : (z == 1) ? bk : bv;

    const int warp  = tid >> 5;
    const int lane  = tid & 31;
    const int warpM = warp >> 2;
    const int warpN = warp & 3;
    const int g  = lane >> 2;
    const int t  = lane & 3;
    const int mrow = warpM * 64;
    const int nrow = warpN * 32;

    float acc[4][4][4];
#pragma unroll
    for (int mi = 0; mi < 4; mi++)
#pragma unroll
        for (int ni = 0; ni < 4; ni++)
#pragma unroll
            for (int r = 0; r < 4; r++) acc[mi][ni][r] = 0.f;

    auto load_stage = [&](int stage, int ktile) {
        uint32_t s0 = sbase + stage * STAGE_BYTES;
        int kb = ktile * 32;
#pragma unroll
        for (int i = 0; i < 8; i++) {
            int idx = i * 256 + tid;
            int arr = idx >> 10;
            int r = (idx >> 3) & 127;
            int c = idx & 7;
            const float* src = arr ? (Wt + (size_t)r * Hn + kb + c * 4)
                                   : (Ag + (size_t)r * Hn + kb + c * 4);
            CPASYNC16(s0 + arr * TILE_BYTES + (uint32_t)(r * 144 + c * 16), src);
        }
    };

    auto compute = [&](int stage) {
        const float* sA = smem + stage * STAGE_F;
        const float* sW = sA + TILE_F;
        const float* aB = sA + (mrow + g) * 36 + t;
        const float* bB = sW + (nrow + g) * 36 + t;
#pragma unroll
        for (int ks = 0; ks < 4; ks++) {
            const int kf = ks * 8;
            uint32_t a[4][4];
#pragma unroll
            for (int mi = 0; mi < 4; mi++) {
                a[mi][0] = __float_as_uint(aB[mi * 576 + kf]);
                a[mi][1] = __float_as_uint(aB[mi * 576 + 288 + kf]);
                a[mi][2] = __float_as_uint(aB[mi * 576 + kf + 4]);
                a[mi][3] = __float_as_uint(aB[mi * 576 + 288 + kf + 4]);
            }
            uint32_t b[4][2];
#pragma unroll
            for (int ni = 0; ni < 4; ni++) {
                b[ni][0] = __float_as_uint(bB[ni * 288 + kf]);
                b[ni][1] = __float_as_uint(bB[ni * 288 + kf + 4]);
            }
#pragma unroll
            for (int mi = 0; mi < 4; mi++)
#pragma unroll
                for (int ni = 0; ni < 4; ni++)
                    mma_tf32(acc[mi][ni], a[mi][0], a[mi][1], a[mi][2], a[mi][3],
                             b[ni][0], b[ni][1]);
        }
    };

    const int NKT = Hn / 32;   // 24
    load_stage(0, 0); CP_COMMIT();
    load_stage(1, 1); CP_COMMIT();

    for (int kt = 0; kt < NKT; kt++) {
        if (kt < NKT - 2) { CP_WAIT(1); } else { CP_WAIT(0); }
        __syncthreads();
        if (kt + 2 < NKT) {
            load_stage((kt + 2) % GSTAGES, kt + 2);
            CP_COMMIT();
        }
        compute(kt % GSTAGES);
    }

    // epilogue: add bias, round to tf32, store; V tiles also column-sum
    const bool do_vsum = (z == 2) && ((blockIdx.y % 6) < 5);
    float s0[4] = {0.f, 0.f, 0.f, 0.f};
    float s1[4] = {0.f, 0.f, 0.f, 0.f};

#pragma unroll
    for (int mi = 0; mi < 4; mi++) {
#pragma unroll
        for (int ni = 0; ni < 4; ni++) {
            int row0 = rowBase + mrow + mi * 16 + g;
            int col0 = colBase + nrow + ni * 8 + 2 * t;
            float b0 = bias[col0], b1 = bias[col0 + 1];
            float2 v0 = make_float2(tf32r(acc[mi][ni][0] + b0), tf32r(acc[mi][ni][1] + b1));
            float2 v1 = make_float2(tf32r(acc[mi][ni][2] + b0), tf32r(acc[mi][ni][3] + b1));
            *(float2*)(C + (size_t)row0 * Hn + col0) = v0;
            *(float2*)(C + (size_t)(row0 + 8) * Hn + col0) = v1;
            s0[ni] += v0.x + v1.x;
            s1[ni] += v0.y + v1.y;
        }
    }

    if (do_vsum) {
        const int bb = rowBase / Sn;
#pragma unroll
        for (int ni = 0; ni < 4; ni++) {
            float a0 = s0[ni], a1 = s1[ni];
            a0 += __shfl_xor_sync(0xFFFFFFFFu, a0, 4);
            a0 += __shfl_xor_sync(0xFFFFFFFFu, a0, 8);
            a0 += __shfl_xor_sync(0xFFFFFFFFu, a0, 16);
            a1 += __shfl_xor_sync(0xFFFFFFFFu, a1, 4);
            a1 += __shfl_xor_sync(0xFFFFFFFFu, a1, 8);
            a1 += __shfl_xor_sync(0xFFFFFFFFu, a1, 16);
            if (g == 0) {
                int col = colBase + nrow + ni * 8 + 2 * t;
                atomicAdd(&g_Vsum[bb * Hn + col], a0);
                atomicAdd(&g_Vsum[bb * Hn + col + 1], a1);
            }
        }
    }
}

// ---------------------------------------------------------------------------
// Fused attention (512 threads, 2 CTAs/SM): one CTA per (chunk, head, batch).
// chunk==10 CTAs copy the V tail rows to the output (fused tail_copy).
// Scores: tf32 mma. PV: tf32 mma with V B-fragments from global.
// ---------------------------------------------------------------------------
#define SQS 68
#define SPS 196
#define SMALL_OFF (64 * SQS + 192 * SQS)   // 17408 floats

__global__ __launch_bounds__(512, 2) void attn_kernel(float* __restrict__ out)
{
    const int tid = threadIdx.x;
    const int chunk = blockIdx.x;
    const int h = blockIdx.y;
    const int b = blockIdx.z;

    if (chunk == CHn) {
        // tail copy: out rows 640..767, cols h*64..h*64+63  <- g_V
        const size_t base = ((size_t)b * Sn + NQn) * Hn + h * DHn;
#pragma unroll
        for (int r = 0; r < 4; r++) {
            int idx = r * 512 + tid;            // 0..2047 -> 128 rows x 16 float4
            int row = idx >> 4, c4 = idx & 15;
            *(float4*)(out + base + (size_t)row * Hn + c4 * 4) =
                *(const float4*)(g_V + base + (size_t)row * Hn + c4 * 4);
        }
        return;
    }

    extern __shared__ float sm[];
    float* sq  = sm;                    // 64 * 68
    float* sk  = sm + 64 * SQS;         // 192 * 68
    float* sp  = sm;                    // overlay
    float* sem = sm + SMALL_OFF;        // 64
    float* sz  = sem + 64;              // 64
    float* sms = sz + 64;               // 64

    const size_t rowC = (size_t)b * Sn + chunk * 64;
    const size_t baseC = rowC * Hn + h * DHn;
    const size_t baseT = ((size_t)b * Sn + 576) * Hn + h * DHn;   // rows 576+j, j>=64
    const float* vc = g_V + baseC;
    const float* vt = g_V + ((size_t)b * Sn + NQn) * Hn + h * DHn;

    for (int idx = tid; idx < 64 * 64; idx += 512) {
        int i = idx >> 6, d = idx & 63;
        sq[i * SQS + d] = g_Q[baseC + (size_t)i * Hn + d];
    }
    for (int idx = tid; idx < 192 * 64; idx += 512) {
        int j = idx >> 6, d = idx & 63;
        size_t off = (j < 64) ? (baseC + (size_t)j * Hn + d)
                              : (baseT + (size_t)j * Hn + d);
        sk[j * SQS + d] = g_K[off];
    }
    __syncthreads();

    const int lane = tid & 31;
    const int wid = tid >> 5;
    const int g = lane >> 2;
    const int t = lane & 3;
    const int mbase = (wid & 3) * 16;    // 4 row-groups of 16
    const int nbase = (wid >> 2) * 48;   // 4 col-groups of 48 (scores)

    // ---- scores: tf32 mma, each warp 16 rows x 48 cols over k=64 ----
    float acc[6][4];
#pragma unroll
    for (int nt = 0; nt < 6; nt++)
#pragma unroll
        for (int r = 0; r < 4; r++) acc[nt][r] = 0.f;

#pragma unroll
    for (int ks = 0; ks < 8; ks++) {
        const int k0 = ks * 8;
        uint32_t a0 = __float_as_uint(sq[(mbase + g) * SQS + k0 + t]);
        uint32_t a1 = __float_as_uint(sq[(mbase + g + 8) * SQS + k0 + t]);
        uint32_t a2 = __float_as_uint(sq[(mbase + g) * SQS + k0 + t + 4]);
        uint32_t a3 = __float_as_uint(sq[(mbase + g + 8) * SQS + k0 + t + 4]);
#pragma unroll
        for (int nt = 0; nt < 6; nt++) {
            const int n = nbase + nt * 8 + g;
            uint32_t b0 = __float_as_uint(sk[n * SQS + k0 + t]);
            uint32_t b1 = __float_as_uint(sk[n * SQS + k0 + t + 4]);
            mma_tf32(acc[nt], a0, a1, a2, a3, b0, b1);
        }
    }
    __syncthreads();   // all sq/sk reads done -> safe to overlay sp

#pragma unroll
    for (int nt = 0; nt < 6; nt++) {
        const int c0 = nbase + nt * 8 + 2 * t;
        *(float2*)&sp[(mbase + g) * SPS + c0] =
            make_float2(acc[nt][0] * 0.125f, acc[nt][1] * 0.125f);
        *(float2*)&sp[(mbase + g + 8) * SPS + c0] =
            make_float2(acc[nt][2] * 0.125f, acc[nt][3] * 0.125f);
    }

    // masked-v sum: d = tid/8, 8 threads sum 8 chunk-rows each (global reads)
    {
        const int d = tid >> 3, part = tid & 7;
        float s = 0.f;
#pragma unroll
        for (int j = part * 8; j < part * 8 + 8; j++)
            s += __ldg(vc + (size_t)j * Hn + d);
        s += __shfl_xor_sync(0xFFFFFFFFu, s, 1);
        s += __shfl_xor_sync(0xFFFFFFFFu, s, 2);
        s += __shfl_xor_sync(0xFFFFFFFFu, s, 4);
        if (part == 0) sms[d] = __ldg(&g_Vsum[b * Hn + h * DHn + d]) - s;
    }
    __syncthreads();

    // softmax: row = tid/8, 8 threads x 24 cols; probs stored tf32-rounded
    {
        const int i = tid >> 3, part = tid & 7;
        const int j0 = part * 24;
        float m = 0.f;   // masked scores are exactly 0
#pragma unroll
        for (int j = j0; j < j0 + 24; j++) m = fmaxf(m, sp[i * SPS + j]);
        m = fmaxf(m, __shfl_xor_sync(0xFFFFFFFFu, m, 1));
        m = fmaxf(m, __shfl_xor_sync(0xFFFFFFFFu, m, 2));
        m = fmaxf(m, __shfl_xor_sync(0xFFFFFFFFu, m, 4));
        float Z = 0.f;
#pragma unroll
        for (int j = j0; j < j0 + 24; j++) {
            float e = tf32r(__expf(sp[i * SPS + j] - m));
            sp[i * SPS + j] = e;
            Z += e;
        }
        Z += __shfl_xor_sync(0xFFFFFFFFu, Z, 1);
        Z += __shfl_xor_sync(0xFFFFFFFFu, Z, 2);
        Z += __shfl_xor_sync(0xFFFFFFFFu, Z, 4);
        if (part == 0) {
            float em = __expf(-m);
            sem[i] = em;
            sz[i] = 1.f / (Z + 576.f * em);
        }
    }
    __syncthreads();

    // ---- PV: tf32 mma; warp = 16 q-rows x 16 d-cols; V frags from global ----
    {
        const int dbase = (wid >> 2) * 16;
        float c0[4] = {0.f, 0.f, 0.f, 0.f};
        float c1[4] = {0.f, 0.f, 0.f, 0.f};

#pragma unroll
        for (int ks = 0; ks < 24; ks++) {
            const int k0 = ks * 8;
            const float* vb = (ks < 8) ? (vc + (size_t)(k0 + t) * Hn)
                                       : (vt + (size_t)(k0 - 64 + t) * Hn);
            const float* vb2 = vb + 4 * Hn;
            uint32_t a0 = __float_as_uint(sp[(mbase + g) * SPS + k0 + t]);
            uint32_t a1 = __float_as_uint(sp[(mbase + g + 8) * SPS + k0 + t]);
            uint32_t a2 = __float_as_uint(sp[(mbase + g) * SPS + k0 + t + 4]);
            uint32_t a3 = __float_as_uint(sp[(mbase + g + 8) * SPS + k0 + t + 4]);
            uint32_t b00 = __float_as_uint(__ldg(vb  + dbase + g));
            uint32_t b01 = __float_as_uint(__ldg(vb2 + dbase + g));
            uint32_t b10 = __float_as_uint(__ldg(vb  + dbase + 8 + g));
            uint32_t b11 = __float_as_uint(__ldg(vb2 + dbase + 8 + g));
            mma_tf32(c0, a0, a1, a2, a3, b00, b01);
            mma_tf32(c1, a0, a1, a2, a3, b10, b11);
        }

        const int r0 = mbase + g, r1 = r0 + 8;
        const float inv0 = sz[r0], em0 = sem[r0];
        const float inv1 = sz[r1], em1 = sem[r1];
#pragma unroll
        for (int nt = 0; nt < 2; nt++) {
            const float* cc = nt ? c1 : c0;
            const int col = dbase + nt * 8 + 2 * t;
            const float s0 = sms[col], s1 = sms[col + 1];
            float2 o0 = make_float2((cc[0] + em0 * s0) * inv0,
                                    (cc[1] + em0 * s1) * inv0);
            float2 o1 = make_float2((cc[2] + em1 * s0) * inv1,
                                    (cc[3] + em1 * s1) * inv1);
            *(float2*)(out + (rowC + r0) * Hn + h * DHn + col) = o0;
            *(float2*)(out + (rowC + r1) * Hn + h * DHn + col) = o1;
        }
    }
}

// ---------------------------------------------------------------------------
extern "C" void kernel_launch(void* const* d_in, const int* in_sizes, int n_in,
                              void* d_out, int out_size)
{
    const float* hs = (const float*)d_in[0];
    const float* Wq = (const float*)d_in[1];
    const float* bq = (const float*)d_in[2];
    const float* Wk = (const float*)d_in[3];
    const float* bk = (const float*)d_in[4];
    const float* Wv = (const float*)d_in[5];
    const float* bv = (const float*)d_in[6];
    float* out = (float*)d_out;

    prep<<<2048, 256>>>(hs, Wq, Wk, Wv);     // idx 0

    cudaFuncSetAttribute(gemm_qkv, cudaFuncAttributeMaxDynamicSharedMemorySize,
                         GEMM_SMEM);
    gemm_qkv<<<dim3(Hn / 128, Mn / 128, 3), 256, GEMM_SMEM>>>(bq, bk, bv); // idx 1

    const size_t attn_smem = (size_t)(SMALL_OFF + 3 * 64) * sizeof(float);  // 70400 B
    cudaFuncSetAttribute(attn_kernel, cudaFuncAttributeMaxDynamicSharedMemorySize,
                         (int)attn_smem);
    attn_kernel<<<dim3(CHn + 1, NHn, Bn), 512, attn_smem>>>(out);          // idx 2 (ncu)
}

// round 14
// speedup vs baseline: 1.9893x; 1.0432x over previous
#include <cuda_runtime.h>
#include <cuda_bf16.h>
#include <cstdint>
#include <math.h>

#define Bn 16
#define Sn 768
#define Hn 768
#define Tn 128
#define NQn 640
#define DHn 64
#define NHn 12
#define CHn 10
#define Mn (Bn * Sn)   // 12288

// ---------------- device scratch (no cudaMalloc allowed) -------------------
__device__ float g_Q[(size_t)Mn * Hn];
__device__ float g_K[(size_t)Mn * Hn];
__device__ float g_V[(size_t)Mn * Hn];
__device__ float g_Vsum[Bn * Hn];
__device__ float g_Wt[3 * Hn * Hn];     // tf32-rounded Wq|Wk|Wv
__device__ float g_At[(size_t)Mn * Hn]; // tf32-rounded hs

// ---------------------------------------------------------------------------
__device__ __forceinline__ float tf32r(float x)
{
    float r;
    asm("cvt.rna.tf32.f32 %0, %1;" : "=f"(r) : "f"(x));
    return r;
}

__device__ __forceinline__ void mma_tf32(float c[4], uint32_t a0, uint32_t a1,
                                         uint32_t a2, uint32_t a3,
                                         uint32_t b0, uint32_t b1)
{
    asm volatile(
        "mma.sync.aligned.m16n8k8.row.col.f32.tf32.tf32.f32 "
        "{%0,%1,%2,%3}, {%4,%5,%6,%7}, {%8,%9}, {%0,%1,%2,%3};\n"
        : "+f"(c[0]), "+f"(c[1]), "+f"(c[2]), "+f"(c[3])
        : "r"(a0), "r"(a1), "r"(a2), "r"(a3), "r"(b0), "r"(b1));
}

#define CPASYNC16(saddr, gptr) \
    asm volatile("cp.async.cg.shared.global [%0], [%1], 16;\n" :: "r"(saddr), "l"(gptr))
#define CP_COMMIT() asm volatile("cp.async.commit_group;\n")
#define CP_WAIT(N)  asm volatile("cp.async.wait_group %0;\n" :: "n"(N))

// ---------------------------------------------------------------------------
// prep: fused W-round + A-round + Vsum zero
// ---------------------------------------------------------------------------
__global__ void prep(const float* __restrict__ hs,
                     const float* __restrict__ Wq, const float* __restrict__ Wk,
                     const float* __restrict__ Wv)
{
    const int gs = gridDim.x * blockDim.x;
    const int t0 = blockIdx.x * blockDim.x + threadIdx.x;

    const int n4 = (Mn * Hn) / 4;
    float4* dst = (float4*)g_At;
    for (int i = t0; i < n4; i += gs) {
        float4 x = ((const float4*)hs)[i];
        x.x = tf32r(x.x); x.y = tf32r(x.y);
        x.z = tf32r(x.z); x.w = tf32r(x.w);
        dst[i] = x;
    }
    const int n = Hn * Hn;
    for (int i = t0; i < 3 * n; i += gs) {
        int z = i / n, j = i - z * n;
        const float* W = (z == 0) ? Wq : (z == 1) ? Wk : Wv;
        g_Wt[i] = tf32r(W[j]);
    }
    for (int i = t0; i < Bn * Hn; i += gs) g_Vsum[i] = 0.f;
}

// ---------------------------------------------------------------------------
// tf32 tensor-core GEMM. Outputs tf32-rounded. Skips unused Q tiles.
// V tiles (z==2, rows<640) also accumulate per-column sums into g_Vsum.
// ---------------------------------------------------------------------------
#define TILE_F 4608                  // 128 rows * 36 floats
#define TILE_BYTES (TILE_F * 4)      // 18432
#define STAGE_F (2 * TILE_F)
#define STAGE_BYTES (2 * TILE_BYTES) // 36864
#define GSTAGES 3
#define GEMM_SMEM (GSTAGES * STAGE_BYTES)  // 110592

__global__ __launch_bounds__(256, 2) void gemm_qkv(
    const float* __restrict__ bq, const float* __restrict__ bk,
    const float* __restrict__ bv)
{
    extern __shared__ float smem[];
    const uint32_t sbase = (uint32_t)__cvta_generic_to_shared(smem);

    const int tid = threadIdx.x;
    const int rowBase = blockIdx.y * 128;
    const int colBase = blockIdx.x * 128;
    const int z = blockIdx.z;

    if (z == 0 && (blockIdx.y % 6) == 5) return;   // Q tail rows never read

    const float* Ag = g_At + (size_t)rowBase * Hn;
    const float* Wt = g_Wt + (size_t)z * Hn * Hn + (size_t)colBase * Hn;
    float* C = (z == 0) ? g_Q : (z == 1) ? g_K : g_V;
    const float* bias = (z == 0) ? bq : (z == 1) ? bk : bv;

    const int warp  = tid >> 5;
    const int lane  = tid & 31;
    const int warpM = warp >> 2;
    const int warpN = warp & 3;
    const int g  = lane >> 2;
    const int t  = lane & 3;
    const int mrow = warpM * 64;
    const int nrow = warpN * 32;

    float acc[4][4][4];
#pragma unroll
    for (int mi = 0; mi < 4; mi++)
#pragma unroll
        for (int ni = 0; ni < 4; ni++)
#pragma unroll
            for (int r = 0; r < 4; r++) acc[mi][ni][r] = 0.f;

    auto load_stage = [&](int stage, int ktile) {
        uint32_t s0 = sbase + stage * STAGE_BYTES;
        int kb = ktile * 32;
#pragma unroll
        for (int i = 0; i < 8; i++) {
            int idx = i * 256 + tid;
            int arr = idx >> 10;
            int r = (idx >> 3) & 127;
            int c = idx & 7;
            const float* src = arr ? (Wt + (size_t)r * Hn + kb + c * 4)
                                   : (Ag + (size_t)r * Hn + kb + c * 4);
            CPASYNC16(s0 + arr * TILE_BYTES + (uint32_t)(r * 144 + c * 16), src);
        }
    };

    auto compute = [&](int stage) {
        const float* sA = smem + stage * STAGE_F;
        const float* sW = sA + TILE_F;
        const float* aB = sA + (mrow + g) * 36 + t;
        const float* bB = sW + (nrow + g) * 36 + t;
#pragma unroll
        for (int ks = 0; ks < 4; ks++) {
            const int kf = ks * 8;
            uint32_t a[4][4];
#pragma unroll
            for (int mi = 0; mi < 4; mi++) {
                a[mi][0] = __float_as_uint(aB[mi * 576 + kf]);
                a[mi][1] = __float_as_uint(aB[mi * 576 + 288 + kf]);
                a[mi][2] = __float_as_uint(aB[mi * 576 + kf + 4]);
                a[mi][3] = __float_as_uint(aB[mi * 576 + 288 + kf + 4]);
            }
            uint32_t b[4][2];
#pragma unroll
            for (int ni = 0; ni < 4; ni++) {
                b[ni][0] = __float_as_uint(bB[ni * 288 + kf]);
                b[ni][1] = __float_as_uint(bB[ni * 288 + kf + 4]);
            }
#pragma unroll
            for (int mi = 0; mi < 4; mi++)
#pragma unroll
                for (int ni = 0; ni < 4; ni++)
                    mma_tf32(acc[mi][ni], a[mi][0], a[mi][1], a[mi][2], a[mi][3],
                             b[ni][0], b[ni][1]);
        }
    };

    const int NKT = Hn / 32;   // 24
    load_stage(0, 0); CP_COMMIT();
    load_stage(1, 1); CP_COMMIT();

    for (int kt = 0; kt < NKT; kt++) {
        if (kt < NKT - 2) { CP_WAIT(1); } else { CP_WAIT(0); }
        __syncthreads();
        if (kt + 2 < NKT) {
            load_stage((kt + 2) % GSTAGES, kt + 2);
            CP_COMMIT();
        }
        compute(kt % GSTAGES);
    }

    // epilogue: add bias, round to tf32, store; V tiles also column-sum
    const bool do_vsum = (z == 2) && ((blockIdx.y % 6) < 5);
    float s0[4] = {0.f, 0.f, 0.f, 0.f};
    float s1[4] = {0.f, 0.f, 0.f, 0.f};

#pragma unroll
    for (int mi = 0; mi < 4; mi++) {
#pragma unroll
        for (int ni = 0; ni < 4; ni++) {
            int row0 = rowBase + mrow + mi * 16 + g;
            int col0 = colBase + nrow + ni * 8 + 2 * t;
            float b0 = bias[col0], b1 = bias[col0 + 1];
            float2 v0 = make_float2(tf32r(acc[mi][ni][0] + b0), tf32r(acc[mi][ni][1] + b1));
            float2 v1 = make_float2(tf32r(acc[mi][ni][2] + b0), tf32r(acc[mi][ni][3] + b1));
            *(float2*)(C + (size_t)row0 * Hn + col0) = v0;
            *(float2*)(C + (size_t)(row0 + 8) * Hn + col0) = v1;
            s0[ni] += v0.x + v1.x;
            s1[ni] += v0.y + v1.y;
        }
    }

    if (do_vsum) {
        const int bb = rowBase / Sn;
#pragma unroll
        for (int ni = 0; ni < 4; ni++) {
            float a0 = s0[ni], a1 = s1[ni];
            a0 += __shfl_xor_sync(0xFFFFFFFFu, a0, 4);
            a0 += __shfl_xor_sync(0xFFFFFFFFu, a0, 8);
            a0 += __shfl_xor_sync(0xFFFFFFFFu, a0, 16);
            a1 += __shfl_xor_sync(0xFFFFFFFFu, a1, 4);
            a1 += __shfl_xor_sync(0xFFFFFFFFu, a1, 8);
            a1 += __shfl_xor_sync(0xFFFFFFFFu, a1, 16);
            if (g == 0) {
                int col = colBase + nrow + ni * 8 + 2 * t;
                atomicAdd(&g_Vsum[bb * Hn + col], a0);
                atomicAdd(&g_Vsum[bb * Hn + col + 1], a1);
            }
        }
    }
}

// ---------------------------------------------------------------------------
// Fused attention (512 threads, 2 CTAs/SM): one CTA per (chunk, head, batch).
// chunk==10 CTAs copy the V tail rows to the output (fused tail_copy).
// Scores: tf32 mma (Q A-frags from global, K from smem).
// PV: tf32 mma (P in smem with chunk-fold e-em, V staged in smem stride 72).
// Mask correction: out = PV' + em*Vsum (fold), no masked-v-sum phase.
// ---------------------------------------------------------------------------
#define SVS 72                            // V stride: 72 % 32 == 8 -> PV LDS conflict-free
#define SKS 68
#define SPS 196
#define OFF_K (192 * SVS)                 // 13824
#define OFF_SMALL (OFF_K + 192 * SKS)     // 26880
#define ATTN_F (OFF_SMALL + 128)          // 27008 floats = 108032 B

__global__ __launch_bounds__(512, 2) void attn_kernel(float* __restrict__ out)
{
    const int tid = threadIdx.x;
    const int chunk = blockIdx.x;
    const int h = blockIdx.y;
    const int b = blockIdx.z;

    if (chunk == CHn) {
        const size_t base = ((size_t)b * Sn + NQn) * Hn + h * DHn;
#pragma unroll
        for (int r = 0; r < 4; r++) {
            int idx = r * 512 + tid;
            int row = idx >> 4, c4 = idx & 15;
            *(float4*)(out + base + (size_t)row * Hn + c4 * 4) =
                *(const float4*)(g_V + base + (size_t)row * Hn + c4 * 4);
        }
        return;
    }

    extern __shared__ float sm[];
    float* sV  = sm;                    // 192 * 72 (persists)
    float* sk  = sm + OFF_K;            // 192 * 68 (scores only)
    float* sp  = sm + OFF_K;            // overlay after scores (64*196 <= 13056)
    float* sem = sm + OFF_SMALL;        // 64
    float* sz  = sem + 64;              // 64

    const size_t rowC = (size_t)b * Sn + chunk * 64;
    const size_t baseC = rowC * Hn + h * DHn;
    const size_t baseT = ((size_t)b * Sn + 576) * Hn + h * DHn;   // rows 576+j, j>=64
    const float* qp = g_Q + baseC;
    const float* vc = g_V + baseC;
    const float* vt = g_V + ((size_t)b * Sn + NQn) * Hn + h * DHn;

    // stage V (float4) and K (float4)
    for (int idx = tid; idx < 192 * 16; idx += 512) {
        int j = idx >> 4, c4 = idx & 15;
        const float* src = (j < 64) ? (vc + (size_t)j * Hn + c4 * 4)
                                    : (vt + (size_t)(j - 64) * Hn + c4 * 4);
        *(float4*)&sV[j * SVS + c4 * 4] = *(const float4*)src;
    }
    for (int idx = tid; idx < 192 * 16; idx += 512) {
        int j = idx >> 4, c4 = idx & 15;
        size_t off = (j < 64) ? (baseC + (size_t)j * Hn + c4 * 4)
                              : (baseT + (size_t)j * Hn + c4 * 4);
        *(float4*)&sk[j * SKS + c4 * 4] = *(const float4*)(g_K + off);
    }
    __syncthreads();

    const int lane = tid & 31;
    const int wid = tid >> 5;
    const int g = lane >> 2;
    const int t = lane & 3;
    const int mbase = (wid & 3) * 16;    // 4 row-groups of 16
    const int nbase = (wid >> 2) * 48;   // 4 col-groups of 48 (scores)

    // ---- scores: tf32 mma; Q A-frags straight from global (L1-hot) ----
    float acc[6][4];
#pragma unroll
    for (int nt = 0; nt < 6; nt++)
#pragma unroll
        for (int r = 0; r < 4; r++) acc[nt][r] = 0.f;

    const float* qr0 = qp + (size_t)(mbase + g) * Hn + t;
    const float* qr1 = qr0 + 8 * Hn;
#pragma unroll
    for (int ks = 0; ks < 8; ks++) {
        const int k0 = ks * 8;
        uint32_t a0 = __float_as_uint(__ldg(qr0 + k0));
        uint32_t a1 = __float_as_uint(__ldg(qr1 + k0));
        uint32_t a2 = __float_as_uint(__ldg(qr0 + k0 + 4));
        uint32_t a3 = __float_as_uint(__ldg(qr1 + k0 + 4));
#pragma unroll
        for (int nt = 0; nt < 6; nt++) {
            const int n = nbase + nt * 8 + g;
            uint32_t b0 = __float_as_uint(sk[n * SKS + k0 + t]);
            uint32_t b1 = __float_as_uint(sk[n * SKS + k0 + t + 4]);
            mma_tf32(acc[nt], a0, a1, a2, a3, b0, b1);
        }
    }
    __syncthreads();   // all sk reads done -> safe to overlay sp

#pragma unroll
    for (int nt = 0; nt < 6; nt++) {
        const int c0 = nbase + nt * 8 + 2 * t;
        *(float2*)&sp[(mbase + g) * SPS + c0] =
            make_float2(acc[nt][0] * 0.125f, acc[nt][1] * 0.125f);
        *(float2*)&sp[(mbase + g + 8) * SPS + c0] =
            make_float2(acc[nt][2] * 0.125f, acc[nt][3] * 0.125f);
    }
    __syncthreads();

    // softmax: row = tid/8, 8 threads x 24 cols; chunk cols store e-em (fold)
    {
        const int i = tid >> 3, part = tid & 7;
        const int j0 = part * 24;
        float m = 0.f;   // masked scores are exactly 0
#pragma unroll
        for (int j = j0; j < j0 + 24; j++) m = fmaxf(m, sp[i * SPS + j]);
        m = fmaxf(m, __shfl_xor_sync(0xFFFFFFFFu, m, 1));
        m = fmaxf(m, __shfl_xor_sync(0xFFFFFFFFu, m, 2));
        m = fmaxf(m, __shfl_xor_sync(0xFFFFFFFFu, m, 4));
        const float em = __expf(-m);
        float Z = 0.f;
#pragma unroll
        for (int j = j0; j < j0 + 24; j++) {
            float e = __expf(sp[i * SPS + j] - m);
            Z += e;
            sp[i * SPS + j] = tf32r((j < 64) ? (e - em) : e);
        }
        Z += __shfl_xor_sync(0xFFFFFFFFu, Z, 1);
        Z += __shfl_xor_sync(0xFFFFFFFFu, Z, 2);
        Z += __shfl_xor_sync(0xFFFFFFFFu, Z, 4);
        if (part == 0) {
            sem[i] = em;
            sz[i] = 1.f / (Z + 576.f * em);
        }
    }
    __syncthreads();

    // ---- PV: tf32 mma; warp = 16 q-rows x 16 d-cols; V frags from smem ----
    {
        const int dbase = (wid >> 2) * 16;
        float c0[4] = {0.f, 0.f, 0.f, 0.f};
        float c1[4] = {0.f, 0.f, 0.f, 0.f};

#pragma unroll
        for (int ks = 0; ks < 24; ks++) {
            const int k0 = ks * 8;
            uint32_t a0 = __float_as_uint(sp[(mbase + g) * SPS + k0 + t]);
            uint32_t a1 = __float_as_uint(sp[(mbase + g + 8) * SPS + k0 + t]);
            uint32_t a2 = __float_as_uint(sp[(mbase + g) * SPS + k0 + t + 4]);
            uint32_t a3 = __float_as_uint(sp[(mbase + g + 8) * SPS + k0 + t + 4]);
            uint32_t b00 = __float_as_uint(sV[(k0 + t) * SVS + dbase + g]);
            uint32_t b01 = __float_as_uint(sV[(k0 + t + 4) * SVS + dbase + g]);
            uint32_t b10 = __float_as_uint(sV[(k0 + t) * SVS + dbase + 8 + g]);
            uint32_t b11 = __float_as_uint(sV[(k0 + t + 4) * SVS + dbase + 8 + g]);
            mma_tf32(c0, a0, a1, a2, a3, b00, b01);
            mma_tf32(c1, a0, a1, a2, a3, b10, b11);
        }

        const int r0 = mbase + g, r1 = r0 + 8;
        const float inv0 = sz[r0], em0 = sem[r0];
        const float inv1 = sz[r1], em1 = sem[r1];
        const float* vsum = g_Vsum + b * Hn + h * DHn;
#pragma unroll
        for (int nt = 0; nt < 2; nt++) {
            const float* cc = nt ? c1 : c0;
            const int col = dbase + nt * 8 + 2 * t;
            const float s0 = __ldg(vsum + col), s1 = __ldg(vsum + col + 1);
            float2 o0 = make_float2((cc[0] + em0 * s0) * inv0,
                                    (cc[1] + em0 * s1) * inv0);
            float2 o1 = make_float2((cc[2] + em1 * s0) * inv1,
                                    (cc[3] + em1 * s1) * inv1);
            *(float2*)(out + (rowC + r0) * Hn + h * DHn + col) = o0;
            *(float2*)(out + (rowC + r1) * Hn + h * DHn + col) = o1;
        }
    }
}

// ---------------------------------------------------------------------------
extern "C" void kernel_launch(void* const* d_in, const int* in_sizes, int n_in,
                              void* d_out, int out_size)
{
    const float* hs = (const float*)d_in[0];
    const float* Wq = (const float*)d_in[1];
    const float* bq = (const float*)d_in[2];
    const float* Wk = (const float*)d_in[3];
    const float* bk = (const float*)d_in[4];
    const float* Wv = (const float*)d_in[5];
    const float* bv = (const float*)d_in[6];
    float* out = (float*)d_out;

    prep<<<2048, 256>>>(hs, Wq, Wk, Wv);     // idx 0

    cudaFuncSetAttribute(gemm_qkv, cudaFuncAttributeMaxDynamicSharedMemorySize,
                         GEMM_SMEM);
    gemm_qkv<<<dim3(Hn / 128, Mn / 128, 3), 256, GEMM_SMEM>>>(bq, bk, bv); // idx 1

    const int attn_smem = ATTN_F * 4;   // 108032 B
    cudaFuncSetAttribute(attn_kernel, cudaFuncAttributeMaxDynamicSharedMemorySize,
                         attn_smem);
    attn_kernel<<<dim3(CHn + 1, NHn, Bn), 512, attn_smem>>>(out);          // idx 2
}

// round 15
// speedup vs baseline: 2.8331x; 1.4242x over previous
#include <cuda_runtime.h>
#include <cuda_fp16.h>
#include <cstdint>
#include <math.h>

#define Bn 16
#define Sn 768
#define Hn 768
#define Tn 128
#define NQn 640
#define DHn 64
#define NHn 12
#define CHn 10
#define Mn (Bn * Sn)   // 12288

// ---------------- device scratch (no cudaMalloc allowed) -------------------
__device__ float g_Q[(size_t)Mn * Hn];
__device__ float g_K[(size_t)Mn * Hn];
__device__ float g_V[(size_t)Mn * Hn];
__device__ float g_Vsum[Bn * Hn];
__device__ __half g_Ah[(size_t)Mn * Hn];   // fp16 hs
__device__ __half g_Wh[3 * Hn * Hn];       // fp16 Wq|Wk|Wv

// ---------------------------------------------------------------------------
__device__ __forceinline__ float tf32r(float x)
{
    float r;
    asm("cvt.rna.tf32.f32 %0, %1;" : "=f"(r) : "f"(x));
    return r;
}

__device__ __forceinline__ void mma_tf32(float c[4], uint32_t a0, uint32_t a1,
                                         uint32_t a2, uint32_t a3,
                                         uint32_t b0, uint32_t b1)
{
    asm volatile(
        "mma.sync.aligned.m16n8k8.row.col.f32.tf32.tf32.f32 "
        "{%0,%1,%2,%3}, {%4,%5,%6,%7}, {%8,%9}, {%0,%1,%2,%3};\n"
        : "+f"(c[0]), "+f"(c[1]), "+f"(c[2]), "+f"(c[3])
        : "r"(a0), "r"(a1), "r"(a2), "r"(a3), "r"(b0), "r"(b1));
}

__device__ __forceinline__ void mma_f16(float c[4], uint32_t a0, uint32_t a1,
                                        uint32_t a2, uint32_t a3,
                                        uint32_t b0, uint32_t b1)
{
    asm volatile(
        "mma.sync.aligned.m16n8k16.row.col.f32.f16.f16.f32 "
        "{%0,%1,%2,%3}, {%4,%5,%6,%7}, {%8,%9}, {%0,%1,%2,%3};\n"
        : "+f"(c[0]), "+f"(c[1]), "+f"(c[2]), "+f"(c[3])
        : "r"(a0), "r"(a1), "r"(a2), "r"(a3), "r"(b0), "r"(b1));
}

#define CPASYNC16(saddr, gptr) \
    asm volatile("cp.async.cg.shared.global [%0], [%1], 16;\n" :: "r"(saddr), "l"(gptr))
#define CP_COMMIT() asm volatile("cp.async.commit_group;\n")
#define CP_WAIT(N)  asm volatile("cp.async.wait_group %0;\n" :: "n"(N))

// ---------------------------------------------------------------------------
// prep: fp16-convert hs and W, zero Vsum
// ---------------------------------------------------------------------------
__global__ void prep(const float* __restrict__ hs,
                     const float* __restrict__ Wq, const float* __restrict__ Wk,
                     const float* __restrict__ Wv)
{
    const int gs = gridDim.x * blockDim.x;
    const int t0 = blockIdx.x * blockDim.x + threadIdx.x;

    const int n4 = (Mn * Hn) / 4;
    __half2* dst = (__half2*)g_Ah;
    for (int i = t0; i < n4; i += gs) {
        float4 x = ((const float4*)hs)[i];
        dst[2 * i + 0] = __floats2half2_rn(x.x, x.y);
        dst[2 * i + 1] = __floats2half2_rn(x.z, x.w);
    }
    const int n = Hn * Hn;
    for (int i = t0; i < 3 * n; i += gs) {
        int z = i / n, j = i - z * n;
        const float* W = (z == 0) ? Wq : (z == 1) ? Wk : Wv;
        g_Wh[i] = __float2half_rn(W[j]);
    }
    for (int i = t0; i < Bn * Hn; i += gs) g_Vsum[i] = 0.f;
}

// ---------------------------------------------------------------------------
// fp16 tensor-core GEMM (m16n8k16, fp32 accum). Outputs tf32-rounded fp32.
// 128x128 tile, BK=64, 256 threads (8 warps 2x4), 3-stage cp.async, 2 CTAs/SM.
// smem rows: 72 halves (144 B) -> 36-word rows, conflict-free scalar LDS.
// V tiles (z==2, rows<640) also accumulate per-column sums into g_Vsum.
// ---------------------------------------------------------------------------
#define TILE_BYTES (128 * 144)         // 18432 B per operand tile
#define STAGE_BYTES (2 * TILE_BYTES)   // 36864
#define GSTAGES 3
#define GEMM_SMEM (GSTAGES * STAGE_BYTES)  // 110592

__global__ __launch_bounds__(256, 2) void gemm_qkv(
    const float* __restrict__ bq, const float* __restrict__ bk,
    const float* __restrict__ bv)
{
    extern __shared__ char smem[];
    const uint32_t sbase = (uint32_t)__cvta_generic_to_shared(smem);

    const int tid = threadIdx.x;
    const int rowBase = blockIdx.y * 128;
    const int colBase = blockIdx.x * 128;
    const int z = blockIdx.z;

    if (z == 0 && (blockIdx.y % 6) == 5) return;   // Q tail rows never read

    const __half* Ag = g_Ah + (size_t)rowBase * Hn;
    const __half* Wt = g_Wh + (size_t)z * Hn * Hn + (size_t)colBase * Hn;
    float* C = (z == 0) ? g_Q : (z == 1) ? g_K : g_V;
    const float* bias = (z == 0) ? bq : (z == 1) ? bk : bv;

    const int warp  = tid >> 5;
    const int lane  = tid & 31;
    const int warpM = warp >> 2;
    const int warpN = warp & 3;
    const int g  = lane >> 2;
    const int t  = lane & 3;
    const int mrow = warpM * 64;
    const int nrow = warpN * 32;

    float acc[4][4][4];
#pragma unroll
    for (int mi = 0; mi < 4; mi++)
#pragma unroll
        for (int ni = 0; ni < 4; ni++)
#pragma unroll
            for (int r = 0; r < 4; r++) acc[mi][ni][r] = 0.f;

    auto load_stage = [&](int stage, int ktile) {
        uint32_t s0 = sbase + stage * STAGE_BYTES;
        int kb = ktile * 64;
        // 2 arrays x 128 rows x 8 chunks(16B=8 halves) = 2048 chunks, 8/thread
#pragma unroll
        for (int i = 0; i < 8; i++) {
            int idx = i * 256 + tid;
            int arr = idx >> 10;
            int r = (idx >> 3) & 127;
            int c = idx & 7;
            const __half* src = arr ? (Wt + (size_t)r * Hn + kb + c * 8)
                                    : (Ag + (size_t)r * Hn + kb + c * 8);
            CPASYNC16(s0 + arr * TILE_BYTES + (uint32_t)(r * 144 + c * 16), src);
        }
    };

    auto compute = [&](int stage) {
        const uint32_t* sA = (const uint32_t*)(smem + stage * STAGE_BYTES);
        const uint32_t* sW = (const uint32_t*)(smem + stage * STAGE_BYTES + TILE_BYTES);
        const uint32_t* aB = sA + (mrow + g) * 36 + t;
        const uint32_t* bB = sW + (nrow + g) * 36 + t;
#pragma unroll
        for (int ks = 0; ks < 4; ks++) {
            const int kf = ks * 8;
            uint32_t a[4][4];
#pragma unroll
            for (int mi = 0; mi < 4; mi++) {
                a[mi][0] = aB[mi * 576 + kf];
                a[mi][1] = aB[mi * 576 + 288 + kf];
                a[mi][2] = aB[mi * 576 + kf + 4];
                a[mi][3] = aB[mi * 576 + 288 + kf + 4];
            }
            uint32_t b[4][2];
#pragma unroll
            for (int ni = 0; ni < 4; ni++) {
                b[ni][0] = bB[ni * 288 + kf];
                b[ni][1] = bB[ni * 288 + kf + 4];
            }
#pragma unroll
            for (int mi = 0; mi < 4; mi++)
#pragma unroll
                for (int ni = 0; ni < 4; ni++)
                    mma_f16(acc[mi][ni], a[mi][0], a[mi][1], a[mi][2], a[mi][3],
                            b[ni][0], b[ni][1]);
        }
    };

    const int NKT = Hn / 64;   // 12
    load_stage(0, 0); CP_COMMIT();
    load_stage(1, 1); CP_COMMIT();

    for (int kt = 0; kt < NKT; kt++) {
        if (kt < NKT - 2) { CP_WAIT(1); } else { CP_WAIT(0); }
        __syncthreads();
        if (kt + 2 < NKT) {
            load_stage((kt + 2) % GSTAGES, kt + 2);
            CP_COMMIT();
        }
        compute(kt % GSTAGES);
    }

    // epilogue: add bias, round to tf32, store; V tiles also column-sum
    const bool do_vsum = (z == 2) && ((blockIdx.y % 6) < 5);
    float s0[4] = {0.f, 0.f, 0.f, 0.f};
    float s1[4] = {0.f, 0.f, 0.f, 0.f};

#pragma unroll
    for (int mi = 0; mi < 4; mi++) {
#pragma unroll
        for (int ni = 0; ni < 4; ni++) {
            int row0 = rowBase + mrow + mi * 16 + g;
            int col0 = colBase + nrow + ni * 8 + 2 * t;
            float b0 = bias[col0], b1 = bias[col0 + 1];
            float2 v0 = make_float2(tf32r(acc[mi][ni][0] + b0), tf32r(acc[mi][ni][1] + b1));
            float2 v1 = make_float2(tf32r(acc[mi][ni][2] + b0), tf32r(acc[mi][ni][3] + b1));
            *(float2*)(C + (size_t)row0 * Hn + col0) = v0;
            *(float2*)(C + (size_t)(row0 + 8) * Hn + col0) = v1;
            s0[ni] += v0.x + v1.x;
            s1[ni] += v0.y + v1.y;
        }
    }

    if (do_vsum) {
        const int bb = rowBase / Sn;
#pragma unroll
        for (int ni = 0; ni < 4; ni++) {
            float a0 = s0[ni], a1 = s1[ni];
            a0 += __shfl_xor_sync(0xFFFFFFFFu, a0, 4);
            a0 += __shfl_xor_sync(0xFFFFFFFFu, a0, 8);
            a0 += __shfl_xor_sync(0xFFFFFFFFu, a0, 16);
            a1 += __shfl_xor_sync(0xFFFFFFFFu, a1, 4);
            a1 += __shfl_xor_sync(0xFFFFFFFFu, a1, 8);
            a1 += __shfl_xor_sync(0xFFFFFFFFu, a1, 16);
            if (g == 0) {
                int col = colBase + nrow + ni * 8 + 2 * t;
                atomicAdd(&g_Vsum[bb * Hn + col], a0);
                atomicAdd(&g_Vsum[bb * Hn + col + 1], a1);
            }
        }
    }
}

// ---------------------------------------------------------------------------
// Fused attention (512 threads, 2 CTAs/SM): one CTA per (chunk, head, batch).
// chunk==10 CTAs copy the V tail rows to the output (fused tail_copy).
// Scores: tf32 mma (Q A-frags from global, K from smem).
// PV: tf32 mma (P in smem with chunk-fold e-em, V staged in smem stride 72).
// Mask correction: out = PV' + em*Vsum (fold), no masked-v-sum phase.
// ---------------------------------------------------------------------------
#define SVS 72
#define SKS 68
#define SPS 196
#define OFF_K (192 * SVS)                 // 13824
#define OFF_SMALL (OFF_K + 192 * SKS)     // 26880
#define ATTN_F (OFF_SMALL + 128)          // 27008 floats = 108032 B

__global__ __launch_bounds__(512, 2) void attn_kernel(float* __restrict__ out)
{
    const int tid = threadIdx.x;
    const int chunk = blockIdx.x;
    const int h = blockIdx.y;
    const int b = blockIdx.z;

    if (chunk == CHn) {
        const size_t base = ((size_t)b * Sn + NQn) * Hn + h * DHn;
#pragma unroll
        for (int r = 0; r < 4; r++) {
            int idx = r * 512 + tid;
            int row = idx >> 4, c4 = idx & 15;
            *(float4*)(out + base + (size_t)row * Hn + c4 * 4) =
                *(const float4*)(g_V + base + (size_t)row * Hn + c4 * 4);
        }
        return;
    }

    extern __shared__ float sm[];
    float* sV  = sm;                    // 192 * 72 (persists)
    float* sk  = sm + OFF_K;            // 192 * 68 (scores only)
    float* sp  = sm + OFF_K;            // overlay after scores
    float* sem = sm + OFF_SMALL;        // 64
    float* sz  = sem + 64;              // 64

    const size_t rowC = (size_t)b * Sn + chunk * 64;
    const size_t baseC = rowC * Hn + h * DHn;
    const size_t baseT = ((size_t)b * Sn + 576) * Hn + h * DHn;   // rows 576+j, j>=64
    const float* qp = g_Q + baseC;
    const float* vc = g_V + baseC;
    const float* vt = g_V + ((size_t)b * Sn + NQn) * Hn + h * DHn;

    for (int idx = tid; idx < 192 * 16; idx += 512) {
        int j = idx >> 4, c4 = idx & 15;
        const float* src = (j < 64) ? (vc + (size_t)j * Hn + c4 * 4)
                                    : (vt + (size_t)(j - 64) * Hn + c4 * 4);
        *(float4*)&sV[j * SVS + c4 * 4] = *(const float4*)src;
    }
    for (int idx = tid; idx < 192 * 16; idx += 512) {
        int j = idx >> 4, c4 = idx & 15;
        size_t off = (j < 64) ? (baseC + (size_t)j * Hn + c4 * 4)
                              : (baseT + (size_t)j * Hn + c4 * 4);
        *(float4*)&sk[j * SKS + c4 * 4] = *(const float4*)(g_K + off);
    }
    __syncthreads();

    const int lane = tid & 31;
    const int wid = tid >> 5;
    const int g = lane >> 2;
    const int t = lane & 3;
    const int mbase = (wid & 3) * 16;    // 4 row-groups of 16
    const int nbase = (wid >> 2) * 48;   // 4 col-groups of 48 (scores)

    float acc[6][4];
#pragma unroll
    for (int nt = 0; nt < 6; nt++)
#pragma unroll
        for (int r = 0; r < 4; r++) acc[nt][r] = 0.f;

    const float* qr0 = qp + (size_t)(mbase + g) * Hn + t;
    const float* qr1 = qr0 + 8 * Hn;
#pragma unroll
    for (int ks = 0; ks < 8; ks++) {
        const int k0 = ks * 8;
        uint32_t a0 = __float_as_uint(__ldg(qr0 + k0));
        uint32_t a1 = __float_as_uint(__ldg(qr1 + k0));
        uint32_t a2 = __float_as_uint(__ldg(qr0 + k0 + 4));
        uint32_t a3 = __float_as_uint(__ldg(qr1 + k0 + 4));
#pragma unroll
        for (int nt = 0; nt < 6; nt++) {
            const int n = nbase + nt * 8 + g;
            uint32_t b0 = __float_as_uint(sk[n * SKS + k0 + t]);
            uint32_t b1 = __float_as_uint(sk[n * SKS + k0 + t + 4]);
            mma_tf32(acc[nt], a0, a1, a2, a3, b0, b1);
        }
    }
    __syncthreads();

#pragma unroll
    for (int nt = 0; nt < 6; nt++) {
        const int c0 = nbase + nt * 8 + 2 * t;
        *(float2*)&sp[(mbase + g) * SPS + c0] =
            make_float2(acc[nt][0] * 0.125f, acc[nt][1] * 0.125f);
        *(float2*)&sp[(mbase + g + 8) * SPS + c0] =
            make_float2(acc[nt][2] * 0.125f, acc[nt][3] * 0.125f);
    }
    __syncthreads();

    // softmax: chunk cols store e-em (mask fold)
    {
        const int i = tid >> 3, part = tid & 7;
        const int j0 = part * 24;
        float m = 0.f;
#pragma unroll
        for (int j = j0; j < j0 + 24; j++) m = fmaxf(m, sp[i * SPS + j]);
        m = fmaxf(m, __shfl_xor_sync(0xFFFFFFFFu, m, 1));
        m = fmaxf(m, __shfl_xor_sync(0xFFFFFFFFu, m, 2));
        m = fmaxf(m, __shfl_xor_sync(0xFFFFFFFFu, m, 4));
        const float em = __expf(-m);
        float Z = 0.f;
#pragma unroll
        for (int j = j0; j < j0 + 24; j++) {
            float e = __expf(sp[i * SPS + j] - m);
            Z += e;
            sp[i * SPS + j] = tf32r((j < 64) ? (e - em) : e);
        }
        Z += __shfl_xor_sync(0xFFFFFFFFu, Z, 1);
        Z += __shfl_xor_sync(0xFFFFFFFFu, Z, 2);
        Z += __shfl_xor_sync(0xFFFFFFFFu, Z, 4);
        if (part == 0) {
            sem[i] = em;
            sz[i] = 1.f / (Z + 576.f * em);
        }
    }
    __syncthreads();

    // PV: tf32 mma; warp = 16 q-rows x 16 d-cols; V frags from smem
    {
        const int dbase = (wid >> 2) * 16;
        float c0[4] = {0.f, 0.f, 0.f, 0.f};
        float c1[4] = {0.f, 0.f, 0.f, 0.f};

#pragma unroll
        for (int ks = 0; ks < 24; ks++) {
            const int k0 = ks * 8;
            uint32_t a0 = __float_as_uint(sp[(mbase + g) * SPS + k0 + t]);
            uint32_t a1 = __float_as_uint(sp[(mbase + g + 8) * SPS + k0 + t]);
            uint32_t a2 = __float_as_uint(sp[(mbase + g) * SPS + k0 + t + 4]);
            uint32_t a3 = __float_as_uint(sp[(mbase + g + 8) * SPS + k0 + t + 4]);
            uint32_t b00 = __float_as_uint(sV[(k0 + t) * SVS + dbase + g]);
            uint32_t b01 = __float_as_uint(sV[(k0 + t + 4) * SVS + dbase + g]);
            uint32_t b10 = __float_as_uint(sV[(k0 + t) * SVS + dbase + 8 + g]);
            uint32_t b11 = __float_as_uint(sV[(k0 + t + 4) * SVS + dbase + 8 + g]);
            mma_tf32(c0, a0, a1, a2, a3, b00, b01);
            mma_tf32(c1, a0, a1, a2, a3, b10, b11);
        }

        const int r0 = mbase + g, r1 = r0 + 8;
        const float inv0 = sz[r0], em0 = sem[r0];
        const float inv1 = sz[r1], em1 = sem[r1];
        const float* vsum = g_Vsum + b * Hn + h * DHn;
#pragma unroll
        for (int nt = 0; nt < 2; nt++) {
            const float* cc = nt ? c1 : c0;
            const int col = dbase + nt * 8 + 2 * t;
            const float s0 = __ldg(vsum + col), s1 = __ldg(vsum + col + 1);
            float2 o0 = make_float2((cc[0] + em0 * s0) * inv0,
                                    (cc[1] + em0 * s1) * inv0);
            float2 o1 = make_float2((cc[2] + em1 * s0) * inv1,
                                    (cc[3] + em1 * s1) * inv1);
            *(float2*)(out + (rowC + r0) * Hn + h * DHn + col) = o0;
            *(float2*)(out + (rowC + r1) * Hn + h * DHn + col) = o1;
        }
    }
}

// ---------------------------------------------------------------------------
extern "C" void kernel_launch(void* const* d_in, const int* in_sizes, int n_in,
                              void* d_out, int out_size)
{
    const float* hs = (const float*)d_in[0];
    const float* Wq = (const float*)d_in[1];
    const float* bq = (const float*)d_in[2];
    const float* Wk = (const float*)d_in[3];
    const float* bk = (const float*)d_in[4];
    const float* Wv = (const float*)d_in[5];
    const float* bv = (const float*)d_in[6];
    float* out = (float*)d_out;

    prep<<<2048, 256>>>(hs, Wq, Wk, Wv);     // idx 0

    cudaFuncSetAttribute(gemm_qkv, cudaFuncAttributeMaxDynamicSharedMemorySize,
                         GEMM_SMEM);
    gemm_qkv<<<dim3(Hn / 128, Mn / 128, 3), 256, GEMM_SMEM>>>(bq, bk, bv); // idx 1

    const int attn_smem = ATTN_F * 4;   // 108032 B
    cudaFuncSetAttribute(attn_kernel, cudaFuncAttributeMaxDynamicSharedMemorySize,
                         attn_smem);
    attn_kernel<<<dim3(CHn + 1, NHn, Bn), 512, attn_smem>>>(out);          // idx 2
}

// round 16
// speedup vs baseline: 3.1750x; 1.1207x over previous
#include <cuda_runtime.h>
#include <cuda_fp16.h>
#include <cstdint>
#include <math.h>

#define Bn 16
#define Sn 768
#define Hn 768
#define Tn 128
#define NQn 640
#define DHn 64
#define NHn 12
#define CHn 10
#define Mn (Bn * Sn)   // 12288

// ---------------- device scratch (no cudaMalloc allowed) -------------------
__device__ float g_V[(size_t)Mn * Hn];       // fp32 V (tail copy)
__device__ float g_Vsum[Bn * Hn];
__device__ __half g_Ah[(size_t)Mn * Hn];     // fp16 hs (GEMM A)
__device__ __half g_Wh[3 * Hn * Hn];         // fp16 W (GEMM B)
__device__ __half g_Qh[(size_t)Mn * Hn];     // fp16 projections
__device__ __half g_Kh[(size_t)Mn * Hn];
__device__ __half g_Vh[(size_t)Mn * Hn];

// ---------------------------------------------------------------------------
__device__ __forceinline__ void mma_f16(float c[4], uint32_t a0, uint32_t a1,
                                        uint32_t a2, uint32_t a3,
                                        uint32_t b0, uint32_t b1)
{
    asm volatile(
        "mma.sync.aligned.m16n8k16.row.col.f32.f16.f16.f32 "
        "{%0,%1,%2,%3}, {%4,%5,%6,%7}, {%8,%9}, {%0,%1,%2,%3};\n"
        : "+f"(c[0]), "+f"(c[1]), "+f"(c[2]), "+f"(c[3])
        : "r"(a0), "r"(a1), "r"(a2), "r"(a3), "r"(b0), "r"(b1));
}

#define CPASYNC16(saddr, gptr) \
    asm volatile("cp.async.cg.shared.global [%0], [%1], 16;\n" :: "r"(saddr), "l"(gptr))
#define CP_COMMIT() asm volatile("cp.async.commit_group;\n")
#define CP_WAIT(N)  asm volatile("cp.async.wait_group %0;\n" :: "n"(N))

// ---------------------------------------------------------------------------
// prep: fp16-convert hs and W, zero Vsum
// ---------------------------------------------------------------------------
__global__ void prep(const float* __restrict__ hs,
                     const float* __restrict__ Wq, const float* __restrict__ Wk,
                     const float* __restrict__ Wv)
{
    const int gs = gridDim.x * blockDim.x;
    const int t0 = blockIdx.x * blockDim.x + threadIdx.x;

    const int n4 = (Mn * Hn) / 4;
    __half2* dst = (__half2*)g_Ah;
    for (int i = t0; i < n4; i += gs) {
        float4 x = ((const float4*)hs)[i];
        dst[2 * i + 0] = __floats2half2_rn(x.x, x.y);
        dst[2 * i + 1] = __floats2half2_rn(x.z, x.w);
    }
    const int n = Hn * Hn;
    for (int i = t0; i < 3 * n; i += gs) {
        int z = i / n, j = i - z * n;
        const float* W = (z == 0) ? Wq : (z == 1) ? Wk : Wv;
        g_Wh[i] = __float2half_rn(W[j]);
    }
    for (int i = t0; i < Bn * Hn; i += gs) g_Vsum[i] = 0.f;
}

// ---------------------------------------------------------------------------
// fp16 tensor-core GEMM (m16n8k16, fp32 accum). Emits fp16 Q/K/V (+fp32 V).
// 128x128 tile, BK=64, 256 threads, 3-stage cp.async, 2 CTAs/SM.
// V tiles (z==2, rows<640) accumulate fp16-rounded column sums into g_Vsum.
// ---------------------------------------------------------------------------
#define TILE_BYTES (128 * 144)
#define STAGE_BYTES (2 * TILE_BYTES)
#define GSTAGES 3
#define GEMM_SMEM (GSTAGES * STAGE_BYTES)  // 110592

__global__ __launch_bounds__(256, 2) void gemm_qkv(
    const float* __restrict__ bq, const float* __restrict__ bk,
    const float* __restrict__ bv)
{
    extern __shared__ char smem[];
    const uint32_t sbase = (uint32_t)__cvta_generic_to_shared(smem);

    const int tid = threadIdx.x;
    const int rowBase = blockIdx.y * 128;
    const int colBase = blockIdx.x * 128;
    const int z = blockIdx.z;

    if (z == 0 && (blockIdx.y % 6) == 5) return;   // Q tail rows never read

    const __half* Ag = g_Ah + (size_t)rowBase * Hn;
    const __half* Wt = g_Wh + (size_t)z * Hn * Hn + (size_t)colBase * Hn;
    __half* Ch = (z == 0) ? g_Qh : (z == 1) ? g_Kh : g_Vh;
    const float* bias = (z == 0) ? bq : (z == 1) ? bk : bv;

    const int warp  = tid >> 5;
    const int lane  = tid & 31;
    const int warpM = warp >> 2;
    const int warpN = warp & 3;
    const int g  = lane >> 2;
    const int t  = lane & 3;
    const int mrow = warpM * 64;
    const int nrow = warpN * 32;

    float acc[4][4][4];
#pragma unroll
    for (int mi = 0; mi < 4; mi++)
#pragma unroll
        for (int ni = 0; ni < 4; ni++)
#pragma unroll
            for (int r = 0; r < 4; r++) acc[mi][ni][r] = 0.f;

    auto load_stage = [&](int stage, int ktile) {
        uint32_t s0 = sbase + stage * STAGE_BYTES;
        int kb = ktile * 64;
#pragma unroll
        for (int i = 0; i < 8; i++) {
            int idx = i * 256 + tid;
            int arr = idx >> 10;
            int r = (idx >> 3) & 127;
            int c = idx & 7;
            const __half* src = arr ? (Wt + (size_t)r * Hn + kb + c * 8)
                                    : (Ag + (size_t)r * Hn + kb + c * 8);
            CPASYNC16(s0 + arr * TILE_BYTES + (uint32_t)(r * 144 + c * 16), src);
        }
    };

    auto compute = [&](int stage) {
        const uint32_t* sA = (const uint32_t*)(smem + stage * STAGE_BYTES);
        const uint32_t* sW = (const uint32_t*)(smem + stage * STAGE_BYTES + TILE_BYTES);
        const uint32_t* aB = sA + (mrow + g) * 36 + t;
        const uint32_t* bB = sW + (nrow + g) * 36 + t;
#pragma unroll
        for (int ks = 0; ks < 4; ks++) {
            const int kf = ks * 8;
            uint32_t a[4][4];
#pragma unroll
            for (int mi = 0; mi < 4; mi++) {
                a[mi][0] = aB[mi * 576 + kf];
                a[mi][1] = aB[mi * 576 + 288 + kf];
                a[mi][2] = aB[mi * 576 + kf + 4];
                a[mi][3] = aB[mi * 576 + 288 + kf + 4];
            }
            uint32_t b[4][2];
#pragma unroll
            for (int ni = 0; ni < 4; ni++) {
                b[ni][0] = bB[ni * 288 + kf];
                b[ni][1] = bB[ni * 288 + kf + 4];
            }
#pragma unroll
            for (int mi = 0; mi < 4; mi++)
#pragma unroll
                for (int ni = 0; ni < 4; ni++)
                    mma_f16(acc[mi][ni], a[mi][0], a[mi][1], a[mi][2], a[mi][3],
                            b[ni][0], b[ni][1]);
        }
    };

    const int NKT = Hn / 64;   // 12
    load_stage(0, 0); CP_COMMIT();
    load_stage(1, 1); CP_COMMIT();

    for (int kt = 0; kt < NKT; kt++) {
        if (kt < NKT - 2) { CP_WAIT(1); } else { CP_WAIT(0); }
        __syncthreads();
        if (kt + 2 < NKT) {
            load_stage((kt + 2) % GSTAGES, kt + 2);
            CP_COMMIT();
        }
        compute(kt % GSTAGES);
    }

    // epilogue: bias, fp16 store (+fp32 V), fp16-consistent Vsum
    const bool isV = (z == 2);
    const bool do_vsum = isV && ((blockIdx.y % 6) < 5);
    float s0[4] = {0.f, 0.f, 0.f, 0.f};
    float s1[4] = {0.f, 0.f, 0.f, 0.f};

#pragma unroll
    for (int mi = 0; mi < 4; mi++) {
#pragma unroll
        for (int ni = 0; ni < 4; ni++) {
            int row0 = rowBase + mrow + mi * 16 + g;
            int col0 = colBase + nrow + ni * 8 + 2 * t;
            float b0 = bias[col0], b1 = bias[col0 + 1];
            float v00 = acc[mi][ni][0] + b0, v01 = acc[mi][ni][1] + b1;
            float v10 = acc[mi][ni][2] + b0, v11 = acc[mi][ni][3] + b1;
            __half2 h0 = __floats2half2_rn(v00, v01);
            __half2 h1 = __floats2half2_rn(v10, v11);
            *(__half2*)(Ch + (size_t)row0 * Hn + col0) = h0;
            *(__half2*)(Ch + (size_t)(row0 + 8) * Hn + col0) = h1;
            if (isV) {
                *(float2*)(g_V + (size_t)row0 * Hn + col0) = make_float2(v00, v01);
                *(float2*)(g_V + (size_t)(row0 + 8) * Hn + col0) = make_float2(v10, v11);
                s0[ni] += __half2float(__low2half(h0)) + __half2float(__low2half(h1));
                s1[ni] += __half2float(__high2half(h0)) + __half2float(__high2half(h1));
            }
        }
    }

    if (do_vsum) {
        const int bb = rowBase / Sn;
#pragma unroll
        for (int ni = 0; ni < 4; ni++) {
            float a0 = s0[ni], a1 = s1[ni];
            a0 += __shfl_xor_sync(0xFFFFFFFFu, a0, 4);
            a0 += __shfl_xor_sync(0xFFFFFFFFu, a0, 8);
            a0 += __shfl_xor_sync(0xFFFFFFFFu, a0, 16);
            a1 += __shfl_xor_sync(0xFFFFFFFFu, a1, 4);
            a1 += __shfl_xor_sync(0xFFFFFFFFu, a1, 8);
            a1 += __shfl_xor_sync(0xFFFFFFFFu, a1, 16);
            if (g == 0) {
                int col = colBase + nrow + ni * 8 + 2 * t;
                atomicAdd(&g_Vsum[bb * Hn + col], a0);
                atomicAdd(&g_Vsum[bb * Hn + col + 1], a1);
            }
        }
    }
}

// ---------------------------------------------------------------------------
// Fused attention (512 threads, 2 CTAs/SM); fp16 MMAs for scores and PV.
// smem (floats): sVp[96*72 half2-words] | sK[192*36 words] (overlay: sPh
// 64*100 words) | sp fp32[64*196] | sem/sz.
// PV V-layout: sVp[k/2][d] word = (v[2k'],v[2k'+1]); conflict-free B LDS.
// Mask fold: chunk cols hold e-em; out = PV + em*Vsum.
// ---------------------------------------------------------------------------
#define SPW 196
#define OFF_KS 6912
#define OFF_SP (OFF_KS + 6912)            // 13824
#define OFF_SM (OFF_SP + 64 * SPW)        // 26368
#define ATTN_F (OFF_SM + 128)             // 26496 floats = 105984 B

__global__ __launch_bounds__(512, 2) void attn_kernel(float* __restrict__ out)
{
    const int tid = threadIdx.x;
    const int chunk = blockIdx.x;
    const int h = blockIdx.y;
    const int b = blockIdx.z;

    if (chunk == CHn) {
        const size_t base = ((size_t)b * Sn + NQn) * Hn + h * DHn;
#pragma unroll
        for (int r = 0; r < 4; r++) {
            int idx = r * 512 + tid;
            int row = idx >> 4, c4 = idx & 15;
            *(float4*)(out + base + (size_t)row * Hn + c4 * 4) =
                *(const float4*)(g_V + base + (size_t)row * Hn + c4 * 4);
        }
        return;
    }

    extern __shared__ float sm[];
    uint32_t* sVp  = (uint32_t*)sm;               // 96 x 72 words
    uint32_t* skw  = (uint32_t*)(sm + OFF_KS);    // 192 x 36 words
    uint32_t* sphw = (uint32_t*)(sm + OFF_KS);    // overlay: 64 x 100 words
    __half*   sph  = (__half*)(sm + OFF_KS);
    float*    sp   = sm + OFF_SP;                 // fp32 scores 64 x 196
    float*    sem  = sm + OFF_SM;
    float*    sz   = sem + 64;

    const size_t rowC = (size_t)b * Sn + chunk * 64;
    const size_t baseC = rowC * Hn + h * DHn;
    const size_t baseT = ((size_t)b * Sn + 576) * Hn + h * DHn;   // j>=64
    const __half* qh  = g_Qh + baseC;
    const __half* vhc = g_Vh + baseC;
    const __half* vht = g_Vh + ((size_t)b * Sn + NQn) * Hn + h * DHn;

    // stage V as k-pair half2 words: sVp[jp*72 + d] = (v[2jp][d], v[2jp+1][d])
    for (int idx = tid; idx < 96 * 8; idx += 512) {
        int jp = idx >> 3, c = idx & 7;
        int j = 2 * jp, d0 = c * 8;
        const __half* r0p = (j < 64) ? (vhc + (size_t)j * Hn + d0)
                                     : (vht + (size_t)(j - 64) * Hn + d0);
        const __half* r1p = r0p + Hn;
        uint4 u0 = *(const uint4*)r0p;
        uint4 u1 = *(const uint4*)r1p;
        const __half* h0 = (const __half*)&u0;
        const __half* h1 = (const __half*)&u1;
        uint32_t w[8];
#pragma unroll
        for (int c2 = 0; c2 < 8; c2++) {
            __half2 p = __halves2half2(h0[c2], h1[c2]);
            w[c2] = *(uint32_t*)&p;
        }
        *(uint4*)&sVp[jp * 72 + d0] = make_uint4(w[0], w[1], w[2], w[3]);
        *(uint4*)&sVp[jp * 72 + d0 + 4] = make_uint4(w[4], w[5], w[6], w[7]);
    }
    // stage K fp16 rows (stride 36 words)
    for (int idx = tid; idx < 192 * 8; idx += 512) {
        int j = idx >> 3, c = idx & 7;
        size_t off = (j < 64) ? (baseC + (size_t)j * Hn + c * 8)
                              : (baseT + (size_t)j * Hn + c * 8);
        *(uint4*)&skw[j * 36 + c * 4] = *(const uint4*)(g_Kh + off);
    }
    __syncthreads();

    const int lane = tid & 31;
    const int wid = tid >> 5;
    const int g = lane >> 2;
    const int t = lane & 3;
    const int mbase = (wid & 3) * 16;
    const int nbase = (wid >> 2) * 48;

    // ---- scores: fp16 mma, warp = 16 rows x 48 cols, 4 k-steps ----
    float acc[6][4];
#pragma unroll
    for (int nt = 0; nt < 6; nt++)
#pragma unroll
        for (int r = 0; r < 4; r++) acc[nt][r] = 0.f;

    const __half* q0 = qh + (size_t)(mbase + g) * Hn + 2 * t;
    const __half* q1 = q0 + 8 * Hn;
#pragma unroll
    for (int ks = 0; ks < 4; ks++) {
        const int kh = ks * 16;
        uint32_t a0 = __ldg((const uint32_t*)(q0 + kh));
        uint32_t a1 = __ldg((const uint32_t*)(q1 + kh));
        uint32_t a2 = __ldg((const uint32_t*)(q0 + kh + 8));
        uint32_t a3 = __ldg((const uint32_t*)(q1 + kh + 8));
        const int kw = ks * 8;
#pragma unroll
        for (int nt = 0; nt < 6; nt++) {
            const int n = nbase + nt * 8 + g;
            uint32_t b0 = skw[n * 36 + kw + t];
            uint32_t b1 = skw[n * 36 + kw + t + 4];
            mma_f16(acc[nt], a0, a1, a2, a3, b0, b1);
        }
    }
    __syncthreads();   // all skw reads done -> sph overlay safe after softmax

#pragma unroll
    for (int nt = 0; nt < 6; nt++) {
        const int c0 = nbase + nt * 8 + 2 * t;
        *(float2*)&sp[(mbase + g) * SPW + c0] =
            make_float2(acc[nt][0] * 0.125f, acc[nt][1] * 0.125f);
        *(float2*)&sp[(mbase + g + 8) * SPW + c0] =
            make_float2(acc[nt][2] * 0.125f, acc[nt][3] * 0.125f);
    }
    __syncthreads();

    // softmax: row = tid/8, 8 threads x 24 cols; P stored fp16 (chunk: e-em)
    {
        const int i = tid >> 3, part = tid & 7;
        const int j0 = part * 24;
        float m = 0.f;
#pragma unroll
        for (int j = j0; j < j0 + 24; j++) m = fmaxf(m, sp[i * SPW + j]);
        m = fmaxf(m, __shfl_xor_sync(0xFFFFFFFFu, m, 1));
        m = fmaxf(m, __shfl_xor_sync(0xFFFFFFFFu, m, 2));
        m = fmaxf(m, __shfl_xor_sync(0xFFFFFFFFu, m, 4));
        const float em = __expf(-m);
        float Z = 0.f;
#pragma unroll
        for (int j = j0; j < j0 + 24; j++) {
            float e = __expf(sp[i * SPW + j] - m);
            Z += e;
            sph[i * 200 + j] = __float2half_rn((j < 64) ? (e - em) : e);
        }
        Z += __shfl_xor_sync(0xFFFFFFFFu, Z, 1);
        Z += __shfl_xor_sync(0xFFFFFFFFu, Z, 2);
        Z += __shfl_xor_sync(0xFFFFFFFFu, Z, 4);
        if (part == 0) {
            sem[i] = em;
            sz[i] = 1.f / (Z + 576.f * em);
        }
    }
    __syncthreads();

    // ---- PV: fp16 mma, 12 k-steps; B from sVp, A from sph ----
    {
        const int dbase = (wid >> 2) * 16;
        float c0[4] = {0.f, 0.f, 0.f, 0.f};
        float c1[4] = {0.f, 0.f, 0.f, 0.f};

#pragma unroll
        for (int ks = 0; ks < 12; ks++) {
            const int kw = ks * 8;
            uint32_t a0 = sphw[(mbase + g) * 100 + kw + t];
            uint32_t a1 = sphw[(mbase + g + 8) * 100 + kw + t];
            uint32_t a2 = sphw[(mbase + g) * 100 + kw + t + 4];
            uint32_t a3 = sphw[(mbase + g + 8) * 100 + kw + t + 4];
            uint32_t b00 = sVp[(kw + t) * 72 + dbase + g];
            uint32_t b01 = sVp[(kw + t + 4) * 72 + dbase + g];
            uint32_t b10 = sVp[(kw + t) * 72 + dbase + 8 + g];
            uint32_t b11 = sVp[(kw + t + 4) * 72 + dbase + 8 + g];
            mma_f16(c0, a0, a1, a2, a3, b00, b01);
            mma_f16(c1, a0, a1, a2, a3, b10, b11);
        }

        const int r0 = mbase + g, r1 = r0 + 8;
        const float inv0 = sz[r0], em0 = sem[r0];
        const float inv1 = sz[r1], em1 = sem[r1];
        const float* vsum = g_Vsum + b * Hn + h * DHn;
#pragma unroll
        for (int nt = 0; nt < 2; nt++) {
            const float* cc = nt ? c1 : c0;
            const int col = dbase + nt * 8 + 2 * t;
            const float s0 = __ldg(vsum + col), s1 = __ldg(vsum + col + 1);
            float2 o0 = make_float2((cc[0] + em0 * s0) * inv0,
                                    (cc[1] + em0 * s1) * inv0);
            float2 o1 = make_float2((cc[2] + em1 * s0) * inv1,
                                    (cc[3] + em1 * s1) * inv1);
            *(float2*)(out + (rowC + r0) * Hn + h * DHn + col) = o0;
            *(float2*)(out + (rowC + r1) * Hn + h * DHn + col) = o1;
        }
    }
}

// ---------------------------------------------------------------------------
extern "C" void kernel_launch(void* const* d_in, const int* in_sizes, int n_in,
                              void* d_out, int out_size)
{
    const float* hs = (const float*)d_in[0];
    const float* Wq = (const float*)d_in[1];
    const float* bq = (const float*)d_in[2];
    const float* Wk = (const float*)d_in[3];
    const float* bk = (const float*)d_in[4];
    const float* Wv = (const float*)d_in[5];
    const float* bv = (const float*)d_in[6];
    float* out = (float*)d_out;

    prep<<<2048, 256>>>(hs, Wq, Wk, Wv);     // idx 0

    cudaFuncSetAttribute(gemm_qkv, cudaFuncAttributeMaxDynamicSharedMemorySize,
                         GEMM_SMEM);
    gemm_qkv<<<dim3(Hn / 128, Mn / 128, 3), 256, GEMM_SMEM>>>(bq, bk, bv); // idx 1

    const int attn_smem = ATTN_F * 4;   // 105984 B
    cudaFuncSetAttribute(attn_kernel, cudaFuncAttributeMaxDynamicSharedMemorySize,
                         attn_smem);
    attn_kernel<<<dim3(CHn + 1, NHn, Bn), 512, attn_smem>>>(out);          // idx 2
}

// round 17
// speedup vs baseline: 3.2647x; 1.0283x over previous
#include <cuda_runtime.h>
#include <cuda_fp16.h>
#include <cstdint>
#include <math.h>

#define Bn 16
#define Sn 768
#define Hn 768
#define Tn 128
#define NQn 640
#define DHn 64
#define NHn 12
#define CHn 10
#define Mn (Bn * Sn)   // 12288

// ---------------- device scratch (no cudaMalloc allowed) -------------------
__device__ float g_Vsum[Bn * Hn];
__device__ __half g_Ah[(size_t)Mn * Hn];     // fp16 hs (GEMM A)
__device__ __half g_Wh[3 * Hn * Hn];         // fp16 W (GEMM B)
__device__ __half g_Qh[(size_t)Mn * Hn];     // fp16 projections
__device__ __half g_Kh[(size_t)Mn * Hn];
__device__ __half g_Vh[(size_t)Mn * Hn];

// ---------------------------------------------------------------------------
__device__ __forceinline__ void mma_f16(float c[4], uint32_t a0, uint32_t a1,
                                        uint32_t a2, uint32_t a3,
                                        uint32_t b0, uint32_t b1)
{
    asm volatile(
        "mma.sync.aligned.m16n8k16.row.col.f32.f16.f16.f32 "
        "{%0,%1,%2,%3}, {%4,%5,%6,%7}, {%8,%9}, {%0,%1,%2,%3};\n"
        : "+f"(c[0]), "+f"(c[1]), "+f"(c[2]), "+f"(c[3])
        : "r"(a0), "r"(a1), "r"(a2), "r"(a3), "r"(b0), "r"(b1));
}

#define CPASYNC16(saddr, gptr) \
    asm volatile("cp.async.cg.shared.global [%0], [%1], 16;\n" :: "r"(saddr), "l"(gptr))
#define CP_COMMIT() asm volatile("cp.async.commit_group;\n")
#define CP_WAIT(N)  asm volatile("cp.async.wait_group %0;\n" :: "n"(N))

// ---------------------------------------------------------------------------
// prep: fp16-convert hs and W, zero Vsum
// ---------------------------------------------------------------------------
__global__ void prep(const float* __restrict__ hs,
                     const float* __restrict__ Wq, const float* __restrict__ Wk,
                     const float* __restrict__ Wv)
{
    const int gs = gridDim.x * blockDim.x;
    const int t0 = blockIdx.x * blockDim.x + threadIdx.x;

    const int n4 = (Mn * Hn) / 4;
    __half2* dst = (__half2*)g_Ah;
    for (int i = t0; i < n4; i += gs) {
        float4 x = ((const float4*)hs)[i];
        dst[2 * i + 0] = __floats2half2_rn(x.x, x.y);
        dst[2 * i + 1] = __floats2half2_rn(x.z, x.w);
    }
    const int n = Hn * Hn;
    for (int i = t0; i < 3 * n; i += gs) {
        int z = i / n, j = i - z * n;
        const float* W = (z == 0) ? Wq : (z == 1) ? Wk : Wv;
        g_Wh[i] = __float2half_rn(W[j]);
    }
    for (int i = t0; i < Bn * Hn; i += gs) g_Vsum[i] = 0.f;
}

// ---------------------------------------------------------------------------
// fp16 tensor-core GEMM (m16n8k16, fp32 accum). Emits fp16 Q/K/V.
// 128x128 tile, BK=64, 256 threads, 3-stage cp.async, 2 CTAs/SM.
// V tiles (z==2, rows<640) accumulate fp16-rounded column sums into g_Vsum.
// ---------------------------------------------------------------------------
#define TILE_BYTES (128 * 144)
#define STAGE_BYTES (2 * TILE_BYTES)
#define GSTAGES 3
#define GEMM_SMEM (GSTAGES * STAGE_BYTES)  // 110592

__global__ __launch_bounds__(256, 2) void gemm_qkv(
    const float* __restrict__ bq, const float* __restrict__ bk,
    const float* __restrict__ bv)
{
    extern __shared__ char smem[];
    const uint32_t sbase = (uint32_t)__cvta_generic_to_shared(smem);

    const int tid = threadIdx.x;
    const int rowBase = blockIdx.y * 128;
    const int colBase = blockIdx.x * 128;
    const int z = blockIdx.z;

    if (z == 0 && (blockIdx.y % 6) == 5) return;   // Q tail rows never read

    const __half* Ag = g_Ah + (size_t)rowBase * Hn;
    const __half* Wt = g_Wh + (size_t)z * Hn * Hn + (size_t)colBase * Hn;
    __half* Ch = (z == 0) ? g_Qh : (z == 1) ? g_Kh : g_Vh;
    const float* bias = (z == 0) ? bq : (z == 1) ? bk : bv;

    const int warp  = tid >> 5;
    const int lane  = tid & 31;
    const int warpM = warp >> 2;
    const int warpN = warp & 3;
    const int g  = lane >> 2;
    const int t  = lane & 3;
    const int mrow = warpM * 64;
    const int nrow = warpN * 32;

    float acc[4][4][4];
#pragma unroll
    for (int mi = 0; mi < 4; mi++)
#pragma unroll
        for (int ni = 0; ni < 4; ni++)
#pragma unroll
            for (int r = 0; r < 4; r++) acc[mi][ni][r] = 0.f;

    auto load_stage = [&](int stage, int ktile) {
        uint32_t s0 = sbase + stage * STAGE_BYTES;
        int kb = ktile * 64;
#pragma unroll
        for (int i = 0; i < 8; i++) {
            int idx = i * 256 + tid;
            int arr = idx >> 10;
            int r = (idx >> 3) & 127;
            int c = idx & 7;
            const __half* src = arr ? (Wt + (size_t)r * Hn + kb + c * 8)
                                    : (Ag + (size_t)r * Hn + kb + c * 8);
            CPASYNC16(s0 + arr * TILE_BYTES + (uint32_t)(r * 144 + c * 16), src);
        }
    };

    auto compute = [&](int stage) {
        const uint32_t* sA = (const uint32_t*)(smem + stage * STAGE_BYTES);
        const uint32_t* sW = (const uint32_t*)(smem + stage * STAGE_BYTES + TILE_BYTES);
        const uint32_t* aB = sA + (mrow + g) * 36 + t;
        const uint32_t* bB = sW + (nrow + g) * 36 + t;
#pragma unroll
        for (int ks = 0; ks < 4; ks++) {
            const int kf = ks * 8;
            uint32_t a[4][4];
#pragma unroll
            for (int mi = 0; mi < 4; mi++) {
                a[mi][0] = aB[mi * 576 + kf];
                a[mi][1] = aB[mi * 576 + 288 + kf];
                a[mi][2] = aB[mi * 576 + kf + 4];
                a[mi][3] = aB[mi * 576 + 288 + kf + 4];
            }
            uint32_t b[4][2];
#pragma unroll
            for (int ni = 0; ni < 4; ni++) {
                b[ni][0] = bB[ni * 288 + kf];
                b[ni][1] = bB[ni * 288 + kf + 4];
            }
#pragma unroll
            for (int mi = 0; mi < 4; mi++)
#pragma unroll
                for (int ni = 0; ni < 4; ni++)
                    mma_f16(acc[mi][ni], a[mi][0], a[mi][1], a[mi][2], a[mi][3],
                            b[ni][0], b[ni][1]);
        }
    };

    const int NKT = Hn / 64;   // 12
    load_stage(0, 0); CP_COMMIT();
    load_stage(1, 1); CP_COMMIT();

    for (int kt = 0; kt < NKT; kt++) {
        if (kt < NKT - 2) { CP_WAIT(1); } else { CP_WAIT(0); }
        __syncthreads();
        if (kt + 2 < NKT) {
            load_stage((kt + 2) % GSTAGES, kt + 2);
            CP_COMMIT();
        }
        compute(kt % GSTAGES);
    }

    // epilogue: bias, fp16 store; fp16-consistent Vsum for V tiles
    const bool isV = (z == 2);
    const bool do_vsum = isV && ((blockIdx.y % 6) < 5);
    float s0[4] = {0.f, 0.f, 0.f, 0.f};
    float s1[4] = {0.f, 0.f, 0.f, 0.f};

#pragma unroll
    for (int mi = 0; mi < 4; mi++) {
#pragma unroll
        for (int ni = 0; ni < 4; ni++) {
            int row0 = rowBase + mrow + mi * 16 + g;
            int col0 = colBase + nrow + ni * 8 + 2 * t;
            float b0 = bias[col0], b1 = bias[col0 + 1];
            __half2 h0 = __floats2half2_rn(acc[mi][ni][0] + b0, acc[mi][ni][1] + b1);
            __half2 h1 = __floats2half2_rn(acc[mi][ni][2] + b0, acc[mi][ni][3] + b1);
            *(__half2*)(Ch + (size_t)row0 * Hn + col0) = h0;
            *(__half2*)(Ch + (size_t)(row0 + 8) * Hn + col0) = h1;
            if (do_vsum) {
                s0[ni] += __half2float(__low2half(h0)) + __half2float(__low2half(h1));
                s1[ni] += __half2float(__high2half(h0)) + __half2float(__high2half(h1));
            }
        }
    }

    if (do_vsum) {
        const int bb = rowBase / Sn;
#pragma unroll
        for (int ni = 0; ni < 4; ni++) {
            float a0 = s0[ni], a1 = s1[ni];
            a0 += __shfl_xor_sync(0xFFFFFFFFu, a0, 4);
            a0 += __shfl_xor_sync(0xFFFFFFFFu, a0, 8);
            a0 += __shfl_xor_sync(0xFFFFFFFFu, a0, 16);
            a1 += __shfl_xor_sync(0xFFFFFFFFu, a1, 4);
            a1 += __shfl_xor_sync(0xFFFFFFFFu, a1, 8);
            a1 += __shfl_xor_sync(0xFFFFFFFFu, a1, 16);
            if (g == 0) {
                int col = colBase + nrow + ni * 8 + 2 * t;
                atomicAdd(&g_Vsum[bb * Hn + col], a0);
                atomicAdd(&g_Vsum[bb * Hn + col + 1], a1);
            }
        }
    }
}

// ---------------------------------------------------------------------------
// Fused attention (512 threads, 2 CTAs/SM); fp16 MMAs for scores and PV.
// chunk==10 CTAs emit the tail rows from g_Vh (fp16 -> fp32).
// Mask fold: chunk cols hold e-em; out = PV + em*Vsum.
// ---------------------------------------------------------------------------
#define SPW 196
#define OFF_KS 6912
#define OFF_SP (OFF_KS + 6912)            // 13824
#define OFF_SM (OFF_SP + 64 * SPW)        // 26368
#define ATTN_F (OFF_SM + 128)             // 26496 floats = 105984 B

__global__ __launch_bounds__(512, 2) void attn_kernel(float* __restrict__ out)
{
    const int tid = threadIdx.x;
    const int chunk = blockIdx.x;
    const int h = blockIdx.y;
    const int b = blockIdx.z;

    if (chunk == CHn) {
        // tail: out rows 640..767, cols h*64.. <- fp16 V upconverted
        const size_t base = ((size_t)b * Sn + NQn) * Hn + h * DHn;
#pragma unroll
        for (int r = 0; r < 8; r++) {
            int idx = r * 512 + tid;            // 128 rows x 32 half2-chunks
            int row = idx >> 5, c2 = idx & 31;
            __half2 v = *(const __half2*)(g_Vh + base + (size_t)row * Hn + c2 * 2);
            *(float2*)(out + base + (size_t)row * Hn + c2 * 2) =
                make_float2(__half2float(__low2half(v)), __half2float(__high2half(v)));
        }
        return;
    }

    extern __shared__ float sm[];
    uint32_t* sVp  = (uint32_t*)sm;               // 96 x 72 words
    uint32_t* skw  = (uint32_t*)(sm + OFF_KS);    // 192 x 36 words
    uint32_t* sphw = (uint32_t*)(sm + OFF_KS);    // overlay: 64 x 100 words
    __half*   sph  = (__half*)(sm + OFF_KS);
    float*    sp   = sm + OFF_SP;                 // fp32 scores 64 x 196
    float*    sem  = sm + OFF_SM;
    float*    sz   = sem + 64;

    const size_t rowC = (size_t)b * Sn + chunk * 64;
    const size_t baseC = rowC * Hn + h * DHn;
    const size_t baseT = ((size_t)b * Sn + 576) * Hn + h * DHn;   // j>=64
    const __half* qh  = g_Qh + baseC;
    const __half* vhc = g_Vh + baseC;
    const __half* vht = g_Vh + ((size_t)b * Sn + NQn) * Hn + h * DHn;

    // stage V as k-pair half2 words: sVp[jp*72 + d] = (v[2jp][d], v[2jp+1][d])
    for (int idx = tid; idx < 96 * 8; idx += 512) {
        int jp = idx >> 3, c = idx & 7;
        int j = 2 * jp, d0 = c * 8;
        const __half* r0p = (j < 64) ? (vhc + (size_t)j * Hn + d0)
                                     : (vht + (size_t)(j - 64) * Hn + d0);
        const __half* r1p = r0p + Hn;
        uint4 u0 = *(const uint4*)r0p;
        uint4 u1 = *(const uint4*)r1p;
        const __half* h0 = (const __half*)&u0;
        const __half* h1 = (const __half*)&u1;
        uint32_t w[8];
#pragma unroll
        for (int c2 = 0; c2 < 8; c2++) {
            __half2 p = __halves2half2(h0[c2], h1[c2]);
            w[c2] = *(uint32_t*)&p;
        }
        *(uint4*)&sVp[jp * 72 + d0] = make_uint4(w[0], w[1], w[2], w[3]);
        *(uint4*)&sVp[jp * 72 + d0 + 4] = make_uint4(w[4], w[5], w[6], w[7]);
    }
    // stage K fp16 rows (stride 36 words)
    for (int idx = tid; idx < 192 * 8; idx += 512) {
        int j = idx >> 3, c = idx & 7;
        size_t off = (j < 64) ? (baseC + (size_t)j * Hn + c * 8)
                              : (baseT + (size_t)j * Hn + c * 8);
        *(uint4*)&skw[j * 36 + c * 4] = *(const uint4*)(g_Kh + off);
    }
    __syncthreads();

    const int lane = tid & 31;
    const int wid = tid >> 5;
    const int g = lane >> 2;
    const int t = lane & 3;
    const int mbase = (wid & 3) * 16;
    const int nbase = (wid >> 2) * 48;

    // ---- scores: fp16 mma, warp = 16 rows x 48 cols, 4 k-steps ----
    float acc[6][4];
#pragma unroll
    for (int nt = 0; nt < 6; nt++)
#pragma unroll
        for (int r = 0; r < 4; r++) acc[nt][r] = 0.f;

    const __half* q0 = qh + (size_t)(mbase + g) * Hn + 2 * t;
    const __half* q1 = q0 + 8 * Hn;
#pragma unroll
    for (int ks = 0; ks < 4; ks++) {
        const int kh = ks * 16;
        uint32_t a0 = __ldg((const uint32_t*)(q0 + kh));
        uint32_t a1 = __ldg((const uint32_t*)(q1 + kh));
        uint32_t a2 = __ldg((const uint32_t*)(q0 + kh + 8));
        uint32_t a3 = __ldg((const uint32_t*)(q1 + kh + 8));
        const int kw = ks * 8;
#pragma unroll
        for (int nt = 0; nt < 6; nt++) {
            const int n = nbase + nt * 8 + g;
            uint32_t b0 = skw[n * 36 + kw + t];
            uint32_t b1 = skw[n * 36 + kw + t + 4];
            mma_f16(acc[nt], a0, a1, a2, a3, b0, b1);
        }
    }
    __syncthreads();

#pragma unroll
    for (int nt = 0; nt < 6; nt++) {
        const int c0 = nbase + nt * 8 + 2 * t;
        *(float2*)&sp[(mbase + g) * SPW + c0] =
            make_float2(acc[nt][0] * 0.125f, acc[nt][1] * 0.125f);
        *(float2*)&sp[(mbase + g + 8) * SPW + c0] =
            make_float2(acc[nt][2] * 0.125f, acc[nt][3] * 0.125f);
    }
    __syncthreads();

    // softmax: row = tid/8, 8 threads x 24 cols; P stored fp16 (chunk: e-em)
    {
        const int i = tid >> 3, part = tid & 7;
        const int j0 = part * 24;
        float m = 0.f;
#pragma unroll
        for (int j = j0; j < j0 + 24; j++) m = fmaxf(m, sp[i * SPW + j]);
        m = fmaxf(m, __shfl_xor_sync(0xFFFFFFFFu, m, 1));
        m = fmaxf(m, __shfl_xor_sync(0xFFFFFFFFu, m, 2));
        m = fmaxf(m, __shfl_xor_sync(0xFFFFFFFFu, m, 4));
        const float em = __expf(-m);
        float Z = 0.f;
#pragma unroll
        for (int j = j0; j < j0 + 24; j++) {
            float e = __expf(sp[i * SPW + j] - m);
            Z += e;
            sph[i * 200 + j] = __float2half_rn((j < 64) ? (e - em) : e);
        }
        Z += __shfl_xor_sync(0xFFFFFFFFu, Z, 1);
        Z += __shfl_xor_sync(0xFFFFFFFFu, Z, 2);
        Z += __shfl_xor_sync(0xFFFFFFFFu, Z, 4);
        if (part == 0) {
            sem[i] = em;
            sz[i] = 1.f / (Z + 576.f * em);
        }
    }
    __syncthreads();

    // ---- PV: fp16 mma, 12 k-steps; B from sVp, A from sph ----
    {
        const int dbase = (wid >> 2) * 16;
        float c0[4] = {0.f, 0.f, 0.f, 0.f};
        float c1[4] = {0.f, 0.f, 0.f, 0.f};

#pragma unroll
        for (int ks = 0; ks < 12; ks++) {
            const int kw = ks * 8;
            uint32_t a0 = sphw[(mbase + g) * 100 + kw + t];
            uint32_t a1 = sphw[(mbase + g + 8) * 100 + kw + t];
            uint32_t a2 = sphw[(mbase + g) * 100 + kw + t + 4];
            uint32_t a3 = sphw[(mbase + g + 8) * 100 + kw + t + 4];
            uint32_t b00 = sVp[(kw + t) * 72 + dbase + g];
            uint32_t b01 = sVp[(kw + t + 4) * 72 + dbase + g];
            uint32_t b10 = sVp[(kw + t) * 72 + dbase + 8 + g];
            uint32_t b11 = sVp[(kw + t + 4) * 72 + dbase + 8 + g];
            mma_f16(c0, a0, a1, a2, a3, b00, b01);
            mma_f16(c1, a0, a1, a2, a3, b10, b11);
        }

        const int r0 = mbase + g, r1 = r0 + 8;
        const float inv0 = sz[r0], em0 = sem[r0];
        const float inv1 = sz[r1], em1 = sem[r1];
        const float* vsum = g_Vsum + b * Hn + h * DHn;
#pragma unroll
        for (int nt = 0; nt < 2; nt++) {
            const float* cc = nt ? c1 : c0;
            const int col = dbase + nt * 8 + 2 * t;
            const float s0 = __ldg(vsum + col), s1 = __ldg(vsum + col + 1);
            float2 o0 = make_float2((cc[0] + em0 * s0) * inv0,
                                    (cc[1] + em0 * s1) * inv0);
            float2 o1 = make_float2((cc[2] + em1 * s0) * inv1,
                                    (cc[3] + em1 * s1) * inv1);
            *(float2*)(out + (rowC + r0) * Hn + h * DHn + col) = o0;
            *(float2*)(out + (rowC + r1) * Hn + h * DHn + col) = o1;
        }
    }
}

// ---------------------------------------------------------------------------
extern "C" void kernel_launch(void* const* d_in, const int* in_sizes, int n_in,
                              void* d_out, int out_size)
{
    const float* hs = (const float*)d_in[0];
    const float* Wq = (const float*)d_in[1];
    const float* bq = (const float*)d_in[2];
    const float* Wk = (const float*)d_in[3];
    const float* bk = (const float*)d_in[4];
    const float* Wv = (const float*)d_in[5];
    const float* bv = (const float*)d_in[6];
    float* out = (float*)d_out;

    prep<<<2048, 256>>>(hs, Wq, Wk, Wv);     // idx 0

    cudaFuncSetAttribute(gemm_qkv, cudaFuncAttributeMaxDynamicSharedMemorySize,
                         GEMM_SMEM);
    gemm_qkv<<<dim3(Hn / 128, Mn / 128, 3), 256, GEMM_SMEM>>>(bq, bk, bv); // idx 1

    const int attn_smem = ATTN_F * 4;   // 105984 B
    cudaFuncSetAttribute(attn_kernel, cudaFuncAttributeMaxDynamicSharedMemorySize,
                         attn_smem);
    attn_kernel<<<dim3(CHn + 1, NHn, Bn), 512, attn_smem>>>(out);          // idx 2
}